// round 2
// baseline (speedup 1.0000x reference)
#include <cuda_runtime.h>
#include <math.h>

// ---------------- problem constants ----------------
#define C_      512
#define S_      8192          // T*H*W
#define HW_     1024          // H*W (frame size)
#define W_      32
#define NGROUP  32
#define CPG     16            // channels per group
#define KC      13824         // 512*27 (conv GEMM K)

// ---------------- scratch (device globals; no allocs allowed) ----------------
__device__ float g_mean[NGROUP];
__device__ float g_rstd[NGROUP];
__device__ float g_act[(size_t)C_ * S_];          // normalized(+silu) activation [c][s]
__device__ float g_col[(size_t)KC * S_];          // im2col, K-major [k][pos]  (452 MB)
__device__ float g_wT [(size_t)KC * C_];          // transposed conv weight [k][co]
__device__ float g_wsT[(size_t)C_ * C_];          // transposed 512x512 weight
__device__ float g_t1 [(size_t)C_ * S_];          // resnet mid / attention output
__device__ float g_y0 [(size_t)C_ * S_];          // resnet0 output (attn input)
__device__ float g_q  [(size_t)C_ * S_];          // Q [d][s]   (reused as resnet1 mid)
__device__ float g_kk [(size_t)C_ * S_];          // K [d][s]
__device__ float g_vv [(size_t)C_ * S_];          // V [d][s]
__device__ float g_p  [(size_t)S_ * S_];          // scores / probs [q][k]  (268 MB)
__device__ float g_o  [(size_t)S_ * C_];          // attn out [s][d]

// ---------------- reductions ----------------
__inline__ __device__ float warp_sum(float v) {
    #pragma unroll
    for (int o = 16; o; o >>= 1) v += __shfl_down_sync(0xffffffffu, v, o);
    return v;
}
__inline__ __device__ float warp_max(float v) {
    #pragma unroll
    for (int o = 16; o; o >>= 1) v = fmaxf(v, __shfl_down_sync(0xffffffffu, v, o));
    return v;
}

// ---------------- GroupNorm statistics: one block per group ----------------
__global__ void gn_stats_k(const float* __restrict__ x) {
    int g = blockIdx.x;
    const float4* p = (const float4*)(x + (size_t)g * CPG * S_);
    const int n4 = (CPG * S_) / 4;
    float s = 0.f, s2 = 0.f;
    for (int i = threadIdx.x; i < n4; i += blockDim.x) {
        float4 v = p[i];
        s  += v.x + v.y + v.z + v.w;
        s2 += v.x * v.x + v.y * v.y + v.z * v.z + v.w * v.w;
    }
    __shared__ float sh0[8], sh1[8];
    float ws = warp_sum(s), ws2 = warp_sum(s2);
    int wid = threadIdx.x >> 5, lid = threadIdx.x & 31;
    if (!lid) { sh0[wid] = ws; sh1[wid] = ws2; }
    __syncthreads();
    if (threadIdx.x == 0) {
        float a = 0.f, b = 0.f;
        #pragma unroll
        for (int i = 0; i < 8; i++) { a += sh0[i]; b += sh1[i]; }
        const float inv_n = 1.f / (float)(CPG * S_);
        float m   = a * inv_n;
        float var = b * inv_n - m * m;
        g_mean[g] = m;
        g_rstd[g] = rsqrtf(var + 1e-6f);
    }
}

// ---------------- normalize (+optional SiLU) ----------------
__global__ void normact_k(const float* __restrict__ x, const float* __restrict__ sc,
                          const float* __restrict__ bi, float* __restrict__ out, int do_silu) {
    int i = blockIdx.x * blockDim.x + threadIdx.x;   // over C_*S_
    int c = i >> 13;                                 // / 8192
    int g = c >> 4;
    float v = (x[i] - g_mean[g]) * g_rstd[g] * sc[c] + bi[c];
    if (do_silu) v = v / (1.f + __expf(-v));
    out[i] = v;
}

// ---------------- im2col (causal/replicate padding), K-major output ----------------
__global__ void im2col_k() {
    int k   = blockIdx.y;                       // 0..13823
    int pos = blockIdx.x * blockDim.x + threadIdx.x;  // 0..8191
    int ci = k / 27;
    int r  = k - ci * 27;
    int kd = r / 9;  r -= kd * 9;
    int kh = r / 3;
    int kw = r - kh * 3;
    int t   = pos >> 10;
    int rem = pos & 1023;
    int y   = rem >> 5;
    int x   = rem & 31;
    int ts = min(max(t + kd - 2, 0), 7);
    int ys = min(max(y + kh - 1, 0), 31);
    int xs = min(max(x + kw - 1, 0), 31);
    g_col[(size_t)k * S_ + pos] = g_act[(size_t)ci * S_ + ts * HW_ + ys * W_ + xs];
}

// ---------------- tiled transpose: in [R][Cc] -> out [Cc][R] (dims % 32 == 0) --------
__global__ void transpose_k(const float* __restrict__ in, float* __restrict__ out,
                            int R, int Cc) {
    __shared__ float tile[32][33];
    int c0 = blockIdx.x * 32, r0 = blockIdx.y * 32;
    int tx = threadIdx.x, ty = threadIdx.y;
    #pragma unroll
    for (int i = ty; i < 32; i += 8)
        tile[i][tx] = in[(size_t)(r0 + i) * Cc + c0 + tx];
    __syncthreads();
    #pragma unroll
    for (int i = ty; i < 32; i += 8)
        out[(size_t)(c0 + i) * R + r0 + tx] = tile[tx][i];
}

// ---------------- SGEMM "TT":  C[m][n] = sum_k A[k][m] * B[k][n] ----------------
// 128x128 block tile, BK=8, 256 threads, 8x8 per thread.
// causal==1: skip tiles with n0 >= ((m0/1024)+1)*1024 (block-causal frame mask).
__global__ void __launch_bounds__(256) gemm_tt_k(
    const float* __restrict__ A, const float* __restrict__ B, float* __restrict__ C,
    int M, int N, int K, int lda, int ldb, int ldc,
    float alpha, const float* __restrict__ bias, const float* __restrict__ addend,
    int causal) {
    int n0 = blockIdx.x * 128, m0 = blockIdx.y * 128;
    if (causal && n0 >= (((m0 >> 10) + 1) << 10)) return;

    __shared__ float As[8][128];
    __shared__ float Bs[8][128];
    int tid = threadIdx.x;
    int lk = tid >> 5, lm = (tid & 31) << 2;
    const float* Ag = A + (size_t)lk * lda + m0 + lm;
    const float* Bg = B + (size_t)lk * ldb + n0 + lm;
    int tx = tid & 15, ty = tid >> 4;

    float acc[8][8];
    #pragma unroll
    for (int i = 0; i < 8; i++)
        #pragma unroll
        for (int j = 0; j < 8; j++) acc[i][j] = 0.f;

    for (int k0 = 0; k0 < K; k0 += 8) {
        float4 av = *(const float4*)Ag;
        float4 bv = *(const float4*)Bg;
        *(float4*)&As[lk][lm] = av;
        *(float4*)&Bs[lk][lm] = bv;
        __syncthreads();
        #pragma unroll
        for (int kkk = 0; kkk < 8; kkk++) {
            float a[8], b[8];
            *(float4*)&a[0] = *(const float4*)&As[kkk][ty << 2];
            *(float4*)&a[4] = *(const float4*)&As[kkk][(ty << 2) + 64];
            *(float4*)&b[0] = *(const float4*)&Bs[kkk][tx << 2];
            *(float4*)&b[4] = *(const float4*)&Bs[kkk][(tx << 2) + 64];
            #pragma unroll
            for (int ii = 0; ii < 8; ii++)
                #pragma unroll
                for (int jj = 0; jj < 8; jj++) acc[ii][jj] += a[ii] * b[jj];
        }
        __syncthreads();
        Ag += lda << 3;
        Bg += ldb << 3;
    }

    #pragma unroll
    for (int ii = 0; ii < 8; ii++) {
        int m = m0 + ((ii < 4) ? (ty << 2) + ii : 60 + (ty << 2) + ii);
        float bval = bias ? bias[m] : 0.f;
        #pragma unroll
        for (int jj = 0; jj < 8; jj++) {
            int n = n0 + ((jj < 4) ? (tx << 2) + jj : 60 + (tx << 2) + jj);
            float v = acc[ii][jj] * alpha + bval;
            if (addend) v += addend[(size_t)m * ldc + n];
            C[(size_t)m * ldc + n] = v;
        }
    }
}

// ---------------- SGEMM "NT":  C[m][n] = sum_k A[m][k] * B[n][k] ----------------
// kcausal==1: per-block K bound = ((m0/1024)+1)*1024 (variable key length in P*V).
__global__ void __launch_bounds__(256) gemm_nt_k(
    const float* __restrict__ A, const float* __restrict__ B, float* __restrict__ C,
    int M, int N, int K, int lda, int ldb, int ldc,
    float alpha, const float* __restrict__ bias, const float* __restrict__ addend,
    int kcausal) {
    int n0 = blockIdx.x * 128, m0 = blockIdx.y * 128;
    int Keff = kcausal ? (((m0 >> 10) + 1) << 10) : K;

    __shared__ float As[8][132];
    __shared__ float Bs[8][132];
    int tid = threadIdx.x;
    int lr = tid >> 1, lq = (tid & 1) << 2;
    const float* Ag = A + (size_t)(m0 + lr) * lda + lq;
    const float* Bg = B + (size_t)(n0 + lr) * ldb + lq;
    int tx = tid & 15, ty = tid >> 4;

    float acc[8][8];
    #pragma unroll
    for (int i = 0; i < 8; i++)
        #pragma unroll
        for (int j = 0; j < 8; j++) acc[i][j] = 0.f;

    for (int k0 = 0; k0 < Keff; k0 += 8) {
        float4 av = *(const float4*)(Ag + k0);
        float4 bv = *(const float4*)(Bg + k0);
        As[lq + 0][lr] = av.x; As[lq + 1][lr] = av.y;
        As[lq + 2][lr] = av.z; As[lq + 3][lr] = av.w;
        Bs[lq + 0][lr] = bv.x; Bs[lq + 1][lr] = bv.y;
        Bs[lq + 2][lr] = bv.z; Bs[lq + 3][lr] = bv.w;
        __syncthreads();
        #pragma unroll
        for (int kkk = 0; kkk < 8; kkk++) {
            float a[8], b[8];
            *(float4*)&a[0] = *(const float4*)&As[kkk][ty << 2];
            *(float4*)&a[4] = *(const float4*)&As[kkk][(ty << 2) + 64];
            *(float4*)&b[0] = *(const float4*)&Bs[kkk][tx << 2];
            *(float4*)&b[4] = *(const float4*)&Bs[kkk][(tx << 2) + 64];
            #pragma unroll
            for (int ii = 0; ii < 8; ii++)
                #pragma unroll
                for (int jj = 0; jj < 8; jj++) acc[ii][jj] += a[ii] * b[jj];
        }
        __syncthreads();
    }

    #pragma unroll
    for (int ii = 0; ii < 8; ii++) {
        int m = m0 + ((ii < 4) ? (ty << 2) + ii : 60 + (ty << 2) + ii);
        float bval = bias ? bias[m] : 0.f;
        #pragma unroll
        for (int jj = 0; jj < 8; jj++) {
            int n = n0 + ((jj < 4) ? (tx << 2) + jj : 60 + (tx << 2) + jj);
            float v = acc[ii][jj] * alpha + bval;
            if (addend) v += addend[(size_t)m * ldc + n];
            C[(size_t)m * ldc + n] = v;
        }
    }
}

// ---------------- row softmax over causal length L(i) ----------------
__global__ void softmax_k() {
    int i = blockIdx.x;                         // query row
    int L = ((i >> 10) + 1) << 10;              // allowed key count
    float4* row = (float4*)(g_p + (size_t)i * (size_t)S_);
    int n4 = L >> 2;
    int tid = threadIdx.x;
    __shared__ float sh[8];

    float mx = -1e30f;
    for (int j = tid; j < n4; j += 256) {
        float4 v = row[j];
        mx = fmaxf(mx, fmaxf(fmaxf(v.x, v.y), fmaxf(v.z, v.w)));
    }
    float wm = warp_max(mx);
    if ((tid & 31) == 0) sh[tid >> 5] = wm;
    __syncthreads();
    if (tid < 32) {
        float m2 = (tid < 8) ? sh[tid] : -1e30f;
        m2 = warp_max(m2);
        if (tid == 0) sh[0] = m2;
    }
    __syncthreads();
    float m = sh[0];
    __syncthreads();

    float s = 0.f;
    for (int j = tid; j < n4; j += 256) {
        float4 v = row[j];
        v.x = __expf(v.x - m); v.y = __expf(v.y - m);
        v.z = __expf(v.z - m); v.w = __expf(v.w - m);
        s += v.x + v.y + v.z + v.w;
        row[j] = v;
    }
    float ws = warp_sum(s);
    if ((tid & 31) == 0) sh[tid >> 5] = ws;
    __syncthreads();
    if (tid < 32) {
        float s2 = (tid < 8) ? sh[tid] : 0.f;
        s2 = warp_sum(s2);
        if (tid == 0) sh[0] = s2;
    }
    __syncthreads();
    float inv = 1.f / sh[0];
    for (int j = tid; j < n4; j += 256) {
        float4 v = row[j];
        v.x *= inv; v.y *= inv; v.z *= inv; v.w *= inv;
        row[j] = v;
    }
}

// ---------------- orchestration ----------------
extern "C" void kernel_launch(void* const* d_in, const int* in_sizes, int n_in,
                              void* d_out, int out_size) {
    (void)in_sizes; (void)n_in; (void)out_size;

    float *act, *col, *wT, *wsT, *t1, *y0, *q, *kb, *vb, *p, *o;
    cudaGetSymbolAddress((void**)&act, g_act);
    cudaGetSymbolAddress((void**)&col, g_col);
    cudaGetSymbolAddress((void**)&wT,  g_wT);
    cudaGetSymbolAddress((void**)&wsT, g_wsT);
    cudaGetSymbolAddress((void**)&t1,  g_t1);
    cudaGetSymbolAddress((void**)&y0,  g_y0);
    cudaGetSymbolAddress((void**)&q,   g_q);
    cudaGetSymbolAddress((void**)&kb,  g_kk);
    cudaGetSymbolAddress((void**)&vb,  g_vv);
    cudaGetSymbolAddress((void**)&p,   g_p);
    cudaGetSymbolAddress((void**)&o,   g_o);

    const float* X = (const float*)d_in[0];
    // resnet0: 1..8, resnet1: 9..16, attention: 17..26
    const float* a_gns = (const float*)d_in[17];
    const float* a_gnb = (const float*)d_in[18];
    const float* a_wq  = (const float*)d_in[19];
    const float* a_bq  = (const float*)d_in[20];
    const float* a_wk  = (const float*)d_in[21];
    const float* a_bk  = (const float*)d_in[22];
    const float* a_wv  = (const float*)d_in[23];
    const float* a_bv  = (const float*)d_in[24];
    const float* a_wo  = (const float*)d_in[25];
    const float* a_bo  = (const float*)d_in[26];

    const dim3 tr_t(32, 8);
    const dim3 gemm_conv(S_ / 128, C_ / 128);   // (64, 4)

    auto resnet = [&](const float* in, int base, float* mid, float* outbuf) {
        const float* n1s = (const float*)d_in[base + 0];
        const float* n1b = (const float*)d_in[base + 1];
        const float* w1  = (const float*)d_in[base + 2];
        const float* b1  = (const float*)d_in[base + 3];
        const float* n2s = (const float*)d_in[base + 4];
        const float* n2b = (const float*)d_in[base + 5];
        const float* w2  = (const float*)d_in[base + 6];
        const float* b2  = (const float*)d_in[base + 7];

        gn_stats_k<<<NGROUP, 256>>>(in);
        normact_k<<<(C_ * S_) / 256, 256>>>(in, n1s, n1b, act, 1);
        im2col_k<<<dim3(S_ / 256, KC), 256>>>();
        transpose_k<<<dim3(KC / 32, C_ / 32), tr_t>>>(w1, wT, C_, KC);
        gemm_tt_k<<<gemm_conv, 256>>>(wT, col, mid, C_, S_, KC, C_, S_, S_,
                                      1.f, b1, nullptr, 0);
        gn_stats_k<<<NGROUP, 256>>>(mid);
        normact_k<<<(C_ * S_) / 256, 256>>>(mid, n2s, n2b, act, 1);
        im2col_k<<<dim3(S_ / 256, KC), 256>>>();
        transpose_k<<<dim3(KC / 32, C_ / 32), tr_t>>>(w2, wT, C_, KC);
        gemm_tt_k<<<gemm_conv, 256>>>(wT, col, outbuf, C_, S_, KC, C_, S_, S_,
                                      1.f, b2, in, 0);
    };

    // ---- ResNet block 0:  X -> y0 ----
    resnet(X, 1, t1, y0);

    // ---- Causal frame attention on y0 ([c][s] == b,c,(f h w)) ----
    gn_stats_k<<<NGROUP, 256>>>(y0);
    normact_k<<<(C_ * S_) / 256, 256>>>(y0, a_gns, a_gnb, act, 0);

    transpose_k<<<dim3(16, 16), tr_t>>>(a_wq, wsT, C_, C_);
    gemm_tt_k<<<dim3(64, 4), 256>>>(wsT, act, q,  C_, S_, C_, C_, S_, S_, 1.f, a_bq, nullptr, 0);
    transpose_k<<<dim3(16, 16), tr_t>>>(a_wk, wsT, C_, C_);
    gemm_tt_k<<<dim3(64, 4), 256>>>(wsT, act, kb, C_, S_, C_, C_, S_, S_, 1.f, a_bk, nullptr, 0);
    transpose_k<<<dim3(16, 16), tr_t>>>(a_wv, wsT, C_, C_);
    gemm_tt_k<<<dim3(64, 4), 256>>>(wsT, act, vb, C_, S_, C_, C_, S_, S_, 1.f, a_bv, nullptr, 0);

    // scores[i][j] = (Q . K) / sqrt(512), block-causal tile skip
    gemm_tt_k<<<dim3(64, 64), 256>>>(q, kb, p, S_, S_, C_, S_, S_, S_,
                                     0.04419417382415922f, nullptr, nullptr, 1);
    softmax_k<<<S_, 256>>>();
    // O[s][d] = P . V   (variable K per query frame)
    gemm_nt_k<<<dim3(4, 64), 256>>>(p, vb, o, S_, C_, S_, S_, S_, C_,
                                    1.f, nullptr, nullptr, 1);
    // out[c][s] = Wo . O + bo + y0  (residual)
    gemm_nt_k<<<dim3(64, 4), 256>>>(a_wo, o, t1, C_, S_, C_, C_, C_, S_,
                                    1.f, a_bo, y0, 0);

    // ---- ResNet block 1:  t1 -> d_out ----
    resnet(t1, 9, q, (float*)d_out);
}

// round 4
// speedup vs baseline: 1.7615x; 1.7615x over previous
#include <cuda_runtime.h>
#include <cuda_bf16.h>
#include <math.h>
#include <stdint.h>

#define C_      512
#define S_      8192
#define HW_     1024
#define W_      32
#define NGROUP  32
#define CPG     16
#define KC      13824
#define KITERS  432           // KC/32

__device__ float g_mean[NGROUP];
__device__ float g_rstd[NGROUP];
__device__ float g_act[(size_t)C_ * S_];
__device__ float g_wsT[(size_t)C_ * C_];
__device__ float g_t1 [(size_t)C_ * S_];
__device__ float g_y0 [(size_t)C_ * S_];
__device__ float g_q  [(size_t)C_ * S_];
__device__ float g_kk [(size_t)C_ * S_];
__device__ float g_vv [(size_t)C_ * S_];
__device__ float g_p  [(size_t)S_ * S_];
__device__ float g_o  [(size_t)S_ * C_];
// row-major bf16 hi/lo operands
__device__ __align__(16) unsigned short g_whi[(size_t)C_ * KC];
__device__ __align__(16) unsigned short g_wlo[(size_t)C_ * KC];
__device__ __align__(16) unsigned short g_bhi[(size_t)S_ * KC];
__device__ __align__(16) unsigned short g_blo[(size_t)S_ * KC];

// ---------------- PTX helpers ----------------
__device__ __forceinline__ uint32_t smem_u32(const void* p) {
    uint32_t a;
    asm("{ .reg .u64 t; cvta.to.shared.u64 t, %1; cvt.u32.u64 %0, t; }" : "=r"(a) : "l"(p));
    return a;
}
#define CP_ASYNC16(smem, gmem) \
    asm volatile("cp.async.cg.shared.global [%0], [%1], 16;" :: "r"(smem), "l"(gmem) : "memory")
#define CP_COMMIT() asm volatile("cp.async.commit_group;" ::: "memory")
#define CP_WAIT1()  asm volatile("cp.async.wait_group 1;" ::: "memory")
#define LDSM4(r, addr) \
    asm volatile("ldmatrix.sync.aligned.m8n8.x4.shared.b16 {%0,%1,%2,%3}, [%4];" \
        : "=r"((r)[0]),"=r"((r)[1]),"=r"((r)[2]),"=r"((r)[3]) : "r"(addr))
#define MMA16816(d, a, b0, b1) \
    asm volatile("mma.sync.aligned.m16n8k16.row.col.f32.bf16.bf16.f32 " \
        "{%0,%1,%2,%3}, {%4,%5,%6,%7}, {%8,%9}, {%0,%1,%2,%3};" \
        : "+f"((d)[0]),"+f"((d)[1]),"+f"((d)[2]),"+f"((d)[3]) \
        : "r"((a)[0]),"r"((a)[1]),"r"((a)[2]),"r"((a)[3]), "r"(b0),"r"(b1))

__device__ __forceinline__ void split_hilo(float v, unsigned short& h, unsigned short& l) {
    uint32_t u = __float_as_uint(v);
    h = (unsigned short)(u >> 16);
    float rem = v - __uint_as_float(u & 0xffff0000u);
    l = __bfloat16_as_ushort(__float2bfloat16(rem));
}

__inline__ __device__ float warp_sum(float v) {
    #pragma unroll
    for (int o = 16; o; o >>= 1) v += __shfl_down_sync(0xffffffffu, v, o);
    return v;
}
__inline__ __device__ float warp_max(float v) {
    #pragma unroll
    for (int o = 16; o; o >>= 1) v = fmaxf(v, __shfl_down_sync(0xffffffffu, v, o));
    return v;
}

// ---------------- GroupNorm stats ----------------
__global__ void gn_stats_k(const float* __restrict__ x) {
    int g = blockIdx.x;
    const float4* p = (const float4*)(x + (size_t)g * CPG * S_);
    const int n4 = (CPG * S_) / 4;
    float s = 0.f, s2 = 0.f;
    for (int i = threadIdx.x; i < n4; i += blockDim.x) {
        float4 v = p[i];
        s  += v.x + v.y + v.z + v.w;
        s2 += v.x * v.x + v.y * v.y + v.z * v.z + v.w * v.w;
    }
    __shared__ float sh0[8], sh1[8];
    float ws = warp_sum(s), ws2 = warp_sum(s2);
    int wid = threadIdx.x >> 5, lid = threadIdx.x & 31;
    if (!lid) { sh0[wid] = ws; sh1[wid] = ws2; }
    __syncthreads();
    if (threadIdx.x == 0) {
        float a = 0.f, b = 0.f;
        #pragma unroll
        for (int i = 0; i < 8; i++) { a += sh0[i]; b += sh1[i]; }
        const float inv_n = 1.f / (float)(CPG * S_);
        float m = a * inv_n;
        g_mean[g] = m;
        g_rstd[g] = rsqrtf(b * inv_n - m * m + 1e-6f);
    }
}

__global__ void normact_k(const float* __restrict__ x, const float* __restrict__ sc,
                          const float* __restrict__ bi, float* __restrict__ out, int do_silu) {
    int i = blockIdx.x * blockDim.x + threadIdx.x;
    int c = i >> 13;
    int g = c >> 4;
    float v = (x[i] - g_mean[g]) * g_rstd[g] * sc[c] + bi[c];
    if (do_silu) v = v / (1.f + __expf(-v));
    out[i] = v;
}

// ---------------- im2col -> row-major bf16 hi/lo [pos][KC] ----------------
// id = pos*1728 + kchunk; each thread emits 8 consecutive k (16B hi + 16B lo)
__global__ void im2col_pack_k() {
    size_t id = (size_t)blockIdx.x * 256 + threadIdx.x;
    int pos = (int)(id / 1728);
    int kc  = (int)(id - (size_t)pos * 1728);
    int k0 = kc * 8;
    int t = pos >> 10, rem = pos & 1023, y = rem >> 5, x = rem & 31;
    __align__(16) unsigned short hi[8], lo[8];
    #pragma unroll
    for (int e = 0; e < 8; e++) {
        int k = k0 + e;
        int ci = k / 27; int r = k - ci * 27;
        int kd = r / 9;  r -= kd * 9;
        int kh = r / 3;  int kw = r - kh * 3;
        int ts = min(max(t + kd - 2, 0), 7);
        int ys = min(max(y + kh - 1, 0), 31);
        int xs = min(max(x + kw - 1, 0), 31);
        float v = g_act[(size_t)ci * S_ + ts * HW_ + ys * W_ + xs];
        split_hilo(v, hi[e], lo[e]);
    }
    size_t off = (size_t)pos * KC + k0;
    *(uint4*)(g_bhi + off) = *(uint4*)hi;
    *(uint4*)(g_blo + off) = *(uint4*)lo;
}

// ---------------- weight pack -> row-major bf16 hi/lo [co][KC] ----------------
__global__ void wpack_k(const float* __restrict__ w) {
    size_t id = (size_t)blockIdx.x * 256 + threadIdx.x;   // over C_*KC/8
    const float4* src = (const float4*)w;
    float4 v0 = src[id * 2], v1 = src[id * 2 + 1];
    __align__(16) unsigned short hi[8], lo[8];
    split_hilo(v0.x, hi[0], lo[0]); split_hilo(v0.y, hi[1], lo[1]);
    split_hilo(v0.z, hi[2], lo[2]); split_hilo(v0.w, hi[3], lo[3]);
    split_hilo(v1.x, hi[4], lo[4]); split_hilo(v1.y, hi[5], lo[5]);
    split_hilo(v1.z, hi[6], lo[6]); split_hilo(v1.w, hi[7], lo[7]);
    *(uint4*)(g_whi + id * 8) = *(uint4*)hi;
    *(uint4*)(g_wlo + id * 8) = *(uint4*)lo;
}

// ---------------- HMMA conv GEMM: C[m][n] = sum_k W[m][k]*col[n][k] + bias (+add) --
// CTA 128x128, BK=32, 3-stage cp.async, warp tile 64x32, hi/lo 3-pass.
// smem tile: [128 rows][64B], phys = r*64 + ((u ^ ((r>>1)&3))<<4), u = 16B unit 0..3
__global__ void __launch_bounds__(256, 1) conv_hmma_k(
    const unsigned short* __restrict__ Ahi, const unsigned short* __restrict__ Alo,
    const unsigned short* __restrict__ Bhi, const unsigned short* __restrict__ Blo,
    float* __restrict__ Cout, const float* __restrict__ bias,
    const float* __restrict__ addend) {
    extern __shared__ unsigned char dynsm[];
    const uint32_t sm0 = smem_u32(dynsm);
    const int tid = threadIdx.x, lane = tid & 31, warp = tid >> 5;
    const int m0 = blockIdx.y * 128, n0 = blockIdx.x * 128;
    const int wm = warp & 1, wn = warp >> 1;          // warp tile: m 64, n 32

    // cp.async loader: 512 16B-units per 8KB operand tile, 2 per thread
    auto issue = [&](int stage, int k0) {
        uint32_t sb = sm0 + stage * 32768;
        #pragma unroll
        for (int h = 0; h < 2; h++) {
            int id = tid + h * 256;
            int r = id >> 2, cu = id & 3;
            uint32_t soff = r * 64 + (((cu ^ ((r >> 1) & 3))) << 4);
            size_t ga = (size_t)(m0 + r) * KC + k0 + cu * 8;
            size_t gb = (size_t)(n0 + r) * KC + k0 + cu * 8;
            CP_ASYNC16(sb + soff,         Ahi + ga);
            CP_ASYNC16(sb + 8192  + soff, Alo + ga);
            CP_ASYNC16(sb + 16384 + soff, Bhi + gb);
            CP_ASYNC16(sb + 24576 + soff, Blo + gb);
        }
        CP_COMMIT();
    };

    float acc[4][4][4];
    #pragma unroll
    for (int i = 0; i < 4; i++)
        #pragma unroll
        for (int j = 0; j < 4; j++)
            #pragma unroll
            for (int r = 0; r < 4; r++) acc[i][j][r] = 0.f;

    issue(0, 0);
    issue(1, 32);

    const int rl = lane & 15, ul = lane >> 4;
    for (int it = 0; it < KITERS; it++) {
        CP_WAIT1();
        __syncthreads();
        uint32_t sb = sm0 + (it % 3) * 32768;
        #pragma unroll
        for (int k16 = 0; k16 < 2; k16++) {
            uint32_t ahi[4][4], alo[4][4], bhi[2][4], blo[2][4];
            int u = k16 * 2 + ul;
            #pragma unroll
            for (int i = 0; i < 4; i++) {
                int r = wm * 64 + i * 16 + rl;
                uint32_t off = r * 64 + (((u ^ ((r >> 1) & 3))) << 4);
                LDSM4(ahi[i], sb + off);
                LDSM4(alo[i], sb + 8192 + off);
            }
            #pragma unroll
            for (int j2 = 0; j2 < 2; j2++) {
                int r = wn * 32 + j2 * 16 + rl;
                uint32_t off = r * 64 + (((u ^ ((r >> 1) & 3))) << 4);
                LDSM4(bhi[j2], sb + 16384 + off);
                LDSM4(blo[j2], sb + 24576 + off);
            }
            #pragma unroll
            for (int i = 0; i < 4; i++)
                #pragma unroll
                for (int j = 0; j < 4; j++) {
                    int j2 = j >> 1, ts = j & 1;
                    MMA16816(acc[i][j], ahi[i], bhi[j2][ts], bhi[j2][ts + 2]);
                    MMA16816(acc[i][j], ahi[i], blo[j2][ts], blo[j2][ts + 2]);
                    MMA16816(acc[i][j], alo[i], bhi[j2][ts], bhi[j2][ts + 2]);
                }
        }
        __syncthreads();
        if (it + 2 < KITERS) issue((it + 2) % 3, (it + 2) * 32);
        else CP_COMMIT();
    }

    // epilogue: acc[i][j]: rows m0+wm*64+i*16+(lane>>2) (+8), cols n0+wn*32+j*8+(lane&3)*2
    const int mrow = m0 + wm * 64 + (lane >> 2);
    const int ncol = n0 + wn * 32 + (lane & 3) * 2;
    #pragma unroll
    for (int i = 0; i < 4; i++) {
        int ma = mrow + i * 16, mb = ma + 8;
        float bva = bias[ma], bvb = bias[mb];
        #pragma unroll
        for (int j = 0; j < 4; j++) {
            int n = ncol + j * 8;
            float2 va = make_float2(acc[i][j][0] + bva, acc[i][j][1] + bva);
            float2 vb = make_float2(acc[i][j][2] + bvb, acc[i][j][3] + bvb);
            if (addend) {
                float2 aa = *(const float2*)(addend + (size_t)ma * S_ + n);
                float2 ab = *(const float2*)(addend + (size_t)mb * S_ + n);
                va.x += aa.x; va.y += aa.y; vb.x += ab.x; vb.y += ab.y;
            }
            *(float2*)(Cout + (size_t)ma * S_ + n) = va;
            *(float2*)(Cout + (size_t)mb * S_ + n) = vb;
        }
    }
}

// ---------------- transpose (512x512) ----------------
__global__ void transpose_k(const float* __restrict__ in, float* __restrict__ out,
                            int R, int Cc) {
    __shared__ float tile[32][33];
    int c0 = blockIdx.x * 32, r0 = blockIdx.y * 32;
    int tx = threadIdx.x, ty = threadIdx.y;
    #pragma unroll
    for (int i = ty; i < 32; i += 8)
        tile[i][tx] = in[(size_t)(r0 + i) * Cc + c0 + tx];
    __syncthreads();
    #pragma unroll
    for (int i = ty; i < 32; i += 8)
        out[(size_t)(c0 + i) * R + r0 + tx] = tile[tx][i];
}

// ---------------- SGEMM TT: C[m][n] = sum_k A[k][m]*B[k][n] ----------------
__global__ void __launch_bounds__(256) gemm_tt_k(
    const float* __restrict__ A, const float* __restrict__ B, float* __restrict__ C,
    int K, int lda, int ldb, int ldc,
    float alpha, const float* __restrict__ bias, const float* __restrict__ addend,
    int causal) {
    int n0 = blockIdx.x * 128, m0 = blockIdx.y * 128;
    if (causal && n0 >= (((m0 >> 10) + 1) << 10)) return;
    __shared__ float As[8][128];
    __shared__ float Bs[8][128];
    int tid = threadIdx.x;
    int lk = tid >> 5, lm = (tid & 31) << 2;
    const float* Ag = A + (size_t)lk * lda + m0 + lm;
    const float* Bg = B + (size_t)lk * ldb + n0 + lm;
    int tx = tid & 15, ty = tid >> 4;
    float acc[8][8];
    #pragma unroll
    for (int i = 0; i < 8; i++)
        #pragma unroll
        for (int j = 0; j < 8; j++) acc[i][j] = 0.f;
    for (int k0 = 0; k0 < K; k0 += 8) {
        float4 av = *(const float4*)Ag;
        float4 bv = *(const float4*)Bg;
        *(float4*)&As[lk][lm] = av;
        *(float4*)&Bs[lk][lm] = bv;
        __syncthreads();
        #pragma unroll
        for (int kkk = 0; kkk < 8; kkk++) {
            float a[8], b[8];
            *(float4*)&a[0] = *(const float4*)&As[kkk][ty << 2];
            *(float4*)&a[4] = *(const float4*)&As[kkk][(ty << 2) + 64];
            *(float4*)&b[0] = *(const float4*)&Bs[kkk][tx << 2];
            *(float4*)&b[4] = *(const float4*)&Bs[kkk][(tx << 2) + 64];
            #pragma unroll
            for (int ii = 0; ii < 8; ii++)
                #pragma unroll
                for (int jj = 0; jj < 8; jj++) acc[ii][jj] += a[ii] * b[jj];
        }
        __syncthreads();
        Ag += lda << 3;
        Bg += ldb << 3;
    }
    #pragma unroll
    for (int ii = 0; ii < 8; ii++) {
        int m = m0 + ((ii < 4) ? (ty << 2) + ii : 60 + (ty << 2) + ii);
        float bval = bias ? bias[m] : 0.f;
        #pragma unroll
        for (int jj = 0; jj < 8; jj++) {
            int n = n0 + ((jj < 4) ? (tx << 2) + jj : 60 + (tx << 2) + jj);
            float v = acc[ii][jj] * alpha + bval;
            if (addend) v += addend[(size_t)m * ldc + n];
            C[(size_t)m * ldc + n] = v;
        }
    }
}

// ---------------- SGEMM NT: C[m][n] = sum_k A[m][k]*B[n][k] ----------------
__global__ void __launch_bounds__(256) gemm_nt_k(
    const float* __restrict__ A, const float* __restrict__ B, float* __restrict__ C,
    int K, int lda, int ldb, int ldc,
    float alpha, const float* __restrict__ bias, const float* __restrict__ addend,
    int kcausal) {
    int n0 = blockIdx.x * 128, m0 = blockIdx.y * 128;
    int Keff = kcausal ? (((m0 >> 10) + 1) << 10) : K;
    __shared__ float As[8][132];
    __shared__ float Bs[8][132];
    int tid = threadIdx.x;
    int lr = tid >> 1, lq = (tid & 1) << 2;
    const float* Ag = A + (size_t)(m0 + lr) * lda + lq;
    const float* Bg = B + (size_t)(n0 + lr) * ldb + lq;
    int tx = tid & 15, ty = tid >> 4;
    float acc[8][8];
    #pragma unroll
    for (int i = 0; i < 8; i++)
        #pragma unroll
        for (int j = 0; j < 8; j++) acc[i][j] = 0.f;
    for (int k0 = 0; k0 < Keff; k0 += 8) {
        float4 av = *(const float4*)(Ag + k0);
        float4 bv = *(const float4*)(Bg + k0);
        As[lq + 0][lr] = av.x; As[lq + 1][lr] = av.y;
        As[lq + 2][lr] = av.z; As[lq + 3][lr] = av.w;
        Bs[lq + 0][lr] = bv.x; Bs[lq + 1][lr] = bv.y;
        Bs[lq + 2][lr] = bv.z; Bs[lq + 3][lr] = bv.w;
        __syncthreads();
        #pragma unroll
        for (int kkk = 0; kkk < 8; kkk++) {
            float a[8], b[8];
            *(float4*)&a[0] = *(const float4*)&As[kkk][ty << 2];
            *(float4*)&a[4] = *(const float4*)&As[kkk][(ty << 2) + 64];
            *(float4*)&b[0] = *(const float4*)&Bs[kkk][tx << 2];
            *(float4*)&b[4] = *(const float4*)&Bs[kkk][(tx << 2) + 64];
            #pragma unroll
            for (int ii = 0; ii < 8; ii++)
                #pragma unroll
                for (int jj = 0; jj < 8; jj++) acc[ii][jj] += a[ii] * b[jj];
        }
        __syncthreads();
    }
    #pragma unroll
    for (int ii = 0; ii < 8; ii++) {
        int m = m0 + ((ii < 4) ? (ty << 2) + ii : 60 + (ty << 2) + ii);
        float bval = bias ? bias[m] : 0.f;
        #pragma unroll
        for (int jj = 0; jj < 8; jj++) {
            int n = n0 + ((jj < 4) ? (tx << 2) + jj : 60 + (tx << 2) + jj);
            float v = acc[ii][jj] * alpha + bval;
            if (addend) v += addend[(size_t)m * ldc + n];
            C[(size_t)m * ldc + n] = v;
        }
    }
}

// ---------------- row softmax over causal length ----------------
__global__ void softmax_k() {
    int i = blockIdx.x;
    int L = ((i >> 10) + 1) << 10;
    float4* row = (float4*)(g_p + (size_t)i * (size_t)S_);
    int n4 = L >> 2;
    int tid = threadIdx.x;
    __shared__ float sh[8];
    float mx = -1e30f;
    for (int j = tid; j < n4; j += 256) {
        float4 v = row[j];
        mx = fmaxf(mx, fmaxf(fmaxf(v.x, v.y), fmaxf(v.z, v.w)));
    }
    float wm = warp_max(mx);
    if ((tid & 31) == 0) sh[tid >> 5] = wm;
    __syncthreads();
    if (tid < 32) {
        float m2 = (tid < 8) ? sh[tid] : -1e30f;
        m2 = warp_max(m2);
        if (tid == 0) sh[0] = m2;
    }
    __syncthreads();
    float m = sh[0];
    __syncthreads();
    float s = 0.f;
    for (int j = tid; j < n4; j += 256) {
        float4 v = row[j];
        v.x = __expf(v.x - m); v.y = __expf(v.y - m);
        v.z = __expf(v.z - m); v.w = __expf(v.w - m);
        s += v.x + v.y + v.z + v.w;
        row[j] = v;
    }
    float ws = warp_sum(s);
    if ((tid & 31) == 0) sh[tid >> 5] = ws;
    __syncthreads();
    if (tid < 32) {
        float s2 = (tid < 8) ? sh[tid] : 0.f;
        s2 = warp_sum(s2);
        if (tid == 0) sh[0] = s2;
    }
    __syncthreads();
    float inv = 1.f / sh[0];
    for (int j = tid; j < n4; j += 256) {
        float4 v = row[j];
        v.x *= inv; v.y *= inv; v.z *= inv; v.w *= inv;
        row[j] = v;
    }
}

// ---------------- orchestration ----------------
extern "C" void kernel_launch(void* const* d_in, const int* in_sizes, int n_in,
                              void* d_out, int out_size) {
    (void)in_sizes; (void)n_in; (void)out_size;

    float *act, *wsT, *t1, *y0, *q, *kb, *vb, *p, *o;
    unsigned short *whi, *wlo, *bhi, *blo;
    cudaGetSymbolAddress((void**)&act, g_act);
    cudaGetSymbolAddress((void**)&wsT, g_wsT);
    cudaGetSymbolAddress((void**)&t1,  g_t1);
    cudaGetSymbolAddress((void**)&y0,  g_y0);
    cudaGetSymbolAddress((void**)&q,   g_q);
    cudaGetSymbolAddress((void**)&kb,  g_kk);
    cudaGetSymbolAddress((void**)&vb,  g_vv);
    cudaGetSymbolAddress((void**)&p,   g_p);
    cudaGetSymbolAddress((void**)&o,   g_o);
    cudaGetSymbolAddress((void**)&whi, g_whi);
    cudaGetSymbolAddress((void**)&wlo, g_wlo);
    cudaGetSymbolAddress((void**)&bhi, g_bhi);
    cudaGetSymbolAddress((void**)&blo, g_blo);

    cudaFuncSetAttribute(conv_hmma_k, cudaFuncAttributeMaxDynamicSharedMemorySize, 98304);

    const float* X = (const float*)d_in[0];
    const float* a_gns = (const float*)d_in[17];
    const float* a_gnb = (const float*)d_in[18];
    const float* a_wq  = (const float*)d_in[19];
    const float* a_bq  = (const float*)d_in[20];
    const float* a_wk  = (const float*)d_in[21];
    const float* a_bk  = (const float*)d_in[22];
    const float* a_wv  = (const float*)d_in[23];
    const float* a_bv  = (const float*)d_in[24];
    const float* a_wo  = (const float*)d_in[25];
    const float* a_bo  = (const float*)d_in[26];

    const dim3 tr_t(32, 8);
    const dim3 conv_grid(64, 4);          // n tiles x m tiles
    const int IM2COL_BLOCKS = (S_ * (KC / 8)) / 256;   // 55296
    const int WPACK_BLOCKS  = ((C_ * KC) / 8) / 256;   // 3456

    auto resnet = [&](const float* in, int base, float* mid, float* outbuf) {
        const float* n1s = (const float*)d_in[base + 0];
        const float* n1b = (const float*)d_in[base + 1];
        const float* w1  = (const float*)d_in[base + 2];
        const float* b1  = (const float*)d_in[base + 3];
        const float* n2s = (const float*)d_in[base + 4];
        const float* n2b = (const float*)d_in[base + 5];
        const float* w2  = (const float*)d_in[base + 6];
        const float* b2  = (const float*)d_in[base + 7];

        gn_stats_k<<<NGROUP, 256>>>(in);
        normact_k<<<(C_ * S_) / 256, 256>>>(in, n1s, n1b, act, 1);
        im2col_pack_k<<<IM2COL_BLOCKS, 256>>>();
        wpack_k<<<WPACK_BLOCKS, 256>>>(w1);
        conv_hmma_k<<<conv_grid, 256, 98304>>>(whi, wlo, bhi, blo, mid, b1, nullptr);
        gn_stats_k<<<NGROUP, 256>>>(mid);
        normact_k<<<(C_ * S_) / 256, 256>>>(mid, n2s, n2b, act, 1);
        im2col_pack_k<<<IM2COL_BLOCKS, 256>>>();
        wpack_k<<<WPACK_BLOCKS, 256>>>(w2);
        conv_hmma_k<<<conv_grid, 256, 98304>>>(whi, wlo, bhi, blo, outbuf, b2, in);
    };

    // ---- ResNet block 0:  X -> y0 ----
    resnet(X, 1, t1, y0);

    // ---- Causal frame attention on y0 ----
    gn_stats_k<<<NGROUP, 256>>>(y0);
    normact_k<<<(C_ * S_) / 256, 256>>>(y0, a_gns, a_gnb, act, 0);

    transpose_k<<<dim3(16, 16), tr_t>>>(a_wq, wsT, C_, C_);
    gemm_tt_k<<<dim3(64, 4), 256>>>(wsT, act, q,  C_, C_, S_, S_, 1.f, a_bq, nullptr, 0);
    transpose_k<<<dim3(16, 16), tr_t>>>(a_wk, wsT, C_, C_);
    gemm_tt_k<<<dim3(64, 4), 256>>>(wsT, act, kb, C_, C_, S_, S_, 1.f, a_bk, nullptr, 0);
    transpose_k<<<dim3(16, 16), tr_t>>>(a_wv, wsT, C_, C_);
    gemm_tt_k<<<dim3(64, 4), 256>>>(wsT, act, vb, C_, C_, S_, S_, 1.f, a_bv, nullptr, 0);

    gemm_tt_k<<<dim3(64, 64), 256>>>(q, kb, p, C_, S_, S_, S_,
                                     0.04419417382415922f, nullptr, nullptr, 1);
    softmax_k<<<S_, 256>>>();
    gemm_nt_k<<<dim3(4, 64), 256>>>(p, vb, o, S_, S_, S_, C_,
                                    1.f, nullptr, nullptr, 1);
    gemm_nt_k<<<dim3(64, 4), 256>>>(a_wo, o, t1, C_, C_, C_, S_,
                                    1.f, a_bo, y0, 0);

    // ---- ResNet block 1:  t1 -> d_out ----
    resnet(t1, 9, q, (float*)d_out);
}

// round 5
// speedup vs baseline: 2.1452x; 1.2178x over previous
#include <cuda_runtime.h>
#include <cuda_bf16.h>
#include <math.h>
#include <stdint.h>

#define C_      512
#define S_      8192
#define HW_     1024
#define W_      32
#define NGROUP  32
#define CPG     16
#define KC      13824
#define KITERS  432           // KC/32

typedef unsigned short ushort_t;

__device__ float g_mean[NGROUP];
__device__ float g_rstd[NGROUP];
__device__ float g_act[(size_t)C_ * S_];
__device__ float g_t1 [(size_t)C_ * S_];
__device__ float g_y0 [(size_t)C_ * S_];
__device__ float g_mid[(size_t)C_ * S_];
__device__ float g_p  [(size_t)S_ * S_];
// conv operands (row-major bf16 hi/lo)
__device__ __align__(16) ushort_t g_whi[(size_t)C_ * KC];
__device__ __align__(16) ushort_t g_wlo[(size_t)C_ * KC];
__device__ __align__(16) ushort_t g_bhi[(size_t)S_ * KC];
__device__ __align__(16) ushort_t g_blo[(size_t)S_ * KC];
// attention packed operands
__device__ __align__(16) ushort_t g_acth[(size_t)S_ * C_];   // xn [s][c]
__device__ __align__(16) ushort_t g_actl[(size_t)S_ * C_];
__device__ __align__(16) ushort_t g_wahi[(size_t)C_ * C_];   // current 512x512 weight
__device__ __align__(16) ushort_t g_walo[(size_t)C_ * C_];
__device__ __align__(16) ushort_t g_qhi[(size_t)S_ * C_];    // Q [s][d]
__device__ __align__(16) ushort_t g_qlo[(size_t)S_ * C_];
__device__ __align__(16) ushort_t g_khi[(size_t)S_ * C_];    // K [s][d]
__device__ __align__(16) ushort_t g_klo[(size_t)S_ * C_];
__device__ __align__(16) ushort_t g_vhi[(size_t)C_ * S_];    // V [d][s]
__device__ __align__(16) ushort_t g_vlo[(size_t)C_ * S_];
__device__ __align__(16) ushort_t g_ohi[(size_t)S_ * C_];    // O [s][d]
__device__ __align__(16) ushort_t g_olo[(size_t)S_ * C_];
__device__ __align__(16) ushort_t g_phi[(size_t)S_ * S_];    // probs [q][k]
__device__ __align__(16) ushort_t g_plo[(size_t)S_ * S_];

// ---------------- PTX helpers ----------------
__device__ __forceinline__ uint32_t smem_u32(const void* p) {
    uint32_t a;
    asm("{ .reg .u64 t; cvta.to.shared.u64 t, %1; cvt.u32.u64 %0, t; }" : "=r"(a) : "l"(p));
    return a;
}
#define CP_ASYNC16(smem, gmem) \
    asm volatile("cp.async.cg.shared.global [%0], [%1], 16;" :: "r"(smem), "l"(gmem) : "memory")
#define CP_COMMIT() asm volatile("cp.async.commit_group;" ::: "memory")
#define CP_WAIT1()  asm volatile("cp.async.wait_group 1;" ::: "memory")
#define LDSM4(r, addr) \
    asm volatile("ldmatrix.sync.aligned.m8n8.x4.shared.b16 {%0,%1,%2,%3}, [%4];" \
        : "=r"((r)[0]),"=r"((r)[1]),"=r"((r)[2]),"=r"((r)[3]) : "r"(addr))
#define MMA16816(d, a, b0, b1) \
    asm volatile("mma.sync.aligned.m16n8k16.row.col.f32.bf16.bf16.f32 " \
        "{%0,%1,%2,%3}, {%4,%5,%6,%7}, {%8,%9}, {%0,%1,%2,%3};" \
        : "+f"((d)[0]),"+f"((d)[1]),"+f"((d)[2]),"+f"((d)[3]) \
        : "r"((a)[0]),"r"((a)[1]),"r"((a)[2]),"r"((a)[3]), "r"(b0),"r"(b1))

__device__ __forceinline__ void split_hilo(float v, ushort_t& h, ushort_t& l) {
    uint32_t u = __float_as_uint(v);
    h = (ushort_t)(u >> 16);
    float rem = v - __uint_as_float(u & 0xffff0000u);
    l = __bfloat16_as_ushort(__float2bfloat16(rem));
}

__inline__ __device__ float warp_sum(float v) {
    #pragma unroll
    for (int o = 16; o; o >>= 1) v += __shfl_down_sync(0xffffffffu, v, o);
    return v;
}
__inline__ __device__ float warp_max(float v) {
    #pragma unroll
    for (int o = 16; o; o >>= 1) v = fmaxf(v, __shfl_down_sync(0xffffffffu, v, o));
    return v;
}

// ---------------- GroupNorm stats ----------------
__global__ void gn_stats_k(const float* __restrict__ x) {
    int g = blockIdx.x;
    const float4* p = (const float4*)(x + (size_t)g * CPG * S_);
    const int n4 = (CPG * S_) / 4;
    float s = 0.f, s2 = 0.f;
    for (int i = threadIdx.x; i < n4; i += blockDim.x) {
        float4 v = p[i];
        s  += v.x + v.y + v.z + v.w;
        s2 += v.x * v.x + v.y * v.y + v.z * v.z + v.w * v.w;
    }
    __shared__ float sh0[8], sh1[8];
    float ws = warp_sum(s), ws2 = warp_sum(s2);
    int wid = threadIdx.x >> 5, lid = threadIdx.x & 31;
    if (!lid) { sh0[wid] = ws; sh1[wid] = ws2; }
    __syncthreads();
    if (threadIdx.x == 0) {
        float a = 0.f, b = 0.f;
        #pragma unroll
        for (int i = 0; i < 8; i++) { a += sh0[i]; b += sh1[i]; }
        const float inv_n = 1.f / (float)(CPG * S_);
        float m = a * inv_n;
        g_mean[g] = m;
        g_rstd[g] = rsqrtf(b * inv_n - m * m + 1e-6f);
    }
}

__global__ void normact_k(const float* __restrict__ x, const float* __restrict__ sc,
                          const float* __restrict__ bi, float* __restrict__ out, int do_silu) {
    int i = blockIdx.x * blockDim.x + threadIdx.x;
    int c = i >> 13;
    int g = c >> 4;
    float v = (x[i] - g_mean[g]) * g_rstd[g] * sc[c] + bi[c];
    if (do_silu) v = v / (1.f + __expf(-v));
    out[i] = v;
}

// ---------------- im2col -> row-major bf16 hi/lo [pos][KC] ----------------
__global__ void im2col_pack_k() {
    size_t id = (size_t)blockIdx.x * 256 + threadIdx.x;
    int pos = (int)(id / 1728);
    int kc  = (int)(id - (size_t)pos * 1728);
    int k0 = kc * 8;
    int t = pos >> 10, rem = pos & 1023, y = rem >> 5, x = rem & 31;
    __align__(16) ushort_t hi[8], lo[8];
    #pragma unroll
    for (int e = 0; e < 8; e++) {
        int k = k0 + e;
        int ci = k / 27; int r = k - ci * 27;
        int kd = r / 9;  r -= kd * 9;
        int kh = r / 3;  int kw = r - kh * 3;
        int ts = min(max(t + kd - 2, 0), 7);
        int ys = min(max(y + kh - 1, 0), 31);
        int xs = min(max(x + kw - 1, 0), 31);
        float v = g_act[(size_t)ci * S_ + ts * HW_ + ys * W_ + xs];
        split_hilo(v, hi[e], lo[e]);
    }
    size_t off = (size_t)pos * KC + k0;
    *(uint4*)(g_bhi + off) = *(uint4*)hi;
    *(uint4*)(g_blo + off) = *(uint4*)lo;
}

// ---------------- generic pack: fp32 row-major -> bf16 hi/lo ----------------
__global__ void wpack_k(const float* __restrict__ w, ushort_t* __restrict__ dhi,
                        ushort_t* __restrict__ dlo) {
    size_t id = (size_t)blockIdx.x * 256 + threadIdx.x;    // over count/8
    const float4* src = (const float4*)w;
    float4 v0 = src[id * 2], v1 = src[id * 2 + 1];
    __align__(16) ushort_t hi[8], lo[8];
    split_hilo(v0.x, hi[0], lo[0]); split_hilo(v0.y, hi[1], lo[1]);
    split_hilo(v0.z, hi[2], lo[2]); split_hilo(v0.w, hi[3], lo[3]);
    split_hilo(v1.x, hi[4], lo[4]); split_hilo(v1.y, hi[5], lo[5]);
    split_hilo(v1.z, hi[6], lo[6]); split_hilo(v1.w, hi[7], lo[7]);
    *(uint4*)(dhi + id * 8) = *(uint4*)hi;
    *(uint4*)(dlo + id * 8) = *(uint4*)lo;
}

// ---------------- transpose-pack: act [c][s] -> hi/lo [s][c] ----------------
__global__ void atpack_k() {
    __shared__ float tile[32][33];
    int s0 = blockIdx.x * 32, c0 = blockIdx.y * 32;
    int tx = threadIdx.x, ty = threadIdx.y;
    #pragma unroll
    for (int i = ty; i < 32; i += 8)
        tile[i][tx] = g_act[(size_t)(c0 + i) * S_ + s0 + tx];
    __syncthreads();
    #pragma unroll
    for (int i = ty; i < 32; i += 8) {
        float v = tile[tx][i];
        ushort_t h, l;
        split_hilo(v, h, l);
        size_t off = (size_t)(s0 + i) * C_ + c0 + tx;
        g_acth[off] = h;
        g_actl[off] = l;
    }
}

// ================= HMMA GEMM (shared mainloop) =================
// C[m][n] = sum_k A[m][k]*B[n][k], 3-pass hi/lo bf16, CTA 128x128, BK=32.
// smem per stage: Ahi 8K | Alo 8K | Bhi 8K | Blo 8K; phys r*64 + ((u^((r>>1)&3))<<4)

struct HmmaAcc { float a[4][4][4]; };

__device__ __forceinline__ void hmma_mainloop(
    HmmaAcc& A4, uint32_t sm0, int tid,
    const ushort_t* __restrict__ Ahi, const ushort_t* __restrict__ Alo, int lda,
    const ushort_t* __restrict__ Bhi, const ushort_t* __restrict__ Blo, int ldb,
    int m0, int n0, int kiters) {
    const int lane = tid & 31, warp = tid >> 5;
    const int wm = warp & 1, wn = warp >> 1;

    auto issue = [&](int stage, int k0) {
        uint32_t sb = sm0 + stage * 32768;
        #pragma unroll
        for (int h = 0; h < 2; h++) {
            int id = tid + h * 256;
            int r = id >> 2, cu = id & 3;
            uint32_t soff = r * 64 + (((cu ^ ((r >> 1) & 3))) << 4);
            size_t ga = (size_t)(m0 + r) * lda + k0 + cu * 8;
            size_t gb = (size_t)(n0 + r) * ldb + k0 + cu * 8;
            CP_ASYNC16(sb + soff,         Ahi + ga);
            CP_ASYNC16(sb + 8192  + soff, Alo + ga);
            CP_ASYNC16(sb + 16384 + soff, Bhi + gb);
            CP_ASYNC16(sb + 24576 + soff, Blo + gb);
        }
        CP_COMMIT();
    };

    issue(0, 0);
    issue(1, 32);

    const int rl = lane & 15, ul = lane >> 4;
    for (int it = 0; it < kiters; it++) {
        CP_WAIT1();
        __syncthreads();
        uint32_t sb = sm0 + (it % 3) * 32768;
        #pragma unroll
        for (int k16 = 0; k16 < 2; k16++) {
            uint32_t ahi[4][4], alo[4][4], bhi[2][4], blo[2][4];
            int u = k16 * 2 + ul;
            #pragma unroll
            for (int i = 0; i < 4; i++) {
                int r = wm * 64 + i * 16 + rl;
                uint32_t off = r * 64 + (((u ^ ((r >> 1) & 3))) << 4);
                LDSM4(ahi[i], sb + off);
                LDSM4(alo[i], sb + 8192 + off);
            }
            #pragma unroll
            for (int j2 = 0; j2 < 2; j2++) {
                int r = wn * 32 + j2 * 16 + rl;
                uint32_t off = r * 64 + (((u ^ ((r >> 1) & 3))) << 4);
                LDSM4(bhi[j2], sb + 16384 + off);
                LDSM4(blo[j2], sb + 24576 + off);
            }
            #pragma unroll
            for (int i = 0; i < 4; i++)
                #pragma unroll
                for (int j = 0; j < 4; j++) {
                    int j2 = j >> 1, ts = j & 1;
                    MMA16816(A4.a[i][j], ahi[i], bhi[j2][ts], bhi[j2][ts + 2]);
                    MMA16816(A4.a[i][j], ahi[i], blo[j2][ts], blo[j2][ts + 2]);
                    MMA16816(A4.a[i][j], alo[i], bhi[j2][ts], bhi[j2][ts + 2]);
                }
        }
        __syncthreads();
        if (it + 2 < kiters) issue((it + 2) % 3, (it + 2) * 32);
        else CP_COMMIT();
    }
}

// ---------------- conv GEMM (fixed shape M=512, N=8192, K=KC) ----------------
__global__ void __launch_bounds__(256, 1) conv_hmma_k(
    float* __restrict__ Cout, const float* __restrict__ bias,
    const float* __restrict__ addend) {
    extern __shared__ unsigned char dynsm[];
    const uint32_t sm0 = smem_u32(dynsm);
    const int tid = threadIdx.x, lane = tid & 31, warp = tid >> 5;
    const int m0 = blockIdx.y * 128, n0 = blockIdx.x * 128;
    const int wm = warp & 1, wn = warp >> 1;

    HmmaAcc acc;
    #pragma unroll
    for (int i = 0; i < 4; i++)
        #pragma unroll
        for (int j = 0; j < 4; j++)
            #pragma unroll
            for (int r = 0; r < 4; r++) acc.a[i][j][r] = 0.f;

    hmma_mainloop(acc, sm0, tid, g_whi, g_wlo, KC, g_bhi, g_blo, KC, m0, n0, KITERS);

    const int mrow = m0 + wm * 64 + (lane >> 2);
    const int ncol = n0 + wn * 32 + (lane & 3) * 2;
    #pragma unroll
    for (int i = 0; i < 4; i++) {
        int ma = mrow + i * 16, mb = ma + 8;
        float bva = bias[ma], bvb = bias[mb];
        #pragma unroll
        for (int j = 0; j < 4; j++) {
            int n = ncol + j * 8;
            float2 va = make_float2(acc.a[i][j][0] + bva, acc.a[i][j][1] + bva);
            float2 vb = make_float2(acc.a[i][j][2] + bvb, acc.a[i][j][3] + bvb);
            if (addend) {
                float2 aa = *(const float2*)(addend + (size_t)ma * S_ + n);
                float2 ab = *(const float2*)(addend + (size_t)mb * S_ + n);
                va.x += aa.x; va.y += aa.y; vb.x += ab.x; vb.y += ab.y;
            }
            *(float2*)(Cout + (size_t)ma * S_ + n) = va;
            *(float2*)(Cout + (size_t)mb * S_ + n) = vb;
        }
    }
}

// ---------------- generic attention GEMM ----------------
// biasM: per-row bias; biasN: per-col bias; Cf fp32 out (alpha, addend);
// Chi/Clo packed bf16 out; causal: skip dead score tiles; kcausal: K bound.
__global__ void __launch_bounds__(256, 1) hmma_gemm_k(
    const ushort_t* __restrict__ Ahi, const ushort_t* __restrict__ Alo, int lda,
    const ushort_t* __restrict__ Bhi, const ushort_t* __restrict__ Blo, int ldb,
    float* __restrict__ Cf, ushort_t* __restrict__ Chi, ushort_t* __restrict__ Clo,
    int ldc, int K, float alpha,
    const float* __restrict__ biasM, const float* __restrict__ biasN,
    const float* __restrict__ addend, int causal, int kcausal) {
    const int m0 = blockIdx.y * 128, n0 = blockIdx.x * 128;
    if (causal && n0 >= (((m0 >> 10) + 1) << 10)) return;
    int Keff = kcausal ? (((m0 >> 10) + 1) << 10) : K;

    extern __shared__ unsigned char dynsm[];
    const uint32_t sm0 = smem_u32(dynsm);
    const int tid = threadIdx.x, lane = tid & 31, warp = tid >> 5;
    const int wm = warp & 1, wn = warp >> 1;

    HmmaAcc acc;
    #pragma unroll
    for (int i = 0; i < 4; i++)
        #pragma unroll
        for (int j = 0; j < 4; j++)
            #pragma unroll
            for (int r = 0; r < 4; r++) acc.a[i][j][r] = 0.f;

    hmma_mainloop(acc, sm0, tid, Ahi, Alo, lda, Bhi, Blo, ldb, m0, n0, Keff >> 5);

    const int mrow = m0 + wm * 64 + (lane >> 2);
    const int ncol = n0 + wn * 32 + (lane & 3) * 2;
    #pragma unroll
    for (int i = 0; i < 4; i++) {
        int ma = mrow + i * 16, mb = ma + 8;
        float bva = biasM ? biasM[ma] : 0.f;
        float bvb = biasM ? biasM[mb] : 0.f;
        #pragma unroll
        for (int j = 0; j < 4; j++) {
            int n = ncol + j * 8;
            float2 va = make_float2(acc.a[i][j][0] * alpha + bva, acc.a[i][j][1] * alpha + bva);
            float2 vb = make_float2(acc.a[i][j][2] * alpha + bvb, acc.a[i][j][3] * alpha + bvb);
            if (biasN) {
                float b0 = biasN[n], b1 = biasN[n + 1];
                va.x += b0; va.y += b1; vb.x += b0; vb.y += b1;
            }
            if (addend) {
                float2 aa = *(const float2*)(addend + (size_t)ma * ldc + n);
                float2 ab = *(const float2*)(addend + (size_t)mb * ldc + n);
                va.x += aa.x; va.y += aa.y; vb.x += ab.x; vb.y += ab.y;
            }
            if (Cf) {
                *(float2*)(Cf + (size_t)ma * ldc + n) = va;
                *(float2*)(Cf + (size_t)mb * ldc + n) = vb;
            }
            if (Chi) {
                ushort_t h0, l0, h1, l1;
                split_hilo(va.x, h0, l0); split_hilo(va.y, h1, l1);
                *(ushort2*)(Chi + (size_t)ma * ldc + n) = make_ushort2(h0, h1);
                *(ushort2*)(Clo + (size_t)ma * ldc + n) = make_ushort2(l0, l1);
                split_hilo(vb.x, h0, l0); split_hilo(vb.y, h1, l1);
                *(ushort2*)(Chi + (size_t)mb * ldc + n) = make_ushort2(h0, h1);
                *(ushort2*)(Clo + (size_t)mb * ldc + n) = make_ushort2(l0, l1);
            }
        }
    }
}

// ---------------- softmax: fp32 scores -> packed bf16 probs ----------------
__global__ void softmax_k() {
    int i = blockIdx.x;
    int L = ((i >> 10) + 1) << 10;
    float4* row = (float4*)(g_p + ((size_t)i << 13));
    int n4 = L >> 2;
    int tid = threadIdx.x;
    __shared__ float sh[8];
    float mx = -1e30f;
    for (int j = tid; j < n4; j += 256) {
        float4 v = row[j];
        mx = fmaxf(mx, fmaxf(fmaxf(v.x, v.y), fmaxf(v.z, v.w)));
    }
    float wm = warp_max(mx);
    if ((tid & 31) == 0) sh[tid >> 5] = wm;
    __syncthreads();
    if (tid < 32) {
        float m2 = (tid < 8) ? sh[tid] : -1e30f;
        m2 = warp_max(m2);
        if (tid == 0) sh[0] = m2;
    }
    __syncthreads();
    float m = sh[0];
    __syncthreads();
    float s = 0.f;
    for (int j = tid; j < n4; j += 256) {
        float4 v = row[j];
        v.x = __expf(v.x - m); v.y = __expf(v.y - m);
        v.z = __expf(v.z - m); v.w = __expf(v.w - m);
        s += v.x + v.y + v.z + v.w;
        row[j] = v;
    }
    float ws = warp_sum(s);
    if ((tid & 31) == 0) sh[tid >> 5] = ws;
    __syncthreads();
    if (tid < 32) {
        float s2 = (tid < 8) ? sh[tid] : 0.f;
        s2 = warp_sum(s2);
        if (tid == 0) sh[0] = s2;
    }
    __syncthreads();
    float inv = 1.f / sh[0];
    size_t base = (size_t)i << 13;
    for (int j = tid; j < n4; j += 256) {
        float4 v = row[j];
        v.x *= inv; v.y *= inv; v.z *= inv; v.w *= inv;
        ushort_t h0, l0, h1, l1, h2, l2, h3, l3;
        split_hilo(v.x, h0, l0); split_hilo(v.y, h1, l1);
        split_hilo(v.z, h2, l2); split_hilo(v.w, h3, l3);
        uint2 hv = make_uint2((uint32_t)h0 | ((uint32_t)h1 << 16),
                              (uint32_t)h2 | ((uint32_t)h3 << 16));
        uint2 lv = make_uint2((uint32_t)l0 | ((uint32_t)l1 << 16),
                              (uint32_t)l2 | ((uint32_t)l3 << 16));
        *(uint2*)(g_phi + base + 4 * (size_t)j) = hv;
        *(uint2*)(g_plo + base + 4 * (size_t)j) = lv;
    }
}

// ---------------- orchestration ----------------
extern "C" void kernel_launch(void* const* d_in, const int* in_sizes, int n_in,
                              void* d_out, int out_size) {
    (void)in_sizes; (void)n_in; (void)out_size;

    float *act, *t1, *y0, *mid, *p;
    ushort_t *wahi, *walo, *acth, *actl, *qhi, *qlo, *khi, *klo, *vhi, *vlo;
    ushort_t *ohi, *olo, *phi, *plo, *whi, *wlo;
    cudaGetSymbolAddress((void**)&act,  g_act);
    cudaGetSymbolAddress((void**)&t1,   g_t1);
    cudaGetSymbolAddress((void**)&y0,   g_y0);
    cudaGetSymbolAddress((void**)&mid,  g_mid);
    cudaGetSymbolAddress((void**)&p,    g_p);
    cudaGetSymbolAddress((void**)&wahi, g_wahi);
    cudaGetSymbolAddress((void**)&walo, g_walo);
    cudaGetSymbolAddress((void**)&acth, g_acth);
    cudaGetSymbolAddress((void**)&actl, g_actl);
    cudaGetSymbolAddress((void**)&qhi,  g_qhi);
    cudaGetSymbolAddress((void**)&qlo,  g_qlo);
    cudaGetSymbolAddress((void**)&khi,  g_khi);
    cudaGetSymbolAddress((void**)&klo,  g_klo);
    cudaGetSymbolAddress((void**)&vhi,  g_vhi);
    cudaGetSymbolAddress((void**)&vlo,  g_vlo);
    cudaGetSymbolAddress((void**)&ohi,  g_ohi);
    cudaGetSymbolAddress((void**)&olo,  g_olo);
    cudaGetSymbolAddress((void**)&phi,  g_phi);
    cudaGetSymbolAddress((void**)&plo,  g_plo);
    cudaGetSymbolAddress((void**)&whi,  g_whi);
    cudaGetSymbolAddress((void**)&wlo,  g_wlo);

    cudaFuncSetAttribute(conv_hmma_k, cudaFuncAttributeMaxDynamicSharedMemorySize, 98304);
    cudaFuncSetAttribute(hmma_gemm_k, cudaFuncAttributeMaxDynamicSharedMemorySize, 98304);

    const float* X = (const float*)d_in[0];
    const float* a_gns = (const float*)d_in[17];
    const float* a_gnb = (const float*)d_in[18];
    const float* a_wq  = (const float*)d_in[19];
    const float* a_bq  = (const float*)d_in[20];
    const float* a_wk  = (const float*)d_in[21];
    const float* a_bk  = (const float*)d_in[22];
    const float* a_wv  = (const float*)d_in[23];
    const float* a_bv  = (const float*)d_in[24];
    const float* a_wo  = (const float*)d_in[25];
    const float* a_bo  = (const float*)d_in[26];

    const dim3 conv_grid(64, 4);
    const int IM2COL_BLOCKS = (S_ * (KC / 8)) / 256;   // 55296
    const int WPACK_CONV    = ((C_ * KC) / 8) / 256;   // 3456
    const int WPACK_SQ      = ((C_ * C_) / 8) / 256;   // 128

    auto resnet = [&](const float* in, int base, float* midb, float* outbuf) {
        const float* n1s = (const float*)d_in[base + 0];
        const float* n1b = (const float*)d_in[base + 1];
        const float* w1  = (const float*)d_in[base + 2];
        const float* b1  = (const float*)d_in[base + 3];
        const float* n2s = (const float*)d_in[base + 4];
        const float* n2b = (const float*)d_in[base + 5];
        const float* w2  = (const float*)d_in[base + 6];
        const float* b2  = (const float*)d_in[base + 7];

        gn_stats_k<<<NGROUP, 256>>>(in);
        normact_k<<<(C_ * S_) / 256, 256>>>(in, n1s, n1b, act, 1);
        im2col_pack_k<<<IM2COL_BLOCKS, 256>>>();
        wpack_k<<<WPACK_CONV, 256>>>(w1, whi, wlo);
        conv_hmma_k<<<conv_grid, 256, 98304>>>(midb, b1, nullptr);
        gn_stats_k<<<NGROUP, 256>>>(midb);
        normact_k<<<(C_ * S_) / 256, 256>>>(midb, n2s, n2b, act, 1);
        im2col_pack_k<<<IM2COL_BLOCKS, 256>>>();
        wpack_k<<<WPACK_CONV, 256>>>(w2, whi, wlo);
        conv_hmma_k<<<conv_grid, 256, 98304>>>(outbuf, b2, in);
    };

    // ---- ResNet block 0:  X -> y0 ----
    resnet(X, 1, t1, y0);

    // ---- Causal frame attention on y0 ----
    gn_stats_k<<<NGROUP, 256>>>(y0);
    normact_k<<<(C_ * S_) / 256, 256>>>(y0, a_gns, a_gnb, act, 0);
    atpack_k<<<dim3(S_ / 32, C_ / 32), dim3(32, 8)>>>();

    // Q[s][d] = act_s . wq^T + bq   (packed out)
    wpack_k<<<WPACK_SQ, 256>>>(a_wq, wahi, walo);
    hmma_gemm_k<<<dim3(4, 64), 256, 98304>>>(acth, actl, C_, wahi, walo, C_,
        nullptr, qhi, qlo, C_, C_, 1.f, nullptr, a_bq, nullptr, 0, 0);
    // K[s][d]
    wpack_k<<<WPACK_SQ, 256>>>(a_wk, wahi, walo);
    hmma_gemm_k<<<dim3(4, 64), 256, 98304>>>(acth, actl, C_, wahi, walo, C_,
        nullptr, khi, klo, C_, C_, 1.f, nullptr, a_bk, nullptr, 0, 0);
    // V[d][s]  (C[d][s] = wv . act_s^T + bv per-row)
    wpack_k<<<WPACK_SQ, 256>>>(a_wv, wahi, walo);
    hmma_gemm_k<<<dim3(64, 4), 256, 98304>>>(wahi, walo, C_, acth, actl, C_,
        nullptr, vhi, vlo, S_, C_, 1.f, a_bv, nullptr, nullptr, 0, 0);

    // scores[q][k] fp32 (block-causal tile skip)
    hmma_gemm_k<<<dim3(64, 64), 256, 98304>>>(qhi, qlo, C_, khi, klo, C_,
        p, nullptr, nullptr, S_, C_, 0.04419417382415922f,
        nullptr, nullptr, nullptr, 1, 0);
    softmax_k<<<S_, 256>>>();
    // O[s][d] = P . V^T  (packed out, causal K bound)
    hmma_gemm_k<<<dim3(4, 64), 256, 98304>>>(phi, plo, S_, vhi, vlo, S_,
        nullptr, ohi, olo, C_, S_, 1.f, nullptr, nullptr, nullptr, 0, 1);
    // attnout[c][s] = wo . O^T + bo + y0
    wpack_k<<<WPACK_SQ, 256>>>(a_wo, wahi, walo);
    hmma_gemm_k<<<dim3(64, 4), 256, 98304>>>(wahi, walo, C_, ohi, olo, C_,
        t1, nullptr, nullptr, S_, C_, 1.f, a_bo, nullptr, y0, 0, 0);

    // ---- ResNet block 1:  t1 -> d_out ----
    resnet(t1, 9, mid, (float*)d_out);
}

// round 6
// speedup vs baseline: 2.3426x; 1.0920x over previous
#include <cuda_runtime.h>
#include <cuda_bf16.h>
#include <math.h>
#include <stdint.h>

#define C_      512
#define S_      8192
#define HW_     1024
#define W_      32
#define NGROUP  32
#define CPG     16
#define KC      13824
#define NSPLIT  4
#define KSPLIT_ITERS 108      // (KC/32)/4

typedef unsigned short ushort_t;

__device__ float g_mean[NGROUP];
__device__ float g_rstd[NGROUP];
__device__ float g_act[(size_t)C_ * S_];
__device__ float g_t1 [(size_t)C_ * S_];
__device__ float g_y0 [(size_t)C_ * S_];
__device__ float g_mid[(size_t)C_ * S_];
__device__ float g_p  [(size_t)S_ * S_];
__device__ float g_ks [(size_t)NSPLIT * C_ * S_];            // split-K partials (67MB)
// conv operands (row-major bf16 hi/lo)
__device__ __align__(16) ushort_t g_whi[(size_t)C_ * KC];
__device__ __align__(16) ushort_t g_wlo[(size_t)C_ * KC];
__device__ __align__(16) ushort_t g_bhi[(size_t)S_ * KC];
__device__ __align__(16) ushort_t g_blo[(size_t)S_ * KC];
// attention packed operands
__device__ __align__(16) ushort_t g_acth[(size_t)S_ * C_];
__device__ __align__(16) ushort_t g_actl[(size_t)S_ * C_];
__device__ __align__(16) ushort_t g_wahi[(size_t)C_ * C_];
__device__ __align__(16) ushort_t g_walo[(size_t)C_ * C_];
__device__ __align__(16) ushort_t g_qhi[(size_t)S_ * C_];
__device__ __align__(16) ushort_t g_qlo[(size_t)S_ * C_];
__device__ __align__(16) ushort_t g_khi[(size_t)S_ * C_];
__device__ __align__(16) ushort_t g_klo[(size_t)S_ * C_];
__device__ __align__(16) ushort_t g_vhi[(size_t)C_ * S_];
__device__ __align__(16) ushort_t g_vlo[(size_t)C_ * S_];
__device__ __align__(16) ushort_t g_ohi[(size_t)S_ * C_];
__device__ __align__(16) ushort_t g_olo[(size_t)S_ * C_];
__device__ __align__(16) ushort_t g_phi[(size_t)S_ * S_];
__device__ __align__(16) ushort_t g_plo[(size_t)S_ * S_];

// ---------------- PTX helpers ----------------
__device__ __forceinline__ uint32_t smem_u32(const void* p) {
    uint32_t a;
    asm("{ .reg .u64 t; cvta.to.shared.u64 t, %1; cvt.u32.u64 %0, t; }" : "=r"(a) : "l"(p));
    return a;
}
#define CP_ASYNC16(smem, gmem) \
    asm volatile("cp.async.cg.shared.global [%0], [%1], 16;" :: "r"(smem), "l"(gmem) : "memory")
#define CP_COMMIT() asm volatile("cp.async.commit_group;" ::: "memory")
#define CP_WAIT1()  asm volatile("cp.async.wait_group 1;" ::: "memory")
#define CP_WAIT2()  asm volatile("cp.async.wait_group 2;" ::: "memory")
#define LDSM4(r, addr) \
    asm volatile("ldmatrix.sync.aligned.m8n8.x4.shared.b16 {%0,%1,%2,%3}, [%4];" \
        : "=r"((r)[0]),"=r"((r)[1]),"=r"((r)[2]),"=r"((r)[3]) : "r"(addr))
#define MMA16816(d, a, b0, b1) \
    asm volatile("mma.sync.aligned.m16n8k16.row.col.f32.bf16.bf16.f32 " \
        "{%0,%1,%2,%3}, {%4,%5,%6,%7}, {%8,%9}, {%0,%1,%2,%3};" \
        : "+f"((d)[0]),"+f"((d)[1]),"+f"((d)[2]),"+f"((d)[3]) \
        : "r"((a)[0]),"r"((a)[1]),"r"((a)[2]),"r"((a)[3]), "r"(b0),"r"(b1))

__device__ __forceinline__ void split_hilo(float v, ushort_t& h, ushort_t& l) {
    uint32_t u = __float_as_uint(v);
    h = (ushort_t)(u >> 16);
    float rem = v - __uint_as_float(u & 0xffff0000u);
    l = __bfloat16_as_ushort(__float2bfloat16(rem));
}

__inline__ __device__ float warp_sum(float v) {
    #pragma unroll
    for (int o = 16; o; o >>= 1) v += __shfl_down_sync(0xffffffffu, v, o);
    return v;
}
__inline__ __device__ float warp_max(float v) {
    #pragma unroll
    for (int o = 16; o; o >>= 1) v = fmaxf(v, __shfl_down_sync(0xffffffffu, v, o));
    return v;
}

// ---------------- GroupNorm stats ----------------
__global__ void gn_stats_k(const float* __restrict__ x) {
    int g = blockIdx.x;
    const float4* p = (const float4*)(x + (size_t)g * CPG * S_);
    const int n4 = (CPG * S_) / 4;
    float s = 0.f, s2 = 0.f;
    for (int i = threadIdx.x; i < n4; i += blockDim.x) {
        float4 v = p[i];
        s  += v.x + v.y + v.z + v.w;
        s2 += v.x * v.x + v.y * v.y + v.z * v.z + v.w * v.w;
    }
    __shared__ float sh0[8], sh1[8];
    float ws = warp_sum(s), ws2 = warp_sum(s2);
    int wid = threadIdx.x >> 5, lid = threadIdx.x & 31;
    if (!lid) { sh0[wid] = ws; sh1[wid] = ws2; }
    __syncthreads();
    if (threadIdx.x == 0) {
        float a = 0.f, b = 0.f;
        #pragma unroll
        for (int i = 0; i < 8; i++) { a += sh0[i]; b += sh1[i]; }
        const float inv_n = 1.f / (float)(CPG * S_);
        float m = a * inv_n;
        g_mean[g] = m;
        g_rstd[g] = rsqrtf(b * inv_n - m * m + 1e-6f);
    }
}

__global__ void normact_k(const float* __restrict__ x, const float* __restrict__ sc,
                          const float* __restrict__ bi, float* __restrict__ out, int do_silu) {
    int i = blockIdx.x * blockDim.x + threadIdx.x;
    int c = i >> 13;
    int g = c >> 4;
    float v = (x[i] - g_mean[g]) * g_rstd[g] * sc[c] + bi[c];
    if (do_silu) v = v / (1.f + __expf(-v));
    out[i] = v;
}

// ---------------- im2col -> row-major bf16 hi/lo [pos][KC] ----------------
__global__ void im2col_pack_k() {
    size_t id = (size_t)blockIdx.x * 256 + threadIdx.x;
    int pos = (int)(id / 1728);
    int kc  = (int)(id - (size_t)pos * 1728);
    int k0 = kc * 8;
    int t = pos >> 10, rem = pos & 1023, y = rem >> 5, x = rem & 31;
    __align__(16) ushort_t hi[8], lo[8];
    #pragma unroll
    for (int e = 0; e < 8; e++) {
        int k = k0 + e;
        int ci = k / 27; int r = k - ci * 27;
        int kd = r / 9;  r -= kd * 9;
        int kh = r / 3;  int kw = r - kh * 3;
        int ts = min(max(t + kd - 2, 0), 7);
        int ys = min(max(y + kh - 1, 0), 31);
        int xs = min(max(x + kw - 1, 0), 31);
        float v = g_act[(size_t)ci * S_ + ts * HW_ + ys * W_ + xs];
        split_hilo(v, hi[e], lo[e]);
    }
    size_t off = (size_t)pos * KC + k0;
    *(uint4*)(g_bhi + off) = *(uint4*)hi;
    *(uint4*)(g_blo + off) = *(uint4*)lo;
}

// ---------------- generic pack: fp32 row-major -> bf16 hi/lo ----------------
__global__ void wpack_k(const float* __restrict__ w, ushort_t* __restrict__ dhi,
                        ushort_t* __restrict__ dlo) {
    size_t id = (size_t)blockIdx.x * 256 + threadIdx.x;
    const float4* src = (const float4*)w;
    float4 v0 = src[id * 2], v1 = src[id * 2 + 1];
    __align__(16) ushort_t hi[8], lo[8];
    split_hilo(v0.x, hi[0], lo[0]); split_hilo(v0.y, hi[1], lo[1]);
    split_hilo(v0.z, hi[2], lo[2]); split_hilo(v0.w, hi[3], lo[3]);
    split_hilo(v1.x, hi[4], lo[4]); split_hilo(v1.y, hi[5], lo[5]);
    split_hilo(v1.z, hi[6], lo[6]); split_hilo(v1.w, hi[7], lo[7]);
    *(uint4*)(dhi + id * 8) = *(uint4*)hi;
    *(uint4*)(dlo + id * 8) = *(uint4*)lo;
}

// ---------------- transpose-pack: act [c][s] -> hi/lo [s][c] ----------------
__global__ void atpack_k() {
    __shared__ float tile[32][33];
    int s0 = blockIdx.x * 32, c0 = blockIdx.y * 32;
    int tx = threadIdx.x, ty = threadIdx.y;
    #pragma unroll
    for (int i = ty; i < 32; i += 8)
        tile[i][tx] = g_act[(size_t)(c0 + i) * S_ + s0 + tx];
    __syncthreads();
    #pragma unroll
    for (int i = ty; i < 32; i += 8) {
        float v = tile[tx][i];
        ushort_t h, l;
        split_hilo(v, h, l);
        size_t off = (size_t)(s0 + i) * C_ + c0 + tx;
        g_acth[off] = h;
        g_actl[off] = l;
    }
}

// ---------------- split-K reduce: out = sum4(partials) + bias (+addend) ----------
__global__ void ksum_k(float* __restrict__ out, const float* __restrict__ bias,
                       const float* __restrict__ addend) {
    size_t i = ((size_t)blockIdx.x * 256 + threadIdx.x) * 4;
    int c = (int)(i >> 13);
    float4 v0 = *(const float4*)(g_ks + i);
    float4 v1 = *(const float4*)(g_ks + (size_t)C_ * S_ + i);
    float4 v2 = *(const float4*)(g_ks + (size_t)2 * C_ * S_ + i);
    float4 v3 = *(const float4*)(g_ks + (size_t)3 * C_ * S_ + i);
    float bv = bias[c];
    float4 r;
    r.x = v0.x + v1.x + v2.x + v3.x + bv;
    r.y = v0.y + v1.y + v2.y + v3.y + bv;
    r.z = v0.z + v1.z + v2.z + v3.z + bv;
    r.w = v0.w + v1.w + v2.w + v3.w + bv;
    if (addend) {
        float4 a = *(const float4*)(addend + i);
        r.x += a.x; r.y += a.y; r.z += a.z; r.w += a.w;
    }
    *(float4*)(out + i) = r;
}

// ================= HMMA mainloops =================
struct HmmaAcc { float a[4][4][4]; };

// 3-stage (attention)
__device__ __forceinline__ void hmma_mainloop(
    HmmaAcc& A4, uint32_t sm0, int tid,
    const ushort_t* __restrict__ Ahi, const ushort_t* __restrict__ Alo, int lda,
    const ushort_t* __restrict__ Bhi, const ushort_t* __restrict__ Blo, int ldb,
    int m0, int n0, int kiters) {
    const int lane = tid & 31, warp = tid >> 5;
    const int wm = warp & 1, wn = warp >> 1;

    auto issue = [&](int stage, int k0) {
        uint32_t sb = sm0 + stage * 32768;
        #pragma unroll
        for (int h = 0; h < 2; h++) {
            int id = tid + h * 256;
            int r = id >> 2, cu = id & 3;
            uint32_t soff = r * 64 + (((cu ^ ((r >> 1) & 3))) << 4);
            size_t ga = (size_t)(m0 + r) * lda + k0 + cu * 8;
            size_t gb = (size_t)(n0 + r) * ldb + k0 + cu * 8;
            CP_ASYNC16(sb + soff,         Ahi + ga);
            CP_ASYNC16(sb + 8192  + soff, Alo + ga);
            CP_ASYNC16(sb + 16384 + soff, Bhi + gb);
            CP_ASYNC16(sb + 24576 + soff, Blo + gb);
        }
        CP_COMMIT();
    };

    issue(0, 0);
    issue(1, 32);

    const int rl = lane & 15, ul = lane >> 4;
    for (int it = 0; it < kiters; it++) {
        CP_WAIT1();
        __syncthreads();
        uint32_t sb = sm0 + (it % 3) * 32768;
        #pragma unroll
        for (int k16 = 0; k16 < 2; k16++) {
            uint32_t ahi[4][4], alo[4][4], bhi[2][4], blo[2][4];
            int u = k16 * 2 + ul;
            #pragma unroll
            for (int i = 0; i < 4; i++) {
                int r = wm * 64 + i * 16 + rl;
                uint32_t off = r * 64 + (((u ^ ((r >> 1) & 3))) << 4);
                LDSM4(ahi[i], sb + off);
                LDSM4(alo[i], sb + 8192 + off);
            }
            #pragma unroll
            for (int j2 = 0; j2 < 2; j2++) {
                int r = wn * 32 + j2 * 16 + rl;
                uint32_t off = r * 64 + (((u ^ ((r >> 1) & 3))) << 4);
                LDSM4(bhi[j2], sb + 16384 + off);
                LDSM4(blo[j2], sb + 24576 + off);
            }
            #pragma unroll
            for (int i = 0; i < 4; i++)
                #pragma unroll
                for (int j = 0; j < 4; j++) {
                    int j2 = j >> 1, ts = j & 1;
                    MMA16816(A4.a[i][j], ahi[i], bhi[j2][ts], bhi[j2][ts + 2]);
                    MMA16816(A4.a[i][j], ahi[i], blo[j2][ts], blo[j2][ts + 2]);
                    MMA16816(A4.a[i][j], alo[i], bhi[j2][ts], bhi[j2][ts + 2]);
                }
        }
        __syncthreads();
        if (it + 2 < kiters) issue((it + 2) % 3, (it + 2) * 32);
        else CP_COMMIT();
    }
}

// ---------------- conv GEMM, split-K, 4-stage ----------------
// grid (16, 64): x -> m-tile (x&3), ksplit (x>>2); y -> n-tile
__global__ void __launch_bounds__(256, 1) conv_hmma_k() {
    extern __shared__ unsigned char dynsm[];
    const uint32_t sm0 = smem_u32(dynsm);
    const int tid = threadIdx.x, lane = tid & 31, warp = tid >> 5;
    const int m0 = (blockIdx.x & 3) * 128;
    const int ks = blockIdx.x >> 2;
    const int n0 = blockIdx.y * 128;
    const int kbase = ks * (KSPLIT_ITERS * 32);
    const int wm = warp & 1, wn = warp >> 1;

    auto issue = [&](int stage, int k0) {
        uint32_t sb = sm0 + stage * 32768;
        #pragma unroll
        for (int h = 0; h < 2; h++) {
            int id = tid + h * 256;
            int r = id >> 2, cu = id & 3;
            uint32_t soff = r * 64 + (((cu ^ ((r >> 1) & 3))) << 4);
            size_t ga = (size_t)(m0 + r) * KC + k0 + cu * 8;
            size_t gb = (size_t)(n0 + r) * KC + k0 + cu * 8;
            CP_ASYNC16(sb + soff,         g_whi + ga);
            CP_ASYNC16(sb + 8192  + soff, g_wlo + ga);
            CP_ASYNC16(sb + 16384 + soff, g_bhi + gb);
            CP_ASYNC16(sb + 24576 + soff, g_blo + gb);
        }
        CP_COMMIT();
    };

    float acc[4][4][4];
    #pragma unroll
    for (int i = 0; i < 4; i++)
        #pragma unroll
        for (int j = 0; j < 4; j++)
            #pragma unroll
            for (int r = 0; r < 4; r++) acc[i][j][r] = 0.f;

    issue(0, kbase);
    issue(1, kbase + 32);
    issue(2, kbase + 64);

    const int rl = lane & 15, ul = lane >> 4;
    for (int it = 0; it < KSPLIT_ITERS; it++) {
        CP_WAIT2();
        __syncthreads();
        uint32_t sb = sm0 + (it & 3) * 32768;
        #pragma unroll
        for (int k16 = 0; k16 < 2; k16++) {
            uint32_t ahi[4][4], alo[4][4], bhi[2][4], blo[2][4];
            int u = k16 * 2 + ul;
            #pragma unroll
            for (int i = 0; i < 4; i++) {
                int r = wm * 64 + i * 16 + rl;
                uint32_t off = r * 64 + (((u ^ ((r >> 1) & 3))) << 4);
                LDSM4(ahi[i], sb + off);
                LDSM4(alo[i], sb + 8192 + off);
            }
            #pragma unroll
            for (int j2 = 0; j2 < 2; j2++) {
                int r = wn * 32 + j2 * 16 + rl;
                uint32_t off = r * 64 + (((u ^ ((r >> 1) & 3))) << 4);
                LDSM4(bhi[j2], sb + 16384 + off);
                LDSM4(blo[j2], sb + 24576 + off);
            }
            #pragma unroll
            for (int i = 0; i < 4; i++)
                #pragma unroll
                for (int j = 0; j < 4; j++) {
                    int j2 = j >> 1, ts = j & 1;
                    MMA16816(acc[i][j], ahi[i], bhi[j2][ts], bhi[j2][ts + 2]);
                    MMA16816(acc[i][j], ahi[i], blo[j2][ts], blo[j2][ts + 2]);
                    MMA16816(acc[i][j], alo[i], bhi[j2][ts], bhi[j2][ts + 2]);
                }
        }
        __syncthreads();
        if (it + 3 < KSPLIT_ITERS) issue((it + 3) & 3, kbase + (it + 3) * 32);
        else CP_COMMIT();
    }

    float* Sp = g_ks + (size_t)ks * C_ * S_;
    const int mrow = m0 + wm * 64 + (lane >> 2);
    const int ncol = n0 + wn * 32 + (lane & 3) * 2;
    #pragma unroll
    for (int i = 0; i < 4; i++) {
        int ma = mrow + i * 16, mb = ma + 8;
        #pragma unroll
        for (int j = 0; j < 4; j++) {
            int n = ncol + j * 8;
            *(float2*)(Sp + (size_t)ma * S_ + n) = make_float2(acc[i][j][0], acc[i][j][1]);
            *(float2*)(Sp + (size_t)mb * S_ + n) = make_float2(acc[i][j][2], acc[i][j][3]);
        }
    }
}

// ---------------- generic attention GEMM ----------------
__global__ void __launch_bounds__(256, 1) hmma_gemm_k(
    const ushort_t* __restrict__ Ahi, const ushort_t* __restrict__ Alo, int lda,
    const ushort_t* __restrict__ Bhi, const ushort_t* __restrict__ Blo, int ldb,
    float* __restrict__ Cf, ushort_t* __restrict__ Chi, ushort_t* __restrict__ Clo,
    int ldc, int K, float alpha,
    const float* __restrict__ biasM, const float* __restrict__ biasN,
    const float* __restrict__ addend, int causal, int kcausal, int mrev) {
    const int by = mrev ? (gridDim.y - 1 - blockIdx.y) : blockIdx.y;
    const int m0 = by * 128, n0 = blockIdx.x * 128;
    if (causal && n0 >= (((m0 >> 10) + 1) << 10)) return;
    int Keff = kcausal ? (((m0 >> 10) + 1) << 10) : K;

    extern __shared__ unsigned char dynsm[];
    const uint32_t sm0 = smem_u32(dynsm);
    const int tid = threadIdx.x, lane = tid & 31, warp = tid >> 5;
    const int wm = warp & 1, wn = warp >> 1;

    HmmaAcc acc;
    #pragma unroll
    for (int i = 0; i < 4; i++)
        #pragma unroll
        for (int j = 0; j < 4; j++)
            #pragma unroll
            for (int r = 0; r < 4; r++) acc.a[i][j][r] = 0.f;

    hmma_mainloop(acc, sm0, tid, Ahi, Alo, lda, Bhi, Blo, ldb, m0, n0, Keff >> 5);

    const int mrow = m0 + wm * 64 + (lane >> 2);
    const int ncol = n0 + wn * 32 + (lane & 3) * 2;
    #pragma unroll
    for (int i = 0; i < 4; i++) {
        int ma = mrow + i * 16, mb = ma + 8;
        float bva = biasM ? biasM[ma] : 0.f;
        float bvb = biasM ? biasM[mb] : 0.f;
        #pragma unroll
        for (int j = 0; j < 4; j++) {
            int n = ncol + j * 8;
            float2 va = make_float2(acc.a[i][j][0] * alpha + bva, acc.a[i][j][1] * alpha + bva);
            float2 vb = make_float2(acc.a[i][j][2] * alpha + bvb, acc.a[i][j][3] * alpha + bvb);
            if (biasN) {
                float b0 = biasN[n], b1 = biasN[n + 1];
                va.x += b0; va.y += b1; vb.x += b0; vb.y += b1;
            }
            if (addend) {
                float2 aa = *(const float2*)(addend + (size_t)ma * ldc + n);
                float2 ab = *(const float2*)(addend + (size_t)mb * ldc + n);
                va.x += aa.x; va.y += aa.y; vb.x += ab.x; vb.y += ab.y;
            }
            if (Cf) {
                *(float2*)(Cf + (size_t)ma * ldc + n) = va;
                *(float2*)(Cf + (size_t)mb * ldc + n) = vb;
            }
            if (Chi) {
                ushort_t h0, l0, h1, l1;
                split_hilo(va.x, h0, l0); split_hilo(va.y, h1, l1);
                *(ushort2*)(Chi + (size_t)ma * ldc + n) = make_ushort2(h0, h1);
                *(ushort2*)(Clo + (size_t)ma * ldc + n) = make_ushort2(l0, l1);
                split_hilo(vb.x, h0, l0); split_hilo(vb.y, h1, l1);
                *(ushort2*)(Chi + (size_t)mb * ldc + n) = make_ushort2(h0, h1);
                *(ushort2*)(Clo + (size_t)mb * ldc + n) = make_ushort2(l0, l1);
            }
        }
    }
}

// ---------------- softmax: fp32 scores -> packed bf16 probs ----------------
__global__ void softmax_k() {
    int i = blockIdx.x;
    int L = ((i >> 10) + 1) << 10;
    float4* row = (float4*)(g_p + ((size_t)i << 13));
    int n4 = L >> 2;
    int tid = threadIdx.x;
    __shared__ float sh[8];
    float mx = -1e30f;
    for (int j = tid; j < n4; j += 256) {
        float4 v = row[j];
        mx = fmaxf(mx, fmaxf(fmaxf(v.x, v.y), fmaxf(v.z, v.w)));
    }
    float wm = warp_max(mx);
    if ((tid & 31) == 0) sh[tid >> 5] = wm;
    __syncthreads();
    if (tid < 32) {
        float m2 = (tid < 8) ? sh[tid] : -1e30f;
        m2 = warp_max(m2);
        if (tid == 0) sh[0] = m2;
    }
    __syncthreads();
    float m = sh[0];
    __syncthreads();
    float s = 0.f;
    for (int j = tid; j < n4; j += 256) {
        float4 v = row[j];
        v.x = __expf(v.x - m); v.y = __expf(v.y - m);
        v.z = __expf(v.z - m); v.w = __expf(v.w - m);
        s += v.x + v.y + v.z + v.w;
        row[j] = v;
    }
    float ws = warp_sum(s);
    if ((tid & 31) == 0) sh[tid >> 5] = ws;
    __syncthreads();
    if (tid < 32) {
        float s2 = (tid < 8) ? sh[tid] : 0.f;
        s2 = warp_sum(s2);
        if (tid == 0) sh[0] = s2;
    }
    __syncthreads();
    float inv = 1.f / sh[0];
    size_t base = (size_t)i << 13;
    for (int j = tid; j < n4; j += 256) {
        float4 v = row[j];
        v.x *= inv; v.y *= inv; v.z *= inv; v.w *= inv;
        ushort_t h0, l0, h1, l1, h2, l2, h3, l3;
        split_hilo(v.x, h0, l0); split_hilo(v.y, h1, l1);
        split_hilo(v.z, h2, l2); split_hilo(v.w, h3, l3);
        uint2 hv = make_uint2((uint32_t)h0 | ((uint32_t)h1 << 16),
                              (uint32_t)h2 | ((uint32_t)h3 << 16));
        uint2 lv = make_uint2((uint32_t)l0 | ((uint32_t)l1 << 16),
                              (uint32_t)l2 | ((uint32_t)l3 << 16));
        *(uint2*)(g_phi + base + 4 * (size_t)j) = hv;
        *(uint2*)(g_plo + base + 4 * (size_t)j) = lv;
    }
}

// ---------------- orchestration ----------------
extern "C" void kernel_launch(void* const* d_in, const int* in_sizes, int n_in,
                              void* d_out, int out_size) {
    (void)in_sizes; (void)n_in; (void)out_size;

    float *act, *t1, *y0, *mid, *p;
    ushort_t *wahi, *walo, *acth, *actl, *qhi, *qlo, *khi, *klo, *vhi, *vlo;
    ushort_t *ohi, *olo, *phi, *plo, *whi, *wlo;
    cudaGetSymbolAddress((void**)&act,  g_act);
    cudaGetSymbolAddress((void**)&t1,   g_t1);
    cudaGetSymbolAddress((void**)&y0,   g_y0);
    cudaGetSymbolAddress((void**)&mid,  g_mid);
    cudaGetSymbolAddress((void**)&p,    g_p);
    cudaGetSymbolAddress((void**)&wahi, g_wahi);
    cudaGetSymbolAddress((void**)&walo, g_walo);
    cudaGetSymbolAddress((void**)&acth, g_acth);
    cudaGetSymbolAddress((void**)&actl, g_actl);
    cudaGetSymbolAddress((void**)&qhi,  g_qhi);
    cudaGetSymbolAddress((void**)&qlo,  g_qlo);
    cudaGetSymbolAddress((void**)&khi,  g_khi);
    cudaGetSymbolAddress((void**)&klo,  g_klo);
    cudaGetSymbolAddress((void**)&vhi,  g_vhi);
    cudaGetSymbolAddress((void**)&vlo,  g_vlo);
    cudaGetSymbolAddress((void**)&ohi,  g_ohi);
    cudaGetSymbolAddress((void**)&olo,  g_olo);
    cudaGetSymbolAddress((void**)&phi,  g_phi);
    cudaGetSymbolAddress((void**)&plo,  g_plo);
    cudaGetSymbolAddress((void**)&whi,  g_whi);
    cudaGetSymbolAddress((void**)&wlo,  g_wlo);

    cudaFuncSetAttribute(conv_hmma_k, cudaFuncAttributeMaxDynamicSharedMemorySize, 131072);
    cudaFuncSetAttribute(hmma_gemm_k, cudaFuncAttributeMaxDynamicSharedMemorySize, 98304);

    const float* X = (const float*)d_in[0];
    const float* a_gns = (const float*)d_in[17];
    const float* a_gnb = (const float*)d_in[18];
    const float* a_wq  = (const float*)d_in[19];
    const float* a_bq  = (const float*)d_in[20];
    const float* a_wk  = (const float*)d_in[21];
    const float* a_bk  = (const float*)d_in[22];
    const float* a_wv  = (const float*)d_in[23];
    const float* a_bv  = (const float*)d_in[24];
    const float* a_wo  = (const float*)d_in[25];
    const float* a_bo  = (const float*)d_in[26];

    const dim3 conv_grid(16, 64);         // (m,ksplit) x n
    const int IM2COL_BLOCKS = (S_ * (KC / 8)) / 256;
    const int WPACK_CONV    = ((C_ * KC) / 8) / 256;
    const int WPACK_SQ      = ((C_ * C_) / 8) / 256;
    const int KSUM_BLOCKS   = (C_ * S_ / 4) / 256;

    auto resnet = [&](const float* in, int base, float* midb, float* outbuf) {
        const float* n1s = (const float*)d_in[base + 0];
        const float* n1b = (const float*)d_in[base + 1];
        const float* w1  = (const float*)d_in[base + 2];
        const float* b1  = (const float*)d_in[base + 3];
        const float* n2s = (const float*)d_in[base + 4];
        const float* n2b = (const float*)d_in[base + 5];
        const float* w2  = (const float*)d_in[base + 6];
        const float* b2  = (const float*)d_in[base + 7];

        gn_stats_k<<<NGROUP, 256>>>(in);
        normact_k<<<(C_ * S_) / 256, 256>>>(in, n1s, n1b, act, 1);
        im2col_pack_k<<<IM2COL_BLOCKS, 256>>>();
        wpack_k<<<WPACK_CONV, 256>>>(w1, whi, wlo);
        conv_hmma_k<<<conv_grid, 256, 131072>>>();
        ksum_k<<<KSUM_BLOCKS, 256>>>(midb, b1, nullptr);
        gn_stats_k<<<NGROUP, 256>>>(midb);
        normact_k<<<(C_ * S_) / 256, 256>>>(midb, n2s, n2b, act, 1);
        im2col_pack_k<<<IM2COL_BLOCKS, 256>>>();
        wpack_k<<<WPACK_CONV, 256>>>(w2, whi, wlo);
        conv_hmma_k<<<conv_grid, 256, 131072>>>();
        ksum_k<<<KSUM_BLOCKS, 256>>>(outbuf, b2, in);
    };

    // ---- ResNet block 0:  X -> y0 ----
    resnet(X, 1, t1, y0);

    // ---- Causal frame attention on y0 ----
    gn_stats_k<<<NGROUP, 256>>>(y0);
    normact_k<<<(C_ * S_) / 256, 256>>>(y0, a_gns, a_gnb, act, 0);
    atpack_k<<<dim3(S_ / 32, C_ / 32), dim3(32, 8)>>>();

    wpack_k<<<WPACK_SQ, 256>>>(a_wq, wahi, walo);
    hmma_gemm_k<<<dim3(4, 64), 256, 98304>>>(acth, actl, C_, wahi, walo, C_,
        nullptr, qhi, qlo, C_, C_, 1.f, nullptr, a_bq, nullptr, 0, 0, 0);
    wpack_k<<<WPACK_SQ, 256>>>(a_wk, wahi, walo);
    hmma_gemm_k<<<dim3(4, 64), 256, 98304>>>(acth, actl, C_, wahi, walo, C_,
        nullptr, khi, klo, C_, C_, 1.f, nullptr, a_bk, nullptr, 0, 0, 0);
    wpack_k<<<WPACK_SQ, 256>>>(a_wv, wahi, walo);
    hmma_gemm_k<<<dim3(64, 4), 256, 98304>>>(wahi, walo, C_, acth, actl, C_,
        nullptr, vhi, vlo, S_, C_, 1.f, a_bv, nullptr, nullptr, 0, 0, 0);

    hmma_gemm_k<<<dim3(64, 64), 256, 98304>>>(qhi, qlo, C_, khi, klo, C_,
        p, nullptr, nullptr, S_, C_, 0.04419417382415922f,
        nullptr, nullptr, nullptr, 1, 0, 0);
    softmax_k<<<S_, 256>>>();
    // P·V: reversed m-order so longest-K CTAs launch first
    hmma_gemm_k<<<dim3(4, 64), 256, 98304>>>(phi, plo, S_, vhi, vlo, S_,
        nullptr, ohi, olo, C_, S_, 1.f, nullptr, nullptr, nullptr, 0, 1, 1);
    wpack_k<<<WPACK_SQ, 256>>>(a_wo, wahi, walo);
    hmma_gemm_k<<<dim3(64, 4), 256, 98304>>>(wahi, walo, C_, ohi, olo, C_,
        t1, nullptr, nullptr, S_, C_, 1.f, a_bo, nullptr, y0, 0, 0, 0);

    // ---- ResNet block 1:  t1 -> d_out ----
    resnet(t1, 9, mid, (float*)d_out);
}

// round 7
// speedup vs baseline: 3.2710x; 1.3963x over previous
#include <cuda_runtime.h>
#include <cuda_fp16.h>
#include <math.h>
#include <stdint.h>

#define C_      512
#define S_      8192
#define HW_     1024
#define W_      32
#define NGROUP  32
#define CPG     16
#define KC      13824
#define NSPLIT  4
#define KSPLIT_ITERS 108      // (KC/32)/4

// smem stage: Ahi 8K | Alo 8K | Bh 8K
#define STG 24576

typedef unsigned short ushort_t;

__device__ float g_mean[NGROUP];
__device__ float g_rstd[NGROUP];
__device__ float g_act[(size_t)C_ * S_];
__device__ float g_t1 [(size_t)C_ * S_];
__device__ float g_y0 [(size_t)C_ * S_];
__device__ float g_mid[(size_t)C_ * S_];
__device__ float g_p  [(size_t)S_ * S_];
__device__ float g_ks [(size_t)NSPLIT * C_ * S_];
// conv operands (fp16): weights split hi/lo, im2col single
__device__ __align__(16) ushort_t g_whi[(size_t)C_ * KC];
__device__ __align__(16) ushort_t g_wlo[(size_t)C_ * KC];
__device__ __align__(16) ushort_t g_bh [(size_t)S_ * KC];
// attention packed operands (fp16 hi/lo; "hi" doubles as rounded-single)
__device__ __align__(16) ushort_t g_acth[(size_t)S_ * C_];
__device__ __align__(16) ushort_t g_actl[(size_t)S_ * C_];
__device__ __align__(16) ushort_t g_wahi[(size_t)C_ * C_];
__device__ __align__(16) ushort_t g_walo[(size_t)C_ * C_];
__device__ __align__(16) ushort_t g_qhi[(size_t)S_ * C_];
__device__ __align__(16) ushort_t g_qlo[(size_t)S_ * C_];
__device__ __align__(16) ushort_t g_khi[(size_t)S_ * C_];
__device__ __align__(16) ushort_t g_klo[(size_t)S_ * C_];
__device__ __align__(16) ushort_t g_vhi[(size_t)C_ * S_];
__device__ __align__(16) ushort_t g_vlo[(size_t)C_ * S_];
__device__ __align__(16) ushort_t g_ohi[(size_t)S_ * C_];
__device__ __align__(16) ushort_t g_olo[(size_t)S_ * C_];
__device__ __align__(16) ushort_t g_phi[(size_t)S_ * S_];
__device__ __align__(16) ushort_t g_plo[(size_t)S_ * S_];

// ---------------- PTX helpers ----------------
__device__ __forceinline__ uint32_t smem_u32(const void* p) {
    uint32_t a;
    asm("{ .reg .u64 t; cvta.to.shared.u64 t, %1; cvt.u32.u64 %0, t; }" : "=r"(a) : "l"(p));
    return a;
}
#define CP_ASYNC16(smem, gmem) \
    asm volatile("cp.async.cg.shared.global [%0], [%1], 16;" :: "r"(smem), "l"(gmem) : "memory")
#define CP_COMMIT() asm volatile("cp.async.commit_group;" ::: "memory")
#define CP_WAIT1()  asm volatile("cp.async.wait_group 1;" ::: "memory")
#define CP_WAIT2()  asm volatile("cp.async.wait_group 2;" ::: "memory")
#define LDSM4(r, addr) \
    asm volatile("ldmatrix.sync.aligned.m8n8.x4.shared.b16 {%0,%1,%2,%3}, [%4];" \
        : "=r"((r)[0]),"=r"((r)[1]),"=r"((r)[2]),"=r"((r)[3]) : "r"(addr))
#define MMA16816(d, a, b0, b1) \
    asm volatile("mma.sync.aligned.m16n8k16.row.col.f32.f16.f16.f32 " \
        "{%0,%1,%2,%3}, {%4,%5,%6,%7}, {%8,%9}, {%0,%1,%2,%3};" \
        : "+f"((d)[0]),"+f"((d)[1]),"+f"((d)[2]),"+f"((d)[3]) \
        : "r"((a)[0]),"r"((a)[1]),"r"((a)[2]),"r"((a)[3]), "r"(b0),"r"(b1))

// fp16 split: h = rn(v), l = rn(v - h). "h" alone is the rounded single.
__device__ __forceinline__ void split_hilo(float v, ushort_t& h, ushort_t& l) {
    __half hh = __float2half_rn(v);
    h = __half_as_ushort(hh);
    l = __half_as_ushort(__float2half_rn(v - __half2float(hh)));
}
__device__ __forceinline__ ushort_t to_h(float v) {
    return __half_as_ushort(__float2half_rn(v));
}

__inline__ __device__ float warp_sum(float v) {
    #pragma unroll
    for (int o = 16; o; o >>= 1) v += __shfl_down_sync(0xffffffffu, v, o);
    return v;
}
__inline__ __device__ float warp_max(float v) {
    #pragma unroll
    for (int o = 16; o; o >>= 1) v = fmaxf(v, __shfl_down_sync(0xffffffffu, v, o));
    return v;
}

// ---------------- GroupNorm stats ----------------
__global__ void gn_stats_k(const float* __restrict__ x) {
    int g = blockIdx.x;
    const float4* p = (const float4*)(x + (size_t)g * CPG * S_);
    const int n4 = (CPG * S_) / 4;
    float s = 0.f, s2 = 0.f;
    for (int i = threadIdx.x; i < n4; i += blockDim.x) {
        float4 v = p[i];
        s  += v.x + v.y + v.z + v.w;
        s2 += v.x * v.x + v.y * v.y + v.z * v.z + v.w * v.w;
    }
    __shared__ float sh0[8], sh1[8];
    float ws = warp_sum(s), ws2 = warp_sum(s2);
    int wid = threadIdx.x >> 5, lid = threadIdx.x & 31;
    if (!lid) { sh0[wid] = ws; sh1[wid] = ws2; }
    __syncthreads();
    if (threadIdx.x == 0) {
        float a = 0.f, b = 0.f;
        #pragma unroll
        for (int i = 0; i < 8; i++) { a += sh0[i]; b += sh1[i]; }
        const float inv_n = 1.f / (float)(CPG * S_);
        float m = a * inv_n;
        g_mean[g] = m;
        g_rstd[g] = rsqrtf(b * inv_n - m * m + 1e-6f);
    }
}

__global__ void normact_k(const float* __restrict__ x, const float* __restrict__ sc,
                          const float* __restrict__ bi, float* __restrict__ out, int do_silu) {
    int i = blockIdx.x * blockDim.x + threadIdx.x;
    int c = i >> 13;
    int g = c >> 4;
    float v = (x[i] - g_mean[g]) * g_rstd[g] * sc[c] + bi[c];
    if (do_silu) v = v / (1.f + __expf(-v));
    out[i] = v;
}

// ---------------- im2col -> fp16 single [pos][KC] ----------------
__global__ void im2col_pack_k() {
    size_t id = (size_t)blockIdx.x * 256 + threadIdx.x;
    int pos = (int)(id / 1728);
    int kc  = (int)(id - (size_t)pos * 1728);
    int k0 = kc * 8;
    int t = pos >> 10, rem = pos & 1023, y = rem >> 5, x = rem & 31;
    __align__(16) ushort_t hv[8];
    #pragma unroll
    for (int e = 0; e < 8; e++) {
        int k = k0 + e;
        int ci = k / 27; int r = k - ci * 27;
        int kd = r / 9;  r -= kd * 9;
        int kh = r / 3;  int kw = r - kh * 3;
        int ts = min(max(t + kd - 2, 0), 7);
        int ys = min(max(y + kh - 1, 0), 31);
        int xs = min(max(x + kw - 1, 0), 31);
        hv[e] = to_h(g_act[(size_t)ci * S_ + ts * HW_ + ys * W_ + xs]);
    }
    *(uint4*)(g_bh + (size_t)pos * KC + k0) = *(uint4*)hv;
}

// ---------------- generic pack: fp32 row-major -> fp16 hi/lo ----------------
__global__ void wpack_k(const float* __restrict__ w, ushort_t* __restrict__ dhi,
                        ushort_t* __restrict__ dlo) {
    size_t id = (size_t)blockIdx.x * 256 + threadIdx.x;
    const float4* src = (const float4*)w;
    float4 v0 = src[id * 2], v1 = src[id * 2 + 1];
    __align__(16) ushort_t hi[8], lo[8];
    split_hilo(v0.x, hi[0], lo[0]); split_hilo(v0.y, hi[1], lo[1]);
    split_hilo(v0.z, hi[2], lo[2]); split_hilo(v0.w, hi[3], lo[3]);
    split_hilo(v1.x, hi[4], lo[4]); split_hilo(v1.y, hi[5], lo[5]);
    split_hilo(v1.z, hi[6], lo[6]); split_hilo(v1.w, hi[7], lo[7]);
    *(uint4*)(dhi + id * 8) = *(uint4*)hi;
    *(uint4*)(dlo + id * 8) = *(uint4*)lo;
}

// ---------------- transpose-pack: act [c][s] -> fp16 hi/lo [s][c] ----------------
__global__ void atpack_k() {
    __shared__ float tile[32][33];
    int s0 = blockIdx.x * 32, c0 = blockIdx.y * 32;
    int tx = threadIdx.x, ty = threadIdx.y;
    #pragma unroll
    for (int i = ty; i < 32; i += 8)
        tile[i][tx] = g_act[(size_t)(c0 + i) * S_ + s0 + tx];
    __syncthreads();
    #pragma unroll
    for (int i = ty; i < 32; i += 8) {
        float v = tile[tx][i];
        ushort_t h, l;
        split_hilo(v, h, l);
        size_t off = (size_t)(s0 + i) * C_ + c0 + tx;
        g_acth[off] = h;
        g_actl[off] = l;
    }
}

// ---------------- split-K reduce ----------------
__global__ void ksum_k(float* __restrict__ out, const float* __restrict__ bias,
                       const float* __restrict__ addend) {
    size_t i = ((size_t)blockIdx.x * 256 + threadIdx.x) * 4;
    int c = (int)(i >> 13);
    float4 v0 = *(const float4*)(g_ks + i);
    float4 v1 = *(const float4*)(g_ks + (size_t)C_ * S_ + i);
    float4 v2 = *(const float4*)(g_ks + (size_t)2 * C_ * S_ + i);
    float4 v3 = *(const float4*)(g_ks + (size_t)3 * C_ * S_ + i);
    float bv = bias[c];
    float4 r;
    r.x = v0.x + v1.x + v2.x + v3.x + bv;
    r.y = v0.y + v1.y + v2.y + v3.y + bv;
    r.z = v0.z + v1.z + v2.z + v3.z + bv;
    r.w = v0.w + v1.w + v2.w + v3.w + bv;
    if (addend) {
        float4 a = *(const float4*)(addend + i);
        r.x += a.x; r.y += a.y; r.z += a.z; r.w += a.w;
    }
    *(float4*)(out + i) = r;
}

// ================= HMMA mainloops (2-pass fp16: Ahi/Alo split, B single) =========
struct HmmaAcc { float a[4][4][4]; };

// 3-stage generic (attention)
__device__ __forceinline__ void hmma_mainloop(
    HmmaAcc& A4, uint32_t sm0, int tid,
    const ushort_t* __restrict__ Ahi, const ushort_t* __restrict__ Alo, int lda,
    const ushort_t* __restrict__ Bh, int ldb,
    int m0, int n0, int kiters) {
    const int lane = tid & 31, warp = tid >> 5;
    const int wm = warp & 1, wn = warp >> 1;

    auto issue = [&](int stage, int k0) {
        uint32_t sb = sm0 + stage * STG;
        #pragma unroll
        for (int h = 0; h < 2; h++) {
            int id = tid + h * 256;
            int r = id >> 2, cu = id & 3;
            uint32_t soff = r * 64 + (((cu ^ ((r >> 1) & 3))) << 4);
            size_t ga = (size_t)(m0 + r) * lda + k0 + cu * 8;
            size_t gb = (size_t)(n0 + r) * ldb + k0 + cu * 8;
            CP_ASYNC16(sb + soff,         Ahi + ga);
            CP_ASYNC16(sb + 8192  + soff, Alo + ga);
            CP_ASYNC16(sb + 16384 + soff, Bh + gb);
        }
        CP_COMMIT();
    };

    issue(0, 0);
    issue(1, 32);

    const int rl = lane & 15, ul = lane >> 4;
    for (int it = 0; it < kiters; it++) {
        CP_WAIT1();
        __syncthreads();
        uint32_t sb = sm0 + (it % 3) * STG;
        #pragma unroll
        for (int k16 = 0; k16 < 2; k16++) {
            uint32_t ahi[4][4], alo[4][4], bh[2][4];
            int u = k16 * 2 + ul;
            #pragma unroll
            for (int i = 0; i < 4; i++) {
                int r = wm * 64 + i * 16 + rl;
                uint32_t off = r * 64 + (((u ^ ((r >> 1) & 3))) << 4);
                LDSM4(ahi[i], sb + off);
                LDSM4(alo[i], sb + 8192 + off);
            }
            #pragma unroll
            for (int j2 = 0; j2 < 2; j2++) {
                int r = wn * 32 + j2 * 16 + rl;
                uint32_t off = r * 64 + (((u ^ ((r >> 1) & 3))) << 4);
                LDSM4(bh[j2], sb + 16384 + off);
            }
            #pragma unroll
            for (int i = 0; i < 4; i++)
                #pragma unroll
                for (int j = 0; j < 4; j++) {
                    int j2 = j >> 1, ts = j & 1;
                    MMA16816(A4.a[i][j], ahi[i], bh[j2][ts], bh[j2][ts + 2]);
                    MMA16816(A4.a[i][j], alo[i], bh[j2][ts], bh[j2][ts + 2]);
                }
        }
        __syncthreads();
        if (it + 2 < kiters) issue((it + 2) % 3, (it + 2) * 32);
        else CP_COMMIT();
    }
}

// ---------------- conv GEMM, split-K, 4-stage ----------------
// grid (16, 64): x -> m-tile (x&3), ksplit (x>>2); y -> n-tile
__global__ void __launch_bounds__(256, 1) conv_hmma_k() {
    extern __shared__ unsigned char dynsm[];
    const uint32_t sm0 = smem_u32(dynsm);
    const int tid = threadIdx.x, lane = tid & 31, warp = tid >> 5;
    const int m0 = (blockIdx.x & 3) * 128;
    const int ks = blockIdx.x >> 2;
    const int n0 = blockIdx.y * 128;
    const int kbase = ks * (KSPLIT_ITERS * 32);
    const int wm = warp & 1, wn = warp >> 1;

    auto issue = [&](int stage, int k0) {
        uint32_t sb = sm0 + stage * STG;
        #pragma unroll
        for (int h = 0; h < 2; h++) {
            int id = tid + h * 256;
            int r = id >> 2, cu = id & 3;
            uint32_t soff = r * 64 + (((cu ^ ((r >> 1) & 3))) << 4);
            size_t ga = (size_t)(m0 + r) * KC + k0 + cu * 8;
            size_t gb = (size_t)(n0 + r) * KC + k0 + cu * 8;
            CP_ASYNC16(sb + soff,         g_whi + ga);
            CP_ASYNC16(sb + 8192  + soff, g_wlo + ga);
            CP_ASYNC16(sb + 16384 + soff, g_bh  + gb);
        }
        CP_COMMIT();
    };

    float acc[4][4][4];
    #pragma unroll
    for (int i = 0; i < 4; i++)
        #pragma unroll
        for (int j = 0; j < 4; j++)
            #pragma unroll
            for (int r = 0; r < 4; r++) acc[i][j][r] = 0.f;

    issue(0, kbase);
    issue(1, kbase + 32);
    issue(2, kbase + 64);

    const int rl = lane & 15, ul = lane >> 4;
    for (int it = 0; it < KSPLIT_ITERS; it++) {
        CP_WAIT2();
        __syncthreads();
        uint32_t sb = sm0 + (it & 3) * STG;
        #pragma unroll
        for (int k16 = 0; k16 < 2; k16++) {
            uint32_t ahi[4][4], alo[4][4], bh[2][4];
            int u = k16 * 2 + ul;
            #pragma unroll
            for (int i = 0; i < 4; i++) {
                int r = wm * 64 + i * 16 + rl;
                uint32_t off = r * 64 + (((u ^ ((r >> 1) & 3))) << 4);
                LDSM4(ahi[i], sb + off);
                LDSM4(alo[i], sb + 8192 + off);
            }
            #pragma unroll
            for (int j2 = 0; j2 < 2; j2++) {
                int r = wn * 32 + j2 * 16 + rl;
                uint32_t off = r * 64 + (((u ^ ((r >> 1) & 3))) << 4);
                LDSM4(bh[j2], sb + 16384 + off);
            }
            #pragma unroll
            for (int i = 0; i < 4; i++)
                #pragma unroll
                for (int j = 0; j < 4; j++) {
                    int j2 = j >> 1, ts = j & 1;
                    MMA16816(acc[i][j], ahi[i], bh[j2][ts], bh[j2][ts + 2]);
                    MMA16816(acc[i][j], alo[i], bh[j2][ts], bh[j2][ts + 2]);
                }
        }
        __syncthreads();
        if (it + 3 < KSPLIT_ITERS) issue((it + 3) & 3, kbase + (it + 3) * 32);
        else CP_COMMIT();
    }

    float* Sp = g_ks + (size_t)ks * C_ * S_;
    const int mrow = m0 + wm * 64 + (lane >> 2);
    const int ncol = n0 + wn * 32 + (lane & 3) * 2;
    #pragma unroll
    for (int i = 0; i < 4; i++) {
        int ma = mrow + i * 16, mb = ma + 8;
        #pragma unroll
        for (int j = 0; j < 4; j++) {
            int n = ncol + j * 8;
            *(float2*)(Sp + (size_t)ma * S_ + n) = make_float2(acc[i][j][0], acc[i][j][1]);
            *(float2*)(Sp + (size_t)mb * S_ + n) = make_float2(acc[i][j][2], acc[i][j][3]);
        }
    }
}

// ---------------- generic attention GEMM ----------------
__global__ void __launch_bounds__(256, 1) hmma_gemm_k(
    const ushort_t* __restrict__ Ahi, const ushort_t* __restrict__ Alo, int lda,
    const ushort_t* __restrict__ Bh, int ldb,
    float* __restrict__ Cf, ushort_t* __restrict__ Chi, ushort_t* __restrict__ Clo,
    int ldc, int K, float alpha,
    const float* __restrict__ biasM, const float* __restrict__ biasN,
    const float* __restrict__ addend, int causal, int kcausal, int mrev) {
    const int by = mrev ? (gridDim.y - 1 - blockIdx.y) : blockIdx.y;
    const int m0 = by * 128, n0 = blockIdx.x * 128;
    if (causal && n0 >= (((m0 >> 10) + 1) << 10)) return;
    int Keff = kcausal ? (((m0 >> 10) + 1) << 10) : K;

    extern __shared__ unsigned char dynsm[];
    const uint32_t sm0 = smem_u32(dynsm);
    const int tid = threadIdx.x, lane = tid & 31, warp = tid >> 5;
    const int wm = warp & 1, wn = warp >> 1;

    HmmaAcc acc;
    #pragma unroll
    for (int i = 0; i < 4; i++)
        #pragma unroll
        for (int j = 0; j < 4; j++)
            #pragma unroll
            for (int r = 0; r < 4; r++) acc.a[i][j][r] = 0.f;

    hmma_mainloop(acc, sm0, tid, Ahi, Alo, lda, Bh, ldb, m0, n0, Keff >> 5);

    const int mrow = m0 + wm * 64 + (lane >> 2);
    const int ncol = n0 + wn * 32 + (lane & 3) * 2;
    #pragma unroll
    for (int i = 0; i < 4; i++) {
        int ma = mrow + i * 16, mb = ma + 8;
        float bva = biasM ? biasM[ma] : 0.f;
        float bvb = biasM ? biasM[mb] : 0.f;
        #pragma unroll
        for (int j = 0; j < 4; j++) {
            int n = ncol + j * 8;
            float2 va = make_float2(acc.a[i][j][0] * alpha + bva, acc.a[i][j][1] * alpha + bva);
            float2 vb = make_float2(acc.a[i][j][2] * alpha + bvb, acc.a[i][j][3] * alpha + bvb);
            if (biasN) {
                float b0 = biasN[n], b1 = biasN[n + 1];
                va.x += b0; va.y += b1; vb.x += b0; vb.y += b1;
            }
            if (addend) {
                float2 aa = *(const float2*)(addend + (size_t)ma * ldc + n);
                float2 ab = *(const float2*)(addend + (size_t)mb * ldc + n);
                va.x += aa.x; va.y += aa.y; vb.x += ab.x; vb.y += ab.y;
            }
            if (Cf) {
                *(float2*)(Cf + (size_t)ma * ldc + n) = va;
                *(float2*)(Cf + (size_t)mb * ldc + n) = vb;
            }
            if (Chi) {
                ushort_t h0, l0, h1, l1;
                split_hilo(va.x, h0, l0); split_hilo(va.y, h1, l1);
                *(ushort2*)(Chi + (size_t)ma * ldc + n) = make_ushort2(h0, h1);
                *(ushort2*)(Clo + (size_t)ma * ldc + n) = make_ushort2(l0, l1);
                split_hilo(vb.x, h0, l0); split_hilo(vb.y, h1, l1);
                *(ushort2*)(Chi + (size_t)mb * ldc + n) = make_ushort2(h0, h1);
                *(ushort2*)(Clo + (size_t)mb * ldc + n) = make_ushort2(l0, l1);
            }
        }
    }
}

// ---------------- softmax: fp32 scores -> packed fp16 probs ----------------
__global__ void softmax_k() {
    int i = blockIdx.x;
    int L = ((i >> 10) + 1) << 10;
    float4* row = (float4*)(g_p + ((size_t)i << 13));
    int n4 = L >> 2;
    int tid = threadIdx.x;
    __shared__ float sh[8];
    float mx = -1e30f;
    for (int j = tid; j < n4; j += 256) {
        float4 v = row[j];
        mx = fmaxf(mx, fmaxf(fmaxf(v.x, v.y), fmaxf(v.z, v.w)));
    }
    float wm = warp_max(mx);
    if ((tid & 31) == 0) sh[tid >> 5] = wm;
    __syncthreads();
    if (tid < 32) {
        float m2 = (tid < 8) ? sh[tid] : -1e30f;
        m2 = warp_max(m2);
        if (tid == 0) sh[0] = m2;
    }
    __syncthreads();
    float m = sh[0];
    __syncthreads();
    float s = 0.f;
    for (int j = tid; j < n4; j += 256) {
        float4 v = row[j];
        v.x = __expf(v.x - m); v.y = __expf(v.y - m);
        v.z = __expf(v.z - m); v.w = __expf(v.w - m);
        s += v.x + v.y + v.z + v.w;
        row[j] = v;
    }
    float ws = warp_sum(s);
    if ((tid & 31) == 0) sh[tid >> 5] = ws;
    __syncthreads();
    if (tid < 32) {
        float s2 = (tid < 8) ? sh[tid] : 0.f;
        s2 = warp_sum(s2);
        if (tid == 0) sh[0] = s2;
    }
    __syncthreads();
    float inv = 1.f / sh[0];
    size_t base = (size_t)i << 13;
    for (int j = tid; j < n4; j += 256) {
        float4 v = row[j];
        v.x *= inv; v.y *= inv; v.z *= inv; v.w *= inv;
        ushort_t h0, l0, h1, l1, h2, l2, h3, l3;
        split_hilo(v.x, h0, l0); split_hilo(v.y, h1, l1);
        split_hilo(v.z, h2, l2); split_hilo(v.w, h3, l3);
        uint2 hv = make_uint2((uint32_t)h0 | ((uint32_t)h1 << 16),
                              (uint32_t)h2 | ((uint32_t)h3 << 16));
        uint2 lv = make_uint2((uint32_t)l0 | ((uint32_t)l1 << 16),
                              (uint32_t)l2 | ((uint32_t)l3 << 16));
        *(uint2*)(g_phi + base + 4 * (size_t)j) = hv;
        *(uint2*)(g_plo + base + 4 * (size_t)j) = lv;
    }
}

// ---------------- orchestration ----------------
extern "C" void kernel_launch(void* const* d_in, const int* in_sizes, int n_in,
                              void* d_out, int out_size) {
    (void)in_sizes; (void)n_in; (void)out_size;

    float *act, *t1, *y0, *mid, *p;
    ushort_t *wahi, *walo, *acth, *actl, *qhi, *qlo, *khi, *klo, *vhi, *vlo;
    ushort_t *ohi, *olo, *phi, *plo, *whi, *wlo;
    cudaGetSymbolAddress((void**)&act,  g_act);
    cudaGetSymbolAddress((void**)&t1,   g_t1);
    cudaGetSymbolAddress((void**)&y0,   g_y0);
    cudaGetSymbolAddress((void**)&mid,  g_mid);
    cudaGetSymbolAddress((void**)&p,    g_p);
    cudaGetSymbolAddress((void**)&wahi, g_wahi);
    cudaGetSymbolAddress((void**)&walo, g_walo);
    cudaGetSymbolAddress((void**)&acth, g_acth);
    cudaGetSymbolAddress((void**)&actl, g_actl);
    cudaGetSymbolAddress((void**)&qhi,  g_qhi);
    cudaGetSymbolAddress((void**)&qlo,  g_qlo);
    cudaGetSymbolAddress((void**)&khi,  g_khi);
    cudaGetSymbolAddress((void**)&klo,  g_klo);
    cudaGetSymbolAddress((void**)&vhi,  g_vhi);
    cudaGetSymbolAddress((void**)&vlo,  g_vlo);
    cudaGetSymbolAddress((void**)&ohi,  g_ohi);
    cudaGetSymbolAddress((void**)&olo,  g_olo);
    cudaGetSymbolAddress((void**)&phi,  g_phi);
    cudaGetSymbolAddress((void**)&plo,  g_plo);
    cudaGetSymbolAddress((void**)&whi,  g_whi);
    cudaGetSymbolAddress((void**)&wlo,  g_wlo);

    cudaFuncSetAttribute(conv_hmma_k, cudaFuncAttributeMaxDynamicSharedMemorySize, 4 * STG);
    cudaFuncSetAttribute(hmma_gemm_k, cudaFuncAttributeMaxDynamicSharedMemorySize, 3 * STG);

    const float* X = (const float*)d_in[0];
    const float* a_gns = (const float*)d_in[17];
    const float* a_gnb = (const float*)d_in[18];
    const float* a_wq  = (const float*)d_in[19];
    const float* a_bq  = (const float*)d_in[20];
    const float* a_wk  = (const float*)d_in[21];
    const float* a_bk  = (const float*)d_in[22];
    const float* a_wv  = (const float*)d_in[23];
    const float* a_bv  = (const float*)d_in[24];
    const float* a_wo  = (const float*)d_in[25];
    const float* a_bo  = (const float*)d_in[26];

    const dim3 conv_grid(16, 64);
    const int IM2COL_BLOCKS = (S_ * (KC / 8)) / 256;
    const int WPACK_CONV    = ((C_ * KC) / 8) / 256;
    const int WPACK_SQ      = ((C_ * C_) / 8) / 256;
    const int KSUM_BLOCKS   = (C_ * S_ / 4) / 256;

    auto resnet = [&](const float* in, int base, float* midb, float* outbuf) {
        const float* n1s = (const float*)d_in[base + 0];
        const float* n1b = (const float*)d_in[base + 1];
        const float* w1  = (const float*)d_in[base + 2];
        const float* b1  = (const float*)d_in[base + 3];
        const float* n2s = (const float*)d_in[base + 4];
        const float* n2b = (const float*)d_in[base + 5];
        const float* w2  = (const float*)d_in[base + 6];
        const float* b2  = (const float*)d_in[base + 7];

        gn_stats_k<<<NGROUP, 256>>>(in);
        normact_k<<<(C_ * S_) / 256, 256>>>(in, n1s, n1b, act, 1);
        im2col_pack_k<<<IM2COL_BLOCKS, 256>>>();
        wpack_k<<<WPACK_CONV, 256>>>(w1, whi, wlo);
        conv_hmma_k<<<conv_grid, 256, 4 * STG>>>();
        ksum_k<<<KSUM_BLOCKS, 256>>>(midb, b1, nullptr);
        gn_stats_k<<<NGROUP, 256>>>(midb);
        normact_k<<<(C_ * S_) / 256, 256>>>(midb, n2s, n2b, act, 1);
        im2col_pack_k<<<IM2COL_BLOCKS, 256>>>();
        wpack_k<<<WPACK_CONV, 256>>>(w2, whi, wlo);
        conv_hmma_k<<<conv_grid, 256, 4 * STG>>>();
        ksum_k<<<KSUM_BLOCKS, 256>>>(outbuf, b2, in);
    };

    // ---- ResNet block 0:  X -> y0 ----
    resnet(X, 1, t1, y0);

    // ---- Causal frame attention on y0 ----
    gn_stats_k<<<NGROUP, 256>>>(y0);
    normact_k<<<(C_ * S_) / 256, 256>>>(y0, a_gns, a_gnb, act, 0);
    atpack_k<<<dim3(S_ / 32, C_ / 32), dim3(32, 8)>>>();

    // Q[s][d] = act(split) . wq(single)^T + bq
    wpack_k<<<WPACK_SQ, 256>>>(a_wq, wahi, walo);
    hmma_gemm_k<<<dim3(4, 64), 256, 3 * STG>>>(acth, actl, C_, wahi, C_,
        nullptr, qhi, qlo, C_, C_, 1.f, nullptr, a_bq, nullptr, 0, 0, 0);
    // K[s][d]
    wpack_k<<<WPACK_SQ, 256>>>(a_wk, wahi, walo);
    hmma_gemm_k<<<dim3(4, 64), 256, 3 * STG>>>(acth, actl, C_, wahi, C_,
        nullptr, khi, klo, C_, C_, 1.f, nullptr, a_bk, nullptr, 0, 0, 0);
    // V[d][s] = wv(split) . act(single)^T + bv
    wpack_k<<<WPACK_SQ, 256>>>(a_wv, wahi, walo);
    hmma_gemm_k<<<dim3(64, 4), 256, 3 * STG>>>(wahi, walo, C_, acth, C_,
        nullptr, vhi, vlo, S_, C_, 1.f, a_bv, nullptr, nullptr, 0, 0, 0);

    // scores: Q(split) . K(single)
    hmma_gemm_k<<<dim3(64, 64), 256, 3 * STG>>>(qhi, qlo, C_, khi, C_,
        p, nullptr, nullptr, S_, C_, 0.04419417382415922f,
        nullptr, nullptr, nullptr, 1, 0, 0);
    softmax_k<<<S_, 256>>>();
    // O[s][d] = P(split) . V(single)^T   (reversed m-order, causal K bound)
    hmma_gemm_k<<<dim3(4, 64), 256, 3 * STG>>>(phi, plo, S_, vhi, S_,
        nullptr, ohi, olo, C_, S_, 1.f, nullptr, nullptr, nullptr, 0, 1, 1);
    // attnout[c][s] = wo(split) . O(single)^T + bo + y0
    wpack_k<<<WPACK_SQ, 256>>>(a_wo, wahi, walo);
    hmma_gemm_k<<<dim3(64, 4), 256, 3 * STG>>>(wahi, walo, C_, ohi, C_,
        t1, nullptr, nullptr, S_, C_, 1.f, a_bo, nullptr, y0, 0, 0, 0);

    // ---- ResNet block 1:  t1 -> d_out ----
    resnet(t1, 9, mid, (float*)d_out);
}

// round 8
// speedup vs baseline: 4.8637x; 1.4869x over previous
#include <cuda_runtime.h>
#include <cuda_fp16.h>
#include <math.h>
#include <stdint.h>

#define C_      512
#define S_      8192
#define HW_     1024
#define W_      32
#define NGROUP  32
#define CPG     16
#define KC      13824
#define NSPLIT  4
#define KSPLIT_ITERS 108      // (KC/32)/4

// smem stage: A 8K | B 8K
#define STG 16384

typedef unsigned short ushort_t;

__device__ float g_mean[NGROUP];
__device__ float g_rstd[NGROUP];
__device__ float g_act[(size_t)C_ * S_];
__device__ float g_t1 [(size_t)C_ * S_];
__device__ float g_y0 [(size_t)C_ * S_];
__device__ float g_mid[(size_t)C_ * S_];
__device__ float g_p  [(size_t)S_ * S_];
__device__ float g_ks [(size_t)NSPLIT * C_ * S_];
// fp16 single-precision operands
__device__ __align__(16) ushort_t g_wh [(size_t)C_ * KC];    // conv weights
__device__ __align__(16) ushort_t g_bh [(size_t)S_ * KC];    // im2col
__device__ __align__(16) ushort_t g_acth[(size_t)S_ * C_];   // xn [s][c]
__device__ __align__(16) ushort_t g_wah[(size_t)C_ * C_];    // current 512x512 weight
__device__ __align__(16) ushort_t g_qh [(size_t)S_ * C_];    // Q [s][d]
__device__ __align__(16) ushort_t g_kh [(size_t)S_ * C_];    // K [s][d]
__device__ __align__(16) ushort_t g_vh [(size_t)C_ * S_];    // V [d][s]
__device__ __align__(16) ushort_t g_oh [(size_t)S_ * C_];    // O [s][d]
__device__ __align__(16) ushort_t g_ph [(size_t)S_ * S_];    // probs [q][k]

// ---------------- PTX helpers ----------------
__device__ __forceinline__ uint32_t smem_u32(const void* p) {
    uint32_t a;
    asm("{ .reg .u64 t; cvta.to.shared.u64 t, %1; cvt.u32.u64 %0, t; }" : "=r"(a) : "l"(p));
    return a;
}
#define CP_ASYNC16(smem, gmem) \
    asm volatile("cp.async.cg.shared.global [%0], [%1], 16;" :: "r"(smem), "l"(gmem) : "memory")
#define CP_COMMIT() asm volatile("cp.async.commit_group;" ::: "memory")
#define CP_WAIT1()  asm volatile("cp.async.wait_group 1;" ::: "memory")
#define CP_WAIT2()  asm volatile("cp.async.wait_group 2;" ::: "memory")
#define LDSM4(r, addr) \
    asm volatile("ldmatrix.sync.aligned.m8n8.x4.shared.b16 {%0,%1,%2,%3}, [%4];" \
        : "=r"((r)[0]),"=r"((r)[1]),"=r"((r)[2]),"=r"((r)[3]) : "r"(addr))
#define MMA16816(d, a, b0, b1) \
    asm volatile("mma.sync.aligned.m16n8k16.row.col.f32.f16.f16.f32 " \
        "{%0,%1,%2,%3}, {%4,%5,%6,%7}, {%8,%9}, {%0,%1,%2,%3};" \
        : "+f"((d)[0]),"+f"((d)[1]),"+f"((d)[2]),"+f"((d)[3]) \
        : "r"((a)[0]),"r"((a)[1]),"r"((a)[2]),"r"((a)[3]), "r"(b0),"r"(b1))

__device__ __forceinline__ ushort_t to_h(float v) {
    return __half_as_ushort(__float2half_rn(v));
}

__inline__ __device__ float warp_sum(float v) {
    #pragma unroll
    for (int o = 16; o; o >>= 1) v += __shfl_down_sync(0xffffffffu, v, o);
    return v;
}
__inline__ __device__ float warp_max(float v) {
    #pragma unroll
    for (int o = 16; o; o >>= 1) v = fmaxf(v, __shfl_down_sync(0xffffffffu, v, o));
    return v;
}

// ---------------- GroupNorm stats ----------------
__global__ void gn_stats_k(const float* __restrict__ x) {
    int g = blockIdx.x;
    const float4* p = (const float4*)(x + (size_t)g * CPG * S_);
    const int n4 = (CPG * S_) / 4;
    float s = 0.f, s2 = 0.f;
    for (int i = threadIdx.x; i < n4; i += blockDim.x) {
        float4 v = p[i];
        s  += v.x + v.y + v.z + v.w;
        s2 += v.x * v.x + v.y * v.y + v.z * v.z + v.w * v.w;
    }
    __shared__ float sh0[8], sh1[8];
    float ws = warp_sum(s), ws2 = warp_sum(s2);
    int wid = threadIdx.x >> 5, lid = threadIdx.x & 31;
    if (!lid) { sh0[wid] = ws; sh1[wid] = ws2; }
    __syncthreads();
    if (threadIdx.x == 0) {
        float a = 0.f, b = 0.f;
        #pragma unroll
        for (int i = 0; i < 8; i++) { a += sh0[i]; b += sh1[i]; }
        const float inv_n = 1.f / (float)(CPG * S_);
        float m = a * inv_n;
        g_mean[g] = m;
        g_rstd[g] = rsqrtf(b * inv_n - m * m + 1e-6f);
    }
}

__global__ void normact_k(const float* __restrict__ x, const float* __restrict__ sc,
                          const float* __restrict__ bi, float* __restrict__ out, int do_silu) {
    int i = blockIdx.x * blockDim.x + threadIdx.x;
    int c = i >> 13;
    int g = c >> 4;
    float v = (x[i] - g_mean[g]) * g_rstd[g] * sc[c] + bi[c];
    if (do_silu) v = v / (1.f + __expf(-v));
    out[i] = v;
}

// ---------------- im2col -> fp16 [pos][KC] ----------------
__global__ void im2col_pack_k() {
    size_t id = (size_t)blockIdx.x * 256 + threadIdx.x;
    int pos = (int)(id / 1728);
    int kc  = (int)(id - (size_t)pos * 1728);
    int k0 = kc * 8;
    int t = pos >> 10, rem = pos & 1023, y = rem >> 5, x = rem & 31;
    __align__(16) ushort_t hv[8];
    #pragma unroll
    for (int e = 0; e < 8; e++) {
        int k = k0 + e;
        int ci = k / 27; int r = k - ci * 27;
        int kd = r / 9;  r -= kd * 9;
        int kh = r / 3;  int kw = r - kh * 3;
        int ts = min(max(t + kd - 2, 0), 7);
        int ys = min(max(y + kh - 1, 0), 31);
        int xs = min(max(x + kw - 1, 0), 31);
        hv[e] = to_h(g_act[(size_t)ci * S_ + ts * HW_ + ys * W_ + xs]);
    }
    *(uint4*)(g_bh + (size_t)pos * KC + k0) = *(uint4*)hv;
}

// ---------------- pack: fp32 row-major -> fp16 ----------------
__global__ void wpack_k(const float* __restrict__ w, ushort_t* __restrict__ dh) {
    size_t id = (size_t)blockIdx.x * 256 + threadIdx.x;    // over count/8
    const float4* src = (const float4*)w;
    float4 v0 = src[id * 2], v1 = src[id * 2 + 1];
    __align__(16) ushort_t hv[8];
    hv[0] = to_h(v0.x); hv[1] = to_h(v0.y); hv[2] = to_h(v0.z); hv[3] = to_h(v0.w);
    hv[4] = to_h(v1.x); hv[5] = to_h(v1.y); hv[6] = to_h(v1.z); hv[7] = to_h(v1.w);
    *(uint4*)(dh + id * 8) = *(uint4*)hv;
}

// ---------------- transpose-pack: act [c][s] -> fp16 [s][c] ----------------
__global__ void atpack_k() {
    __shared__ float tile[32][33];
    int s0 = blockIdx.x * 32, c0 = blockIdx.y * 32;
    int tx = threadIdx.x, ty = threadIdx.y;
    #pragma unroll
    for (int i = ty; i < 32; i += 8)
        tile[i][tx] = g_act[(size_t)(c0 + i) * S_ + s0 + tx];
    __syncthreads();
    #pragma unroll
    for (int i = ty; i < 32; i += 8)
        g_acth[(size_t)(s0 + i) * C_ + c0 + tx] = to_h(tile[tx][i]);
}

// ---------------- split-K reduce ----------------
__global__ void ksum_k(float* __restrict__ out, const float* __restrict__ bias,
                       const float* __restrict__ addend) {
    size_t i = ((size_t)blockIdx.x * 256 + threadIdx.x) * 4;
    int c = (int)(i >> 13);
    float4 v0 = *(const float4*)(g_ks + i);
    float4 v1 = *(const float4*)(g_ks + (size_t)C_ * S_ + i);
    float4 v2 = *(const float4*)(g_ks + (size_t)2 * C_ * S_ + i);
    float4 v3 = *(const float4*)(g_ks + (size_t)3 * C_ * S_ + i);
    float bv = bias[c];
    float4 r;
    r.x = v0.x + v1.x + v2.x + v3.x + bv;
    r.y = v0.y + v1.y + v2.y + v3.y + bv;
    r.z = v0.z + v1.z + v2.z + v3.z + bv;
    r.w = v0.w + v1.w + v2.w + v3.w + bv;
    if (addend) {
        float4 a = *(const float4*)(addend + i);
        r.x += a.x; r.y += a.y; r.z += a.z; r.w += a.w;
    }
    *(float4*)(out + i) = r;
}

// ================= HMMA mainloops (single-pass fp16) =================
struct HmmaAcc { float a[4][4][4]; };

// 3-stage generic (attention)
__device__ __forceinline__ void hmma_mainloop(
    HmmaAcc& A4, uint32_t sm0, int tid,
    const ushort_t* __restrict__ Ah, int lda,
    const ushort_t* __restrict__ Bh, int ldb,
    int m0, int n0, int kiters) {
    const int lane = tid & 31, warp = tid >> 5;
    const int wm = warp & 1, wn = warp >> 1;

    auto issue = [&](int stage, int k0) {
        uint32_t sb = sm0 + stage * STG;
        #pragma unroll
        for (int h = 0; h < 2; h++) {
            int id = tid + h * 256;
            int r = id >> 2, cu = id & 3;
            uint32_t soff = r * 64 + (((cu ^ ((r >> 1) & 3))) << 4);
            CP_ASYNC16(sb + soff,        Ah + (size_t)(m0 + r) * lda + k0 + cu * 8);
            CP_ASYNC16(sb + 8192 + soff, Bh + (size_t)(n0 + r) * ldb + k0 + cu * 8);
        }
        CP_COMMIT();
    };

    issue(0, 0);
    issue(1, 32);

    const int rl = lane & 15, ul = lane >> 4;
    for (int it = 0; it < kiters; it++) {
        CP_WAIT1();
        __syncthreads();
        uint32_t sb = sm0 + (it % 3) * STG;
        #pragma unroll
        for (int k16 = 0; k16 < 2; k16++) {
            uint32_t a4[4][4], b4[2][4];
            int u = k16 * 2 + ul;
            #pragma unroll
            for (int i = 0; i < 4; i++) {
                int r = wm * 64 + i * 16 + rl;
                LDSM4(a4[i], sb + r * 64 + (((u ^ ((r >> 1) & 3))) << 4));
            }
            #pragma unroll
            for (int j2 = 0; j2 < 2; j2++) {
                int r = wn * 32 + j2 * 16 + rl;
                LDSM4(b4[j2], sb + 8192 + r * 64 + (((u ^ ((r >> 1) & 3))) << 4));
            }
            #pragma unroll
            for (int i = 0; i < 4; i++)
                #pragma unroll
                for (int j = 0; j < 4; j++) {
                    int j2 = j >> 1, ts = j & 1;
                    MMA16816(A4.a[i][j], a4[i], b4[j2][ts], b4[j2][ts + 2]);
                }
        }
        __syncthreads();
        if (it + 2 < kiters) issue((it + 2) % 3, (it + 2) * 32);
        else CP_COMMIT();
    }
}

// ---------------- conv GEMM, split-K, 4-stage ----------------
// grid (16, 64): x -> m-tile (x&3), ksplit (x>>2); y -> n-tile
__global__ void __launch_bounds__(256, 1) conv_hmma_k() {
    extern __shared__ unsigned char dynsm[];
    const uint32_t sm0 = smem_u32(dynsm);
    const int tid = threadIdx.x, lane = tid & 31, warp = tid >> 5;
    const int m0 = (blockIdx.x & 3) * 128;
    const int ks = blockIdx.x >> 2;
    const int n0 = blockIdx.y * 128;
    const int kbase = ks * (KSPLIT_ITERS * 32);
    const int wm = warp & 1, wn = warp >> 1;

    auto issue = [&](int stage, int k0) {
        uint32_t sb = sm0 + stage * STG;
        #pragma unroll
        for (int h = 0; h < 2; h++) {
            int id = tid + h * 256;
            int r = id >> 2, cu = id & 3;
            uint32_t soff = r * 64 + (((cu ^ ((r >> 1) & 3))) << 4);
            CP_ASYNC16(sb + soff,        g_wh + (size_t)(m0 + r) * KC + k0 + cu * 8);
            CP_ASYNC16(sb + 8192 + soff, g_bh + (size_t)(n0 + r) * KC + k0 + cu * 8);
        }
        CP_COMMIT();
    };

    float acc[4][4][4];
    #pragma unroll
    for (int i = 0; i < 4; i++)
        #pragma unroll
        for (int j = 0; j < 4; j++)
            #pragma unroll
            for (int r = 0; r < 4; r++) acc[i][j][r] = 0.f;

    issue(0, kbase);
    issue(1, kbase + 32);
    issue(2, kbase + 64);

    const int rl = lane & 15, ul = lane >> 4;
    for (int it = 0; it < KSPLIT_ITERS; it++) {
        CP_WAIT2();
        __syncthreads();
        uint32_t sb = sm0 + (it & 3) * STG;
        #pragma unroll
        for (int k16 = 0; k16 < 2; k16++) {
            uint32_t a4[4][4], b4[2][4];
            int u = k16 * 2 + ul;
            #pragma unroll
            for (int i = 0; i < 4; i++) {
                int r = wm * 64 + i * 16 + rl;
                LDSM4(a4[i], sb + r * 64 + (((u ^ ((r >> 1) & 3))) << 4));
            }
            #pragma unroll
            for (int j2 = 0; j2 < 2; j2++) {
                int r = wn * 32 + j2 * 16 + rl;
                LDSM4(b4[j2], sb + 8192 + r * 64 + (((u ^ ((r >> 1) & 3))) << 4));
            }
            #pragma unroll
            for (int i = 0; i < 4; i++)
                #pragma unroll
                for (int j = 0; j < 4; j++) {
                    int j2 = j >> 1, ts = j & 1;
                    MMA16816(acc[i][j], a4[i], b4[j2][ts], b4[j2][ts + 2]);
                }
        }
        __syncthreads();
        if (it + 3 < KSPLIT_ITERS) issue((it + 3) & 3, kbase + (it + 3) * 32);
        else CP_COMMIT();
    }

    float* Sp = g_ks + (size_t)ks * C_ * S_;
    const int mrow = m0 + wm * 64 + (lane >> 2);
    const int ncol = n0 + wn * 32 + (lane & 3) * 2;
    #pragma unroll
    for (int i = 0; i < 4; i++) {
        int ma = mrow + i * 16, mb = ma + 8;
        #pragma unroll
        for (int j = 0; j < 4; j++) {
            int n = ncol + j * 8;
            *(float2*)(Sp + (size_t)ma * S_ + n) = make_float2(acc[i][j][0], acc[i][j][1]);
            *(float2*)(Sp + (size_t)mb * S_ + n) = make_float2(acc[i][j][2], acc[i][j][3]);
        }
    }
}

// ---------------- generic attention GEMM ----------------
__global__ void __launch_bounds__(256, 1) hmma_gemm_k(
    const ushort_t* __restrict__ Ah, int lda,
    const ushort_t* __restrict__ Bh, int ldb,
    float* __restrict__ Cf, ushort_t* __restrict__ Ch,
    int ldc, int K, float alpha,
    const float* __restrict__ biasM, const float* __restrict__ biasN,
    const float* __restrict__ addend, int causal, int kcausal, int mrev) {
    const int by = mrev ? (gridDim.y - 1 - blockIdx.y) : blockIdx.y;
    const int m0 = by * 128, n0 = blockIdx.x * 128;
    if (causal && n0 >= (((m0 >> 10) + 1) << 10)) return;
    int Keff = kcausal ? (((m0 >> 10) + 1) << 10) : K;

    extern __shared__ unsigned char dynsm[];
    const uint32_t sm0 = smem_u32(dynsm);
    const int tid = threadIdx.x, lane = tid & 31, warp = tid >> 5;
    const int wm = warp & 1, wn = warp >> 1;

    HmmaAcc acc;
    #pragma unroll
    for (int i = 0; i < 4; i++)
        #pragma unroll
        for (int j = 0; j < 4; j++)
            #pragma unroll
            for (int r = 0; r < 4; r++) acc.a[i][j][r] = 0.f;

    hmma_mainloop(acc, sm0, tid, Ah, lda, Bh, ldb, m0, n0, Keff >> 5);

    const int mrow = m0 + wm * 64 + (lane >> 2);
    const int ncol = n0 + wn * 32 + (lane & 3) * 2;
    #pragma unroll
    for (int i = 0; i < 4; i++) {
        int ma = mrow + i * 16, mb = ma + 8;
        float bva = biasM ? biasM[ma] : 0.f;
        float bvb = biasM ? biasM[mb] : 0.f;
        #pragma unroll
        for (int j = 0; j < 4; j++) {
            int n = ncol + j * 8;
            float2 va = make_float2(acc.a[i][j][0] * alpha + bva, acc.a[i][j][1] * alpha + bva);
            float2 vb = make_float2(acc.a[i][j][2] * alpha + bvb, acc.a[i][j][3] * alpha + bvb);
            if (biasN) {
                float b0 = biasN[n], b1 = biasN[n + 1];
                va.x += b0; va.y += b1; vb.x += b0; vb.y += b1;
            }
            if (addend) {
                float2 aa = *(const float2*)(addend + (size_t)ma * ldc + n);
                float2 ab = *(const float2*)(addend + (size_t)mb * ldc + n);
                va.x += aa.x; va.y += aa.y; vb.x += ab.x; vb.y += ab.y;
            }
            if (Cf) {
                *(float2*)(Cf + (size_t)ma * ldc + n) = va;
                *(float2*)(Cf + (size_t)mb * ldc + n) = vb;
            }
            if (Ch) {
                *(ushort2*)(Ch + (size_t)ma * ldc + n) = make_ushort2(to_h(va.x), to_h(va.y));
                *(ushort2*)(Ch + (size_t)mb * ldc + n) = make_ushort2(to_h(vb.x), to_h(vb.y));
            }
        }
    }
}

// ---------------- softmax: fp32 scores -> fp16 probs ----------------
__global__ void softmax_k() {
    int i = blockIdx.x;
    int L = ((i >> 10) + 1) << 10;
    float4* row = (float4*)(g_p + ((size_t)i << 13));
    int n4 = L >> 2;
    int tid = threadIdx.x;
    __shared__ float sh[8];
    float mx = -1e30f;
    for (int j = tid; j < n4; j += 256) {
        float4 v = row[j];
        mx = fmaxf(mx, fmaxf(fmaxf(v.x, v.y), fmaxf(v.z, v.w)));
    }
    float wm = warp_max(mx);
    if ((tid & 31) == 0) sh[tid >> 5] = wm;
    __syncthreads();
    if (tid < 32) {
        float m2 = (tid < 8) ? sh[tid] : -1e30f;
        m2 = warp_max(m2);
        if (tid == 0) sh[0] = m2;
    }
    __syncthreads();
    float m = sh[0];
    __syncthreads();
    float s = 0.f;
    for (int j = tid; j < n4; j += 256) {
        float4 v = row[j];
        v.x = __expf(v.x - m); v.y = __expf(v.y - m);
        v.z = __expf(v.z - m); v.w = __expf(v.w - m);
        s += v.x + v.y + v.z + v.w;
        row[j] = v;
    }
    float ws = warp_sum(s);
    if ((tid & 31) == 0) sh[tid >> 5] = ws;
    __syncthreads();
    if (tid < 32) {
        float s2 = (tid < 8) ? sh[tid] : 0.f;
        s2 = warp_sum(s2);
        if (tid == 0) sh[0] = s2;
    }
    __syncthreads();
    float inv = 1.f / sh[0];
    size_t base = (size_t)i << 13;
    for (int j = tid; j < n4; j += 256) {
        float4 v = row[j];
        uint2 hv = make_uint2(
            (uint32_t)to_h(v.x * inv) | ((uint32_t)to_h(v.y * inv) << 16),
            (uint32_t)to_h(v.z * inv) | ((uint32_t)to_h(v.w * inv) << 16));
        *(uint2*)(g_ph + base + 4 * (size_t)j) = hv;
    }
}

// ---------------- orchestration ----------------
extern "C" void kernel_launch(void* const* d_in, const int* in_sizes, int n_in,
                              void* d_out, int out_size) {
    (void)in_sizes; (void)n_in; (void)out_size;

    float *act, *t1, *y0, *mid, *p;
    ushort_t *wah, *acth, *qh, *kh, *vh, *oh, *ph, *wh;
    cudaGetSymbolAddress((void**)&act,  g_act);
    cudaGetSymbolAddress((void**)&t1,   g_t1);
    cudaGetSymbolAddress((void**)&y0,   g_y0);
    cudaGetSymbolAddress((void**)&mid,  g_mid);
    cudaGetSymbolAddress((void**)&p,    g_p);
    cudaGetSymbolAddress((void**)&wah,  g_wah);
    cudaGetSymbolAddress((void**)&acth, g_acth);
    cudaGetSymbolAddress((void**)&qh,   g_qh);
    cudaGetSymbolAddress((void**)&kh,   g_kh);
    cudaGetSymbolAddress((void**)&vh,   g_vh);
    cudaGetSymbolAddress((void**)&oh,   g_oh);
    cudaGetSymbolAddress((void**)&ph,   g_ph);
    cudaGetSymbolAddress((void**)&wh,   g_wh);

    cudaFuncSetAttribute(conv_hmma_k, cudaFuncAttributeMaxDynamicSharedMemorySize, 4 * STG);
    cudaFuncSetAttribute(hmma_gemm_k, cudaFuncAttributeMaxDynamicSharedMemorySize, 3 * STG);

    const float* X = (const float*)d_in[0];
    const float* a_gns = (const float*)d_in[17];
    const float* a_gnb = (const float*)d_in[18];
    const float* a_wq  = (const float*)d_in[19];
    const float* a_bq  = (const float*)d_in[20];
    const float* a_wk  = (const float*)d_in[21];
    const float* a_bk  = (const float*)d_in[22];
    const float* a_wv  = (const float*)d_in[23];
    const float* a_bv  = (const float*)d_in[24];
    const float* a_wo  = (const float*)d_in[25];
    const float* a_bo  = (const float*)d_in[26];

    const dim3 conv_grid(16, 64);
    const int IM2COL_BLOCKS = (S_ * (KC / 8)) / 256;
    const int WPACK_CONV    = ((C_ * KC) / 8) / 256;
    const int WPACK_SQ      = ((C_ * C_) / 8) / 256;
    const int KSUM_BLOCKS   = (C_ * S_ / 4) / 256;

    auto resnet = [&](const float* in, int base, float* midb, float* outbuf) {
        const float* n1s = (const float*)d_in[base + 0];
        const float* n1b = (const float*)d_in[base + 1];
        const float* w1  = (const float*)d_in[base + 2];
        const float* b1  = (const float*)d_in[base + 3];
        const float* n2s = (const float*)d_in[base + 4];
        const float* n2b = (const float*)d_in[base + 5];
        const float* w2  = (const float*)d_in[base + 6];
        const float* b2  = (const float*)d_in[base + 7];

        gn_stats_k<<<NGROUP, 256>>>(in);
        normact_k<<<(C_ * S_) / 256, 256>>>(in, n1s, n1b, act, 1);
        im2col_pack_k<<<IM2COL_BLOCKS, 256>>>();
        wpack_k<<<WPACK_CONV, 256>>>(w1, wh);
        conv_hmma_k<<<conv_grid, 256, 4 * STG>>>();
        ksum_k<<<KSUM_BLOCKS, 256>>>(midb, b1, nullptr);
        gn_stats_k<<<NGROUP, 256>>>(midb);
        normact_k<<<(C_ * S_) / 256, 256>>>(midb, n2s, n2b, act, 1);
        im2col_pack_k<<<IM2COL_BLOCKS, 256>>>();
        wpack_k<<<WPACK_CONV, 256>>>(w2, wh);
        conv_hmma_k<<<conv_grid, 256, 4 * STG>>>();
        ksum_k<<<KSUM_BLOCKS, 256>>>(outbuf, b2, in);
    };

    // ---- ResNet block 0:  X -> y0 ----
    resnet(X, 1, t1, y0);

    // ---- Causal frame attention on y0 ----
    gn_stats_k<<<NGROUP, 256>>>(y0);
    normact_k<<<(C_ * S_) / 256, 256>>>(y0, a_gns, a_gnb, act, 0);
    atpack_k<<<dim3(S_ / 32, C_ / 32), dim3(32, 8)>>>();

    // Q[s][d] = act . wq^T + bq
    wpack_k<<<WPACK_SQ, 256>>>(a_wq, wah);
    hmma_gemm_k<<<dim3(4, 64), 256, 3 * STG>>>(acth, C_, wah, C_,
        nullptr, qh, C_, C_, 1.f, nullptr, a_bq, nullptr, 0, 0, 0);
    // K[s][d]
    wpack_k<<<WPACK_SQ, 256>>>(a_wk, wah);
    hmma_gemm_k<<<dim3(4, 64), 256, 3 * STG>>>(acth, C_, wah, C_,
        nullptr, kh, C_, C_, 1.f, nullptr, a_bk, nullptr, 0, 0, 0);
    // V[d][s] = wv . act^T + bv
    wpack_k<<<WPACK_SQ, 256>>>(a_wv, wah);
    hmma_gemm_k<<<dim3(64, 4), 256, 3 * STG>>>(wah, C_, acth, C_,
        nullptr, vh, S_, C_, 1.f, a_bv, nullptr, nullptr, 0, 0, 0);

    // scores: Q . K^T (block-causal tile skip)
    hmma_gemm_k<<<dim3(64, 64), 256, 3 * STG>>>(qh, C_, kh, C_,
        p, nullptr, S_, C_, 0.04419417382415922f,
        nullptr, nullptr, nullptr, 1, 0, 0);
    softmax_k<<<S_, 256>>>();
    // O[s][d] = P . V^T  (reversed m-order, causal K bound)
    hmma_gemm_k<<<dim3(4, 64), 256, 3 * STG>>>(ph, S_, vh, S_,
        nullptr, oh, C_, S_, 1.f, nullptr, nullptr, nullptr, 0, 1, 1);
    // attnout[c][s] = wo . O^T + bo + y0
    wpack_k<<<WPACK_SQ, 256>>>(a_wo, wah);
    hmma_gemm_k<<<dim3(64, 4), 256, 3 * STG>>>(wah, C_, oh, C_,
        t1, nullptr, S_, C_, 1.f, a_bo, nullptr, y0, 0, 0, 0);

    // ---- ResNet block 1:  t1 -> d_out ----
    resnet(t1, 9, mid, (float*)d_out);
}

// round 9
// speedup vs baseline: 5.2782x; 1.0852x over previous
#include <cuda_runtime.h>
#include <cuda_fp16.h>
#include <math.h>
#include <stdint.h>

#define C_      512
#define S_      8192
#define HW_     1024
#define W_      32
#define NGROUP  32
#define CPG     16
#define KC      13824
#define NSPLIT  4
#define KSPLIT_ITERS 108      // (KC/32)/4
#define KSUM_BLOCKS 4096      // (C_*S_/4)/256, 1024 elems per block

// smem stage: A 8K | B 8K
#define STG 16384

typedef unsigned short ushort_t;

__device__ float g_mean[NGROUP];
__device__ float g_rstd[NGROUP];
__device__ float2 g_part[KSUM_BLOCKS];                       // ksum partial (sum, sumsq)
__device__ float g_t1 [(size_t)C_ * S_];
__device__ float g_y0 [(size_t)C_ * S_];
__device__ float g_mid[(size_t)C_ * S_];
__device__ float g_p  [(size_t)S_ * S_];
__device__ float g_ks [(size_t)NSPLIT * C_ * S_];
// fp16 operands
__device__ __align__(16) ushort_t g_af16[(size_t)C_ * S_];   // GN+SiLU act [c][s]
__device__ __align__(16) ushort_t g_wh [(size_t)C_ * KC];    // conv weights
__device__ __align__(16) ushort_t g_bh [(size_t)S_ * KC];    // im2col
__device__ __align__(16) ushort_t g_acth[(size_t)S_ * C_];   // attn xn [s][c]
__device__ __align__(16) ushort_t g_wah[(size_t)C_ * C_];
__device__ __align__(16) ushort_t g_qh [(size_t)S_ * C_];
__device__ __align__(16) ushort_t g_kh [(size_t)S_ * C_];
__device__ __align__(16) ushort_t g_vh [(size_t)C_ * S_];
__device__ __align__(16) ushort_t g_oh [(size_t)S_ * C_];
__device__ __align__(16) ushort_t g_ph [(size_t)S_ * S_];

// ---------------- PTX helpers ----------------
__device__ __forceinline__ uint32_t smem_u32(const void* p) {
    uint32_t a;
    asm("{ .reg .u64 t; cvta.to.shared.u64 t, %1; cvt.u32.u64 %0, t; }" : "=r"(a) : "l"(p));
    return a;
}
#define CP_ASYNC16(smem, gmem) \
    asm volatile("cp.async.cg.shared.global [%0], [%1], 16;" :: "r"(smem), "l"(gmem) : "memory")
#define CP_COMMIT() asm volatile("cp.async.commit_group;" ::: "memory")
#define CP_WAIT1()  asm volatile("cp.async.wait_group 1;" ::: "memory")
#define CP_WAIT2()  asm volatile("cp.async.wait_group 2;" ::: "memory")
#define LDSM4(r, addr) \
    asm volatile("ldmatrix.sync.aligned.m8n8.x4.shared.b16 {%0,%1,%2,%3}, [%4];" \
        : "=r"((r)[0]),"=r"((r)[1]),"=r"((r)[2]),"=r"((r)[3]) : "r"(addr))
#define MMA16816(d, a, b0, b1) \
    asm volatile("mma.sync.aligned.m16n8k16.row.col.f32.f16.f16.f32 " \
        "{%0,%1,%2,%3}, {%4,%5,%6,%7}, {%8,%9}, {%0,%1,%2,%3};" \
        : "+f"((d)[0]),"+f"((d)[1]),"+f"((d)[2]),"+f"((d)[3]) \
        : "r"((a)[0]),"r"((a)[1]),"r"((a)[2]),"r"((a)[3]), "r"(b0),"r"(b1))

__device__ __forceinline__ ushort_t to_h(float v) {
    return __half_as_ushort(__float2half_rn(v));
}

__inline__ __device__ float warp_sum(float v) {
    #pragma unroll
    for (int o = 16; o; o >>= 1) v += __shfl_down_sync(0xffffffffu, v, o);
    return v;
}
__inline__ __device__ float warp_max(float v) {
    #pragma unroll
    for (int o = 16; o; o >>= 1) v = fmaxf(v, __shfl_down_sync(0xffffffffu, v, o));
    return v;
}

// ---------------- GroupNorm stats (full read) ----------------
__global__ void gn_stats_k(const float* __restrict__ x) {
    int g = blockIdx.x;
    const float4* p = (const float4*)(x + (size_t)g * CPG * S_);
    const int n4 = (CPG * S_) / 4;
    float s = 0.f, s2 = 0.f;
    for (int i = threadIdx.x; i < n4; i += blockDim.x) {
        float4 v = p[i];
        s  += v.x + v.y + v.z + v.w;
        s2 += v.x * v.x + v.y * v.y + v.z * v.z + v.w * v.w;
    }
    __shared__ float sh0[8], sh1[8];
    float ws = warp_sum(s), ws2 = warp_sum(s2);
    int wid = threadIdx.x >> 5, lid = threadIdx.x & 31;
    if (!lid) { sh0[wid] = ws; sh1[wid] = ws2; }
    __syncthreads();
    if (threadIdx.x == 0) {
        float a = 0.f, b = 0.f;
        #pragma unroll
        for (int i = 0; i < 8; i++) { a += sh0[i]; b += sh1[i]; }
        const float inv_n = 1.f / (float)(CPG * S_);
        float m = a * inv_n;
        g_mean[g] = m;
        g_rstd[g] = rsqrtf(b * inv_n - m * m + 1e-6f);
    }
}

// ---------------- GroupNorm stats from ksum partials ----------------
// group g <- partial blocks [g*128, g*128+128)
__global__ void gn_stats_p() {
    int g = blockIdx.x;
    float2 v = g_part[g * 128 + threadIdx.x];
    __shared__ float sh0[4], sh1[4];
    float ws = warp_sum(v.x), ws2 = warp_sum(v.y);
    int wid = threadIdx.x >> 5, lid = threadIdx.x & 31;
    if (!lid) { sh0[wid] = ws; sh1[wid] = ws2; }
    __syncthreads();
    if (threadIdx.x == 0) {
        float a = sh0[0] + sh0[1] + sh0[2] + sh0[3];
        float b = sh1[0] + sh1[1] + sh1[2] + sh1[3];
        const float inv_n = 1.f / (float)(CPG * S_);
        float m = a * inv_n;
        g_mean[g] = m;
        g_rstd[g] = rsqrtf(b * inv_n - m * m + 1e-6f);
    }
}

// ---------------- normalize + SiLU -> fp16 [c][s] (conv path) ----------------
__global__ void normact_k(const float* __restrict__ x, const float* __restrict__ sc,
                          const float* __restrict__ bi) {
    int i4 = blockIdx.x * blockDim.x + threadIdx.x;   // over C_*S_/4
    int c = i4 >> 11;
    int g = c >> 4;
    float mu = g_mean[g], rs = g_rstd[g], sv = sc[c], bv = bi[c];
    float4 v = *(const float4*)(((const float*)x) + (size_t)i4 * 4);
    float a0 = (v.x - mu) * rs * sv + bv;
    float a1 = (v.y - mu) * rs * sv + bv;
    float a2 = (v.z - mu) * rs * sv + bv;
    float a3 = (v.w - mu) * rs * sv + bv;
    a0 = a0 / (1.f + __expf(-a0));
    a1 = a1 / (1.f + __expf(-a1));
    a2 = a2 / (1.f + __expf(-a2));
    a3 = a3 / (1.f + __expf(-a3));
    ushort2 o0 = make_ushort2(to_h(a0), to_h(a1));
    ushort2 o1 = make_ushort2(to_h(a2), to_h(a3));
    *(uint2*)(g_af16 + (size_t)i4 * 4) = make_uint2(
        (uint32_t)o0.x | ((uint32_t)o0.y << 16),
        (uint32_t)o1.x | ((uint32_t)o1.y << 16));
}

// ---------------- transposing GN (no act): y0 [c][s] -> fp16 [s][c] ----------------
__global__ void normt_k(const float* __restrict__ x, const float* __restrict__ sc,
                        const float* __restrict__ bi) {
    __shared__ float tile[32][33];
    int s0 = blockIdx.x * 32, c0 = blockIdx.y * 32;
    int tx = threadIdx.x, ty = threadIdx.y;
    #pragma unroll
    for (int i = ty; i < 32; i += 8)
        tile[i][tx] = x[(size_t)(c0 + i) * S_ + s0 + tx];
    __syncthreads();
    int c = c0 + tx;
    int g = c >> 4;
    float mu = g_mean[g], rs = g_rstd[g], sv = sc[c], bv = bi[c];
    #pragma unroll
    for (int i = ty; i < 32; i += 8) {
        float v = (tile[tx][i] - mu) * rs * sv + bv;
        g_acth[(size_t)(s0 + i) * C_ + c] = to_h(v);
    }
}

// ---------------- im2col: fp16 gather [c][s] -> [pos][KC] ----------------
__global__ void im2col_pack_k() {
    size_t id = (size_t)blockIdx.x * 256 + threadIdx.x;
    int pos = (int)(id / 1728);
    int kc  = (int)(id - (size_t)pos * 1728);
    int k0 = kc * 8;
    int t = pos >> 10, rem = pos & 1023, y = rem >> 5, x = rem & 31;
    __align__(16) ushort_t hv[8];
    #pragma unroll
    for (int e = 0; e < 8; e++) {
        int k = k0 + e;
        int ci = k / 27; int r = k - ci * 27;
        int kd = r / 9;  r -= kd * 9;
        int kh = r / 3;  int kw = r - kh * 3;
        int ts = min(max(t + kd - 2, 0), 7);
        int ys = min(max(y + kh - 1, 0), 31);
        int xs = min(max(x + kw - 1, 0), 31);
        hv[e] = g_af16[(size_t)ci * S_ + ts * HW_ + ys * W_ + xs];
    }
    *(uint4*)(g_bh + (size_t)pos * KC + k0) = *(uint4*)hv;
}

// ---------------- pack: fp32 row-major -> fp16 ----------------
__global__ void wpack_k(const float* __restrict__ w, ushort_t* __restrict__ dh) {
    size_t id = (size_t)blockIdx.x * 256 + threadIdx.x;
    const float4* src = (const float4*)w;
    float4 v0 = src[id * 2], v1 = src[id * 2 + 1];
    __align__(16) ushort_t hv[8];
    hv[0] = to_h(v0.x); hv[1] = to_h(v0.y); hv[2] = to_h(v0.z); hv[3] = to_h(v0.w);
    hv[4] = to_h(v1.x); hv[5] = to_h(v1.y); hv[6] = to_h(v1.z); hv[7] = to_h(v1.w);
    *(uint4*)(dh + id * 8) = *(uint4*)hv;
}

// ---------------- split-K reduce + per-block GN partials ----------------
__global__ void ksum_k(float* __restrict__ out, const float* __restrict__ bias,
                       const float* __restrict__ addend) {
    size_t i = ((size_t)blockIdx.x * 256 + threadIdx.x) * 4;
    int c = (int)(i >> 13);
    float4 v0 = *(const float4*)(g_ks + i);
    float4 v1 = *(const float4*)(g_ks + (size_t)C_ * S_ + i);
    float4 v2 = *(const float4*)(g_ks + (size_t)2 * C_ * S_ + i);
    float4 v3 = *(const float4*)(g_ks + (size_t)3 * C_ * S_ + i);
    float bv = bias[c];
    float4 r;
    r.x = v0.x + v1.x + v2.x + v3.x + bv;
    r.y = v0.y + v1.y + v2.y + v3.y + bv;
    r.z = v0.z + v1.z + v2.z + v3.z + bv;
    r.w = v0.w + v1.w + v2.w + v3.w + bv;
    if (addend) {
        float4 a = *(const float4*)(addend + i);
        r.x += a.x; r.y += a.y; r.z += a.z; r.w += a.w;
    }
    *(float4*)(out + i) = r;
    // GN partials for this block (1024 contiguous elements, one channel)
    float s  = r.x + r.y + r.z + r.w;
    float s2 = r.x * r.x + r.y * r.y + r.z * r.z + r.w * r.w;
    __shared__ float sh0[8], sh1[8];
    float ws = warp_sum(s), ws2 = warp_sum(s2);
    int wid = threadIdx.x >> 5, lid = threadIdx.x & 31;
    if (!lid) { sh0[wid] = ws; sh1[wid] = ws2; }
    __syncthreads();
    if (threadIdx.x == 0) {
        float a = 0.f, b = 0.f;
        #pragma unroll
        for (int k = 0; k < 8; k++) { a += sh0[k]; b += sh1[k]; }
        g_part[blockIdx.x] = make_float2(a, b);
    }
}

// ================= HMMA mainloop (single-pass fp16, 3-stage) =================
struct HmmaAcc { float a[4][4][4]; };

__device__ __forceinline__ void hmma_mainloop(
    HmmaAcc& A4, uint32_t sm0, int tid,
    const ushort_t* __restrict__ Ah, int lda,
    const ushort_t* __restrict__ Bh, int ldb,
    int m0, int n0, int kiters) {
    const int lane = tid & 31, warp = tid >> 5;
    const int wm = warp & 1, wn = warp >> 1;

    auto issue = [&](int stage, int k0) {
        uint32_t sb = sm0 + stage * STG;
        #pragma unroll
        for (int h = 0; h < 2; h++) {
            int id = tid + h * 256;
            int r = id >> 2, cu = id & 3;
            uint32_t soff = r * 64 + (((cu ^ ((r >> 1) & 3))) << 4);
            CP_ASYNC16(sb + soff,        Ah + (size_t)(m0 + r) * lda + k0 + cu * 8);
            CP_ASYNC16(sb + 8192 + soff, Bh + (size_t)(n0 + r) * ldb + k0 + cu * 8);
        }
        CP_COMMIT();
    };

    issue(0, 0);
    issue(1, 32);

    const int rl = lane & 15, ul = lane >> 4;
    for (int it = 0; it < kiters; it++) {
        CP_WAIT1();
        __syncthreads();
        uint32_t sb = sm0 + (it % 3) * STG;
        #pragma unroll
        for (int k16 = 0; k16 < 2; k16++) {
            uint32_t a4[4][4], b4[2][4];
            int u = k16 * 2 + ul;
            #pragma unroll
            for (int i = 0; i < 4; i++) {
                int r = wm * 64 + i * 16 + rl;
                LDSM4(a4[i], sb + r * 64 + (((u ^ ((r >> 1) & 3))) << 4));
            }
            #pragma unroll
            for (int j2 = 0; j2 < 2; j2++) {
                int r = wn * 32 + j2 * 16 + rl;
                LDSM4(b4[j2], sb + 8192 + r * 64 + (((u ^ ((r >> 1) & 3))) << 4));
            }
            #pragma unroll
            for (int i = 0; i < 4; i++)
                #pragma unroll
                for (int j = 0; j < 4; j++) {
                    int j2 = j >> 1, ts = j & 1;
                    MMA16816(A4.a[i][j], a4[i], b4[j2][ts], b4[j2][ts + 2]);
                }
        }
        __syncthreads();
        if (it + 2 < kiters) issue((it + 2) % 3, (it + 2) * 32);
        else CP_COMMIT();
    }
}

// ---------------- conv GEMM, split-K, 4-stage, occupancy 2 ----------------
// grid (16, 64): x -> m-tile (x&3), ksplit (x>>2); y -> n-tile
__global__ void __launch_bounds__(256, 2) conv_hmma_k() {
    extern __shared__ unsigned char dynsm[];
    const uint32_t sm0 = smem_u32(dynsm);
    const int tid = threadIdx.x, lane = tid & 31, warp = tid >> 5;
    const int m0 = (blockIdx.x & 3) * 128;
    const int ks = blockIdx.x >> 2;
    const int n0 = blockIdx.y * 128;
    const int kbase = ks * (KSPLIT_ITERS * 32);
    const int wm = warp & 1, wn = warp >> 1;

    auto issue = [&](int stage, int k0) {
        uint32_t sb = sm0 + stage * STG;
        #pragma unroll
        for (int h = 0; h < 2; h++) {
            int id = tid + h * 256;
            int r = id >> 2, cu = id & 3;
            uint32_t soff = r * 64 + (((cu ^ ((r >> 1) & 3))) << 4);
            CP_ASYNC16(sb + soff,        g_wh + (size_t)(m0 + r) * KC + k0 + cu * 8);
            CP_ASYNC16(sb + 8192 + soff, g_bh + (size_t)(n0 + r) * KC + k0 + cu * 8);
        }
        CP_COMMIT();
    };

    float acc[4][4][4];
    #pragma unroll
    for (int i = 0; i < 4; i++)
        #pragma unroll
        for (int j = 0; j < 4; j++)
            #pragma unroll
            for (int r = 0; r < 4; r++) acc[i][j][r] = 0.f;

    issue(0, kbase);
    issue(1, kbase + 32);
    issue(2, kbase + 64);

    const int rl = lane & 15, ul = lane >> 4;
    for (int it = 0; it < KSPLIT_ITERS; it++) {
        CP_WAIT2();
        __syncthreads();
        uint32_t sb = sm0 + (it & 3) * STG;
        #pragma unroll
        for (int k16 = 0; k16 < 2; k16++) {
            uint32_t a4[4][4], b4[2][4];
            int u = k16 * 2 + ul;
            #pragma unroll
            for (int i = 0; i < 4; i++) {
                int r = wm * 64 + i * 16 + rl;
                LDSM4(a4[i], sb + r * 64 + (((u ^ ((r >> 1) & 3))) << 4));
            }
            #pragma unroll
            for (int j2 = 0; j2 < 2; j2++) {
                int r = wn * 32 + j2 * 16 + rl;
                LDSM4(b4[j2], sb + 8192 + r * 64 + (((u ^ ((r >> 1) & 3))) << 4));
            }
            #pragma unroll
            for (int i = 0; i < 4; i++)
                #pragma unroll
                for (int j = 0; j < 4; j++) {
                    int j2 = j >> 1, ts = j & 1;
                    MMA16816(acc[i][j], a4[i], b4[j2][ts], b4[j2][ts + 2]);
                }
        }
        __syncthreads();
        if (it + 3 < KSPLIT_ITERS) issue((it + 3) & 3, kbase + (it + 3) * 32);
        else CP_COMMIT();
    }

    float* Sp = g_ks + (size_t)ks * C_ * S_;
    const int mrow = m0 + wm * 64 + (lane >> 2);
    const int ncol = n0 + wn * 32 + (lane & 3) * 2;
    #pragma unroll
    for (int i = 0; i < 4; i++) {
        int ma = mrow + i * 16, mb = ma + 8;
        #pragma unroll
        for (int j = 0; j < 4; j++) {
            int n = ncol + j * 8;
            *(float2*)(Sp + (size_t)ma * S_ + n) = make_float2(acc[i][j][0], acc[i][j][1]);
            *(float2*)(Sp + (size_t)mb * S_ + n) = make_float2(acc[i][j][2], acc[i][j][3]);
        }
    }
}

// ---------------- generic attention GEMM, occupancy 2 ----------------
__global__ void __launch_bounds__(256, 2) hmma_gemm_k(
    const ushort_t* __restrict__ Ah, int lda,
    const ushort_t* __restrict__ Bh, int ldb,
    float* __restrict__ Cf, ushort_t* __restrict__ Ch,
    int ldc, int K, float alpha,
    const float* __restrict__ biasM, const float* __restrict__ biasN,
    const float* __restrict__ addend, int causal, int kcausal, int mrev) {
    const int by = mrev ? (gridDim.y - 1 - blockIdx.y) : blockIdx.y;
    const int m0 = by * 128, n0 = blockIdx.x * 128;
    if (causal && n0 >= (((m0 >> 10) + 1) << 10)) return;
    int Keff = kcausal ? (((m0 >> 10) + 1) << 10) : K;

    extern __shared__ unsigned char dynsm[];
    const uint32_t sm0 = smem_u32(dynsm);
    const int tid = threadIdx.x, lane = tid & 31, warp = tid >> 5;
    const int wm = warp & 1, wn = warp >> 1;

    HmmaAcc acc;
    #pragma unroll
    for (int i = 0; i < 4; i++)
        #pragma unroll
        for (int j = 0; j < 4; j++)
            #pragma unroll
            for (int r = 0; r < 4; r++) acc.a[i][j][r] = 0.f;

    hmma_mainloop(acc, sm0, tid, Ah, lda, Bh, ldb, m0, n0, Keff >> 5);

    const int mrow = m0 + wm * 64 + (lane >> 2);
    const int ncol = n0 + wn * 32 + (lane & 3) * 2;
    #pragma unroll
    for (int i = 0; i < 4; i++) {
        int ma = mrow + i * 16, mb = ma + 8;
        float bva = biasM ? biasM[ma] : 0.f;
        float bvb = biasM ? biasM[mb] : 0.f;
        #pragma unroll
        for (int j = 0; j < 4; j++) {
            int n = ncol + j * 8;
            float2 va = make_float2(acc.a[i][j][0] * alpha + bva, acc.a[i][j][1] * alpha + bva);
            float2 vb = make_float2(acc.a[i][j][2] * alpha + bvb, acc.a[i][j][3] * alpha + bvb);
            if (biasN) {
                float b0 = biasN[n], b1 = biasN[n + 1];
                va.x += b0; va.y += b1; vb.x += b0; vb.y += b1;
            }
            if (addend) {
                float2 aa = *(const float2*)(addend + (size_t)ma * ldc + n);
                float2 ab = *(const float2*)(addend + (size_t)mb * ldc + n);
                va.x += aa.x; va.y += aa.y; vb.x += ab.x; vb.y += ab.y;
            }
            if (Cf) {
                *(float2*)(Cf + (size_t)ma * ldc + n) = va;
                *(float2*)(Cf + (size_t)mb * ldc + n) = vb;
            }
            if (Ch) {
                *(ushort2*)(Ch + (size_t)ma * ldc + n) = make_ushort2(to_h(va.x), to_h(va.y));
                *(ushort2*)(Ch + (size_t)mb * ldc + n) = make_ushort2(to_h(vb.x), to_h(vb.y));
            }
        }
    }
}

// ---------------- softmax: single gmem pass via smem row buffer ----------------
__global__ void softmax_k() {
    __shared__ float row[S_];
    __shared__ float sh[8];
    int i = blockIdx.x;
    int L = ((i >> 10) + 1) << 10;
    const float4* src = (const float4*)(g_p + ((size_t)i << 13));
    int n4 = L >> 2;
    int tid = threadIdx.x;

    float mx = -1e30f;
    for (int j = tid; j < n4; j += 256) {
        float4 v = src[j];
        *(float4*)(row + 4 * j) = v;
        mx = fmaxf(mx, fmaxf(fmaxf(v.x, v.y), fmaxf(v.z, v.w)));
    }
    float wm = warp_max(mx);
    if ((tid & 31) == 0) sh[tid >> 5] = wm;
    __syncthreads();
    if (tid < 32) {
        float m2 = (tid < 8) ? sh[tid] : -1e30f;
        m2 = warp_max(m2);
        if (tid == 0) sh[0] = m2;
    }
    __syncthreads();
    float m = sh[0];
    __syncthreads();

    float s = 0.f;
    for (int j = tid; j < n4; j += 256) {
        float4 v = *(float4*)(row + 4 * j);
        v.x = __expf(v.x - m); v.y = __expf(v.y - m);
        v.z = __expf(v.z - m); v.w = __expf(v.w - m);
        s += v.x + v.y + v.z + v.w;
        *(float4*)(row + 4 * j) = v;
    }
    float ws = warp_sum(s);
    if ((tid & 31) == 0) sh[tid >> 5] = ws;
    __syncthreads();
    if (tid < 32) {
        float s2 = (tid < 8) ? sh[tid] : 0.f;
        s2 = warp_sum(s2);
        if (tid == 0) sh[0] = s2;
    }
    __syncthreads();
    float inv = 1.f / sh[0];
    size_t base = (size_t)i << 13;
    for (int j = tid; j < n4; j += 256) {
        float4 v = *(float4*)(row + 4 * j);
        uint2 hv = make_uint2(
            (uint32_t)to_h(v.x * inv) | ((uint32_t)to_h(v.y * inv) << 16),
            (uint32_t)to_h(v.z * inv) | ((uint32_t)to_h(v.w * inv) << 16));
        *(uint2*)(g_ph + base + 4 * (size_t)j) = hv;
    }
}

// ---------------- orchestration ----------------
extern "C" void kernel_launch(void* const* d_in, const int* in_sizes, int n_in,
                              void* d_out, int out_size) {
    (void)in_sizes; (void)n_in; (void)out_size;

    float *t1, *y0, *mid, *p;
    ushort_t *wah, *acth, *qh, *kh, *vh, *oh, *ph, *wh;
    cudaGetSymbolAddress((void**)&t1,   g_t1);
    cudaGetSymbolAddress((void**)&y0,   g_y0);
    cudaGetSymbolAddress((void**)&mid,  g_mid);
    cudaGetSymbolAddress((void**)&p,    g_p);
    cudaGetSymbolAddress((void**)&wah,  g_wah);
    cudaGetSymbolAddress((void**)&acth, g_acth);
    cudaGetSymbolAddress((void**)&qh,   g_qh);
    cudaGetSymbolAddress((void**)&kh,   g_kh);
    cudaGetSymbolAddress((void**)&vh,   g_vh);
    cudaGetSymbolAddress((void**)&oh,   g_oh);
    cudaGetSymbolAddress((void**)&ph,   g_ph);
    cudaGetSymbolAddress((void**)&wh,   g_wh);

    cudaFuncSetAttribute(conv_hmma_k, cudaFuncAttributeMaxDynamicSharedMemorySize, 4 * STG);
    cudaFuncSetAttribute(hmma_gemm_k, cudaFuncAttributeMaxDynamicSharedMemorySize, 3 * STG);

    const float* X = (const float*)d_in[0];
    const float* a_gns = (const float*)d_in[17];
    const float* a_gnb = (const float*)d_in[18];
    const float* a_wq  = (const float*)d_in[19];
    const float* a_bq  = (const float*)d_in[20];
    const float* a_wk  = (const float*)d_in[21];
    const float* a_bk  = (const float*)d_in[22];
    const float* a_wv  = (const float*)d_in[23];
    const float* a_bv  = (const float*)d_in[24];
    const float* a_wo  = (const float*)d_in[25];
    const float* a_bo  = (const float*)d_in[26];

    const dim3 conv_grid(16, 64);
    const int IM2COL_BLOCKS = (S_ * (KC / 8)) / 256;
    const int WPACK_CONV    = ((C_ * KC) / 8) / 256;
    const int WPACK_SQ      = ((C_ * C_) / 8) / 256;
    const int NA_BLOCKS     = (C_ * S_ / 4) / 256;

    // stats_from_part: input's GN stats already available via ksum partials
    auto resnet = [&](const float* in, int base, float* midb, float* outbuf,
                      int in_stats_from_part) {
        const float* n1s = (const float*)d_in[base + 0];
        const float* n1b = (const float*)d_in[base + 1];
        const float* w1  = (const float*)d_in[base + 2];
        const float* b1  = (const float*)d_in[base + 3];
        const float* n2s = (const float*)d_in[base + 4];
        const float* n2b = (const float*)d_in[base + 5];
        const float* w2  = (const float*)d_in[base + 6];
        const float* b2  = (const float*)d_in[base + 7];

        if (in_stats_from_part) gn_stats_p<<<NGROUP, 128>>>();
        else                    gn_stats_k<<<NGROUP, 256>>>(in);
        normact_k<<<NA_BLOCKS, 256>>>(in, n1s, n1b);
        im2col_pack_k<<<IM2COL_BLOCKS, 256>>>();
        wpack_k<<<WPACK_CONV, 256>>>(w1, wh);
        conv_hmma_k<<<conv_grid, 256, 4 * STG>>>();
        ksum_k<<<KSUM_BLOCKS, 256>>>(midb, b1, nullptr);
        gn_stats_p<<<NGROUP, 128>>>();
        normact_k<<<NA_BLOCKS, 256>>>(midb, n2s, n2b);
        im2col_pack_k<<<IM2COL_BLOCKS, 256>>>();
        wpack_k<<<WPACK_CONV, 256>>>(w2, wh);
        conv_hmma_k<<<conv_grid, 256, 4 * STG>>>();
        ksum_k<<<KSUM_BLOCKS, 256>>>(outbuf, b2, in);
    };

    // ---- ResNet block 0:  X -> y0 ----
    resnet(X, 1, t1, y0, 0);

    // ---- Causal frame attention on y0 (stats via ksum partials) ----
    gn_stats_p<<<NGROUP, 128>>>();
    normt_k<<<dim3(S_ / 32, C_ / 32), dim3(32, 8)>>>(y0, a_gns, a_gnb);

    // Q[s][d] = act . wq^T + bq
    wpack_k<<<WPACK_SQ, 256>>>(a_wq, wah);
    hmma_gemm_k<<<dim3(4, 64), 256, 3 * STG>>>(acth, C_, wah, C_,
        nullptr, qh, C_, C_, 1.f, nullptr, a_bq, nullptr, 0, 0, 0);
    // K[s][d]
    wpack_k<<<WPACK_SQ, 256>>>(a_wk, wah);
    hmma_gemm_k<<<dim3(4, 64), 256, 3 * STG>>>(acth, C_, wah, C_,
        nullptr, kh, C_, C_, 1.f, nullptr, a_bk, nullptr, 0, 0, 0);
    // V[d][s] = wv . act^T + bv
    wpack_k<<<WPACK_SQ, 256>>>(a_wv, wah);
    hmma_gemm_k<<<dim3(64, 4), 256, 3 * STG>>>(wah, C_, acth, C_,
        nullptr, vh, S_, C_, 1.f, a_bv, nullptr, nullptr, 0, 0, 0);

    // scores: Q . K^T (block-causal tile skip)
    hmma_gemm_k<<<dim3(64, 64), 256, 3 * STG>>>(qh, C_, kh, C_,
        p, nullptr, S_, C_, 0.04419417382415922f,
        nullptr, nullptr, nullptr, 1, 0, 0);
    softmax_k<<<S_, 256>>>();
    // O[s][d] = P . V^T  (reversed m-order, causal K bound)
    hmma_gemm_k<<<dim3(4, 64), 256, 3 * STG>>>(ph, S_, vh, S_,
        nullptr, oh, C_, S_, 1.f, nullptr, nullptr, nullptr, 0, 1, 1);
    // attnout[c][s] = wo . O^T + bo + y0
    wpack_k<<<WPACK_SQ, 256>>>(a_wo, wah);
    hmma_gemm_k<<<dim3(64, 4), 256, 3 * STG>>>(wah, C_, oh, C_,
        t1, nullptr, S_, C_, 1.f, a_bo, nullptr, y0, 0, 0, 0);

    // ---- ResNet block 1:  t1 -> d_out ----
    resnet(t1, 9, mid, (float*)d_out, 0);
}

// round 10
// speedup vs baseline: 7.2752x; 1.3784x over previous
#include <cuda_runtime.h>
#include <cuda_fp16.h>
#include <math.h>
#include <stdint.h>

#define C_      512
#define S_      8192
#define HW_     1024
#define W_      32
#define NGROUP  32
#define CPG     16
#define KC      13824
#define NSPLIT  4
#define KSPLIT_ITERS 108      // (KC/32)/4
#define KSUM_BLOCKS 4096      // (C_*S_/4)/256

// smem stage: A 8K | B 8K
#define STG 16384

typedef unsigned short ushort_t;

__device__ float g_mean[NGROUP];
__device__ float g_rstd[NGROUP];
__device__ float2 g_part[KSUM_BLOCKS];
__device__ float g_t1 [(size_t)C_ * S_];
__device__ float g_y0 [(size_t)C_ * S_];
__device__ float g_mid[(size_t)C_ * S_];
__device__ float g_p  [(size_t)S_ * S_];
__device__ float g_ks [(size_t)NSPLIT * C_ * S_];
// fp16 operands
__device__ __align__(16) ushort_t g_ath[(size_t)S_ * C_];    // normalized act [s][c] (shared conv/attn)
__device__ __align__(16) ushort_t g_wh [(size_t)C_ * KC];    // conv weights, K = r*512+ci
__device__ __align__(16) ushort_t g_wah[(size_t)C_ * C_];
__device__ __align__(16) ushort_t g_qh [(size_t)S_ * C_];
__device__ __align__(16) ushort_t g_kh [(size_t)S_ * C_];
__device__ __align__(16) ushort_t g_vh [(size_t)C_ * S_];
__device__ __align__(16) ushort_t g_oh [(size_t)S_ * C_];
__device__ __align__(16) ushort_t g_ph [(size_t)S_ * S_];

// ---------------- PTX helpers ----------------
__device__ __forceinline__ uint32_t smem_u32(const void* p) {
    uint32_t a;
    asm("{ .reg .u64 t; cvta.to.shared.u64 t, %1; cvt.u32.u64 %0, t; }" : "=r"(a) : "l"(p));
    return a;
}
#define CP_ASYNC16(smem, gmem) \
    asm volatile("cp.async.cg.shared.global [%0], [%1], 16;" :: "r"(smem), "l"(gmem) : "memory")
#define CP_COMMIT() asm volatile("cp.async.commit_group;" ::: "memory")
#define CP_WAIT1()  asm volatile("cp.async.wait_group 1;" ::: "memory")
#define CP_WAIT2()  asm volatile("cp.async.wait_group 2;" ::: "memory")
#define LDSM4(r, addr) \
    asm volatile("ldmatrix.sync.aligned.m8n8.x4.shared.b16 {%0,%1,%2,%3}, [%4];" \
        : "=r"((r)[0]),"=r"((r)[1]),"=r"((r)[2]),"=r"((r)[3]) : "r"(addr))
#define MMA16816(d, a, b0, b1) \
    asm volatile("mma.sync.aligned.m16n8k16.row.col.f32.f16.f16.f32 " \
        "{%0,%1,%2,%3}, {%4,%5,%6,%7}, {%8,%9}, {%0,%1,%2,%3};" \
        : "+f"((d)[0]),"+f"((d)[1]),"+f"((d)[2]),"+f"((d)[3]) \
        : "r"((a)[0]),"r"((a)[1]),"r"((a)[2]),"r"((a)[3]), "r"(b0),"r"(b1))

__device__ __forceinline__ ushort_t to_h(float v) {
    return __half_as_ushort(__float2half_rn(v));
}

__inline__ __device__ float warp_sum(float v) {
    #pragma unroll
    for (int o = 16; o; o >>= 1) v += __shfl_down_sync(0xffffffffu, v, o);
    return v;
}
__inline__ __device__ float warp_max(float v) {
    #pragma unroll
    for (int o = 16; o; o >>= 1) v = fmaxf(v, __shfl_down_sync(0xffffffffu, v, o));
    return v;
}

// ---------------- GroupNorm stats (full read) ----------------
__global__ void gn_stats_k(const float* __restrict__ x) {
    int g = blockIdx.x;
    const float4* p = (const float4*)(x + (size_t)g * CPG * S_);
    const int n4 = (CPG * S_) / 4;
    float s = 0.f, s2 = 0.f;
    for (int i = threadIdx.x; i < n4; i += blockDim.x) {
        float4 v = p[i];
        s  += v.x + v.y + v.z + v.w;
        s2 += v.x * v.x + v.y * v.y + v.z * v.z + v.w * v.w;
    }
    __shared__ float sh0[8], sh1[8];
    float ws = warp_sum(s), ws2 = warp_sum(s2);
    int wid = threadIdx.x >> 5, lid = threadIdx.x & 31;
    if (!lid) { sh0[wid] = ws; sh1[wid] = ws2; }
    __syncthreads();
    if (threadIdx.x == 0) {
        float a = 0.f, b = 0.f;
        #pragma unroll
        for (int i = 0; i < 8; i++) { a += sh0[i]; b += sh1[i]; }
        const float inv_n = 1.f / (float)(CPG * S_);
        float m = a * inv_n;
        g_mean[g] = m;
        g_rstd[g] = rsqrtf(b * inv_n - m * m + 1e-6f);
    }
}

// ---------------- GroupNorm stats from ksum partials ----------------
__global__ void gn_stats_p() {
    int g = blockIdx.x;
    float2 v = g_part[g * 128 + threadIdx.x];
    __shared__ float sh0[4], sh1[4];
    float ws = warp_sum(v.x), ws2 = warp_sum(v.y);
    int wid = threadIdx.x >> 5, lid = threadIdx.x & 31;
    if (!lid) { sh0[wid] = ws; sh1[wid] = ws2; }
    __syncthreads();
    if (threadIdx.x == 0) {
        float a = sh0[0] + sh0[1] + sh0[2] + sh0[3];
        float b = sh1[0] + sh1[1] + sh1[2] + sh1[3];
        const float inv_n = 1.f / (float)(CPG * S_);
        float m = a * inv_n;
        g_mean[g] = m;
        g_rstd[g] = rsqrtf(b * inv_n - m * m + 1e-6f);
    }
}

// ---------------- transposing GN (+optional SiLU): x [c][s] -> fp16 [s][c] ------
__global__ void normact_t_k(const float* __restrict__ x, const float* __restrict__ sc,
                            const float* __restrict__ bi, int do_silu) {
    __shared__ float tile[32][33];
    int s0 = blockIdx.x * 32, c0 = blockIdx.y * 32;
    int tx = threadIdx.x, ty = threadIdx.y;
    #pragma unroll
    for (int i = ty; i < 32; i += 8)
        tile[i][tx] = x[(size_t)(c0 + i) * S_ + s0 + tx];
    __syncthreads();
    int c = c0 + tx;
    int g = c >> 4;
    float mu = g_mean[g], rs = g_rstd[g], sv = sc[c], bv = bi[c];
    #pragma unroll
    for (int i = ty; i < 32; i += 8) {
        float v = (tile[tx][i] - mu) * rs * sv + bv;
        if (do_silu) v = v / (1.f + __expf(-v));
        g_ath[(size_t)(s0 + i) * C_ + c] = to_h(v);
    }
}

// ---------------- conv weight pack: w[co][ci*27+r] -> fp16 g_wh[co][r*512+ci] ----
__global__ void wpack_conv_k(const float* __restrict__ w) {
    size_t id = (size_t)blockIdx.x * 256 + threadIdx.x;    // over C_*KC/8
    int co = (int)(id / 1728);
    int kk = (int)(id - (size_t)co * 1728) * 8;            // permuted k base
    int r  = kk >> 9;
    int ci0 = kk & 511;
    const float* src = w + (size_t)co * KC + r;
    __align__(16) ushort_t hv[8];
    #pragma unroll
    for (int e = 0; e < 8; e++)
        hv[e] = to_h(src[(size_t)(ci0 + e) * 27]);
    *(uint4*)(g_wh + (size_t)co * KC + kk) = *(uint4*)hv;
}

// ---------------- pack: fp32 row-major -> fp16 (attention weights) ----------------
__global__ void wpack_k(const float* __restrict__ w, ushort_t* __restrict__ dh) {
    size_t id = (size_t)blockIdx.x * 256 + threadIdx.x;
    const float4* src = (const float4*)w;
    float4 v0 = src[id * 2], v1 = src[id * 2 + 1];
    __align__(16) ushort_t hv[8];
    hv[0] = to_h(v0.x); hv[1] = to_h(v0.y); hv[2] = to_h(v0.z); hv[3] = to_h(v0.w);
    hv[4] = to_h(v1.x); hv[5] = to_h(v1.y); hv[6] = to_h(v1.z); hv[7] = to_h(v1.w);
    *(uint4*)(dh + id * 8) = *(uint4*)hv;
}

// ---------------- split-K reduce + per-block GN partials ----------------
__global__ void ksum_k(float* __restrict__ out, const float* __restrict__ bias,
                       const float* __restrict__ addend) {
    size_t i = ((size_t)blockIdx.x * 256 + threadIdx.x) * 4;
    int c = (int)(i >> 13);
    float4 v0 = *(const float4*)(g_ks + i);
    float4 v1 = *(const float4*)(g_ks + (size_t)C_ * S_ + i);
    float4 v2 = *(const float4*)(g_ks + (size_t)2 * C_ * S_ + i);
    float4 v3 = *(const float4*)(g_ks + (size_t)3 * C_ * S_ + i);
    float bv = bias[c];
    float4 r;
    r.x = v0.x + v1.x + v2.x + v3.x + bv;
    r.y = v0.y + v1.y + v2.y + v3.y + bv;
    r.z = v0.z + v1.z + v2.z + v3.z + bv;
    r.w = v0.w + v1.w + v2.w + v3.w + bv;
    if (addend) {
        float4 a = *(const float4*)(addend + i);
        r.x += a.x; r.y += a.y; r.z += a.z; r.w += a.w;
    }
    *(float4*)(out + i) = r;
    float s  = r.x + r.y + r.z + r.w;
    float s2 = r.x * r.x + r.y * r.y + r.z * r.z + r.w * r.w;
    __shared__ float sh0[8], sh1[8];
    float ws = warp_sum(s), ws2 = warp_sum(s2);
    int wid = threadIdx.x >> 5, lid = threadIdx.x & 31;
    if (!lid) { sh0[wid] = ws; sh1[wid] = ws2; }
    __syncthreads();
    if (threadIdx.x == 0) {
        float a = 0.f, b = 0.f;
        #pragma unroll
        for (int k = 0; k < 8; k++) { a += sh0[k]; b += sh1[k]; }
        g_part[blockIdx.x] = make_float2(a, b);
    }
}

// ================= HMMA mainloop (single-pass fp16, 3-stage) =================
struct HmmaAcc { float a[4][4][4]; };

__device__ __forceinline__ void hmma_mainloop(
    HmmaAcc& A4, uint32_t sm0, int tid,
    const ushort_t* __restrict__ Ah, int lda,
    const ushort_t* __restrict__ Bh, int ldb,
    int m0, int n0, int kiters) {
    const int lane = tid & 31, warp = tid >> 5;
    const int wm = warp & 1, wn = warp >> 1;

    auto issue = [&](int stage, int k0) {
        uint32_t sb = sm0 + stage * STG;
        #pragma unroll
        for (int h = 0; h < 2; h++) {
            int id = tid + h * 256;
            int r = id >> 2, cu = id & 3;
            uint32_t soff = r * 64 + (((cu ^ ((r >> 1) & 3))) << 4);
            CP_ASYNC16(sb + soff,        Ah + (size_t)(m0 + r) * lda + k0 + cu * 8);
            CP_ASYNC16(sb + 8192 + soff, Bh + (size_t)(n0 + r) * ldb + k0 + cu * 8);
        }
        CP_COMMIT();
    };

    issue(0, 0);
    issue(1, 32);

    const int rl = lane & 15, ul = lane >> 4;
    for (int it = 0; it < kiters; it++) {
        CP_WAIT1();
        __syncthreads();
        uint32_t sb = sm0 + (it % 3) * STG;
        #pragma unroll
        for (int k16 = 0; k16 < 2; k16++) {
            uint32_t a4[4][4], b4[2][4];
            int u = k16 * 2 + ul;
            #pragma unroll
            for (int i = 0; i < 4; i++) {
                int r = wm * 64 + i * 16 + rl;
                LDSM4(a4[i], sb + r * 64 + (((u ^ ((r >> 1) & 3))) << 4));
            }
            #pragma unroll
            for (int j2 = 0; j2 < 2; j2++) {
                int r = wn * 32 + j2 * 16 + rl;
                LDSM4(b4[j2], sb + 8192 + r * 64 + (((u ^ ((r >> 1) & 3))) << 4));
            }
            #pragma unroll
            for (int i = 0; i < 4; i++)
                #pragma unroll
                for (int j = 0; j < 4; j++) {
                    int j2 = j >> 1, ts = j & 1;
                    MMA16816(A4.a[i][j], a4[i], b4[j2][ts], b4[j2][ts + 2]);
                }
        }
        __syncthreads();
        if (it + 2 < kiters) issue((it + 2) % 3, (it + 2) * 32);
        else CP_COMMIT();
    }
}

// ---------------- conv GEMM, implicit im2col gather, split-K, 4-stage, occ2 ------
// grid (16, 64): x -> m-tile (x&3), ksplit (x>>2); y -> n-tile
// K order: k = r*512 + ci, r = kd*9+kh*3+kw. B chunk gathers from g_ath [s][c].
__global__ void __launch_bounds__(256, 2) conv_hmma_k() {
    extern __shared__ unsigned char dynsm[];
    const uint32_t sm0 = smem_u32(dynsm);
    const int tid = threadIdx.x, lane = tid & 31, warp = tid >> 5;
    const int m0 = (blockIdx.x & 3) * 128;
    const int ks = blockIdx.x >> 2;
    const int n0 = blockIdx.y * 128;
    const int kbase = ks * (KSPLIT_ITERS * 32);
    const int wm = warp & 1, wn = warp >> 1;

    // per-thread precompute for the two cp.async rows (h = 0, 1)
    int rrow[2], cu8[2];
    uint32_t soffv[2];
    int tm2[2], ym1[2], xm1[2];
    #pragma unroll
    for (int h = 0; h < 2; h++) {
        int id = tid + h * 256;
        int r = id >> 2, cu = id & 3;
        rrow[h] = r; cu8[h] = cu * 8;
        soffv[h] = r * 64 + (((cu ^ ((r >> 1) & 3))) << 4);
        int pos = n0 + r;
        tm2[h] = (pos >> 10) - 2;
        ym1[h] = ((pos >> 5) & 31) - 1;
        xm1[h] = (pos & 31) - 1;
    }

    auto issue = [&](int stage, int k0) {
        uint32_t sb = sm0 + stage * STG;
        int rcode = k0 >> 9;                 // tap index 0..26 (uniform)
        int ci0 = k0 & 511;
        int kd = rcode / 9;
        int rr = rcode - kd * 9;
        int kh = rr / 3;
        int kw = rr - kh * 3;
        #pragma unroll
        for (int h = 0; h < 2; h++) {
            CP_ASYNC16(sb + soffv[h],
                       g_wh + (size_t)(m0 + rrow[h]) * KC + k0 + cu8[h]);
            int ts = min(max(tm2[h] + kd, 0), 7);
            int ys = min(max(ym1[h] + kh, 0), 31);
            int xs = min(max(xm1[h] + kw, 0), 31);
            CP_ASYNC16(sb + 8192 + soffv[h],
                       g_ath + (size_t)((ts << 10) + (ys << 5) + xs) * C_ + ci0 + cu8[h]);
        }
        CP_COMMIT();
    };

    float acc[4][4][4];
    #pragma unroll
    for (int i = 0; i < 4; i++)
        #pragma unroll
        for (int j = 0; j < 4; j++)
            #pragma unroll
            for (int r = 0; r < 4; r++) acc[i][j][r] = 0.f;

    issue(0, kbase);
    issue(1, kbase + 32);
    issue(2, kbase + 64);

    const int rl = lane & 15, ul = lane >> 4;
    for (int it = 0; it < KSPLIT_ITERS; it++) {
        CP_WAIT2();
        __syncthreads();
        uint32_t sb = sm0 + (it & 3) * STG;
        #pragma unroll
        for (int k16 = 0; k16 < 2; k16++) {
            uint32_t a4[4][4], b4[2][4];
            int u = k16 * 2 + ul;
            #pragma unroll
            for (int i = 0; i < 4; i++) {
                int r = wm * 64 + i * 16 + rl;
                LDSM4(a4[i], sb + r * 64 + (((u ^ ((r >> 1) & 3))) << 4));
            }
            #pragma unroll
            for (int j2 = 0; j2 < 2; j2++) {
                int r = wn * 32 + j2 * 16 + rl;
                LDSM4(b4[j2], sb + 8192 + r * 64 + (((u ^ ((r >> 1) & 3))) << 4));
            }
            #pragma unroll
            for (int i = 0; i < 4; i++)
                #pragma unroll
                for (int j = 0; j < 4; j++) {
                    int j2 = j >> 1, ts = j & 1;
                    MMA16816(acc[i][j], a4[i], b4[j2][ts], b4[j2][ts + 2]);
                }
        }
        __syncthreads();
        if (it + 3 < KSPLIT_ITERS) issue((it + 3) & 3, kbase + (it + 3) * 32);
        else CP_COMMIT();
    }

    float* Sp = g_ks + (size_t)ks * C_ * S_;
    const int mrow = m0 + wm * 64 + (lane >> 2);
    const int ncol = n0 + wn * 32 + (lane & 3) * 2;
    #pragma unroll
    for (int i = 0; i < 4; i++) {
        int ma = mrow + i * 16, mb = ma + 8;
        #pragma unroll
        for (int j = 0; j < 4; j++) {
            int n = ncol + j * 8;
            *(float2*)(Sp + (size_t)ma * S_ + n) = make_float2(acc[i][j][0], acc[i][j][1]);
            *(float2*)(Sp + (size_t)mb * S_ + n) = make_float2(acc[i][j][2], acc[i][j][3]);
        }
    }
}

// ---------------- generic attention GEMM, occ2 ----------------
__global__ void __launch_bounds__(256, 2) hmma_gemm_k(
    const ushort_t* __restrict__ Ah, int lda,
    const ushort_t* __restrict__ Bh, int ldb,
    float* __restrict__ Cf, ushort_t* __restrict__ Ch,
    int ldc, int K, float alpha,
    const float* __restrict__ biasM, const float* __restrict__ biasN,
    const float* __restrict__ addend, int causal, int kcausal, int mrev) {
    const int by = mrev ? (gridDim.y - 1 - blockIdx.y) : blockIdx.y;
    const int m0 = by * 128, n0 = blockIdx.x * 128;
    if (causal && n0 >= (((m0 >> 10) + 1) << 10)) return;
    int Keff = kcausal ? (((m0 >> 10) + 1) << 10) : K;

    extern __shared__ unsigned char dynsm[];
    const uint32_t sm0 = smem_u32(dynsm);
    const int tid = threadIdx.x, lane = tid & 31, warp = tid >> 5;
    const int wm = warp & 1, wn = warp >> 1;

    HmmaAcc acc;
    #pragma unroll
    for (int i = 0; i < 4; i++)
        #pragma unroll
        for (int j = 0; j < 4; j++)
            #pragma unroll
            for (int r = 0; r < 4; r++) acc.a[i][j][r] = 0.f;

    hmma_mainloop(acc, sm0, tid, Ah, lda, Bh, ldb, m0, n0, Keff >> 5);

    const int mrow = m0 + wm * 64 + (lane >> 2);
    const int ncol = n0 + wn * 32 + (lane & 3) * 2;
    #pragma unroll
    for (int i = 0; i < 4; i++) {
        int ma = mrow + i * 16, mb = ma + 8;
        float bva = biasM ? biasM[ma] : 0.f;
        float bvb = biasM ? biasM[mb] : 0.f;
        #pragma unroll
        for (int j = 0; j < 4; j++) {
            int n = ncol + j * 8;
            float2 va = make_float2(acc.a[i][j][0] * alpha + bva, acc.a[i][j][1] * alpha + bva);
            float2 vb = make_float2(acc.a[i][j][2] * alpha + bvb, acc.a[i][j][3] * alpha + bvb);
            if (biasN) {
                float b0 = biasN[n], b1 = biasN[n + 1];
                va.x += b0; va.y += b1; vb.x += b0; vb.y += b1;
            }
            if (addend) {
                float2 aa = *(const float2*)(addend + (size_t)ma * ldc + n);
                float2 ab = *(const float2*)(addend + (size_t)mb * ldc + n);
                va.x += aa.x; va.y += aa.y; vb.x += ab.x; vb.y += ab.y;
            }
            if (Cf) {
                *(float2*)(Cf + (size_t)ma * ldc + n) = va;
                *(float2*)(Cf + (size_t)mb * ldc + n) = vb;
            }
            if (Ch) {
                *(ushort2*)(Ch + (size_t)ma * ldc + n) = make_ushort2(to_h(va.x), to_h(va.y));
                *(ushort2*)(Ch + (size_t)mb * ldc + n) = make_ushort2(to_h(vb.x), to_h(vb.y));
            }
        }
    }
}

// ---------------- softmax: single gmem pass via smem row buffer ----------------
__global__ void softmax_k() {
    __shared__ float row[S_];
    __shared__ float sh[8];
    int i = blockIdx.x;
    int L = ((i >> 10) + 1) << 10;
    const float4* src = (const float4*)(g_p + ((size_t)i << 13));
    int n4 = L >> 2;
    int tid = threadIdx.x;

    float mx = -1e30f;
    for (int j = tid; j < n4; j += 256) {
        float4 v = src[j];
        *(float4*)(row + 4 * j) = v;
        mx = fmaxf(mx, fmaxf(fmaxf(v.x, v.y), fmaxf(v.z, v.w)));
    }
    float wm = warp_max(mx);
    if ((tid & 31) == 0) sh[tid >> 5] = wm;
    __syncthreads();
    if (tid < 32) {
        float m2 = (tid < 8) ? sh[tid] : -1e30f;
        m2 = warp_max(m2);
        if (tid == 0) sh[0] = m2;
    }
    __syncthreads();
    float m = sh[0];
    __syncthreads();

    float s = 0.f;
    for (int j = tid; j < n4; j += 256) {
        float4 v = *(float4*)(row + 4 * j);
        v.x = __expf(v.x - m); v.y = __expf(v.y - m);
        v.z = __expf(v.z - m); v.w = __expf(v.w - m);
        s += v.x + v.y + v.z + v.w;
        *(float4*)(row + 4 * j) = v;
    }
    float ws = warp_sum(s);
    if ((tid & 31) == 0) sh[tid >> 5] = ws;
    __syncthreads();
    if (tid < 32) {
        float s2 = (tid < 8) ? sh[tid] : 0.f;
        s2 = warp_sum(s2);
        if (tid == 0) sh[0] = s2;
    }
    __syncthreads();
    float inv = 1.f / sh[0];
    size_t base = (size_t)i << 13;
    for (int j = tid; j < n4; j += 256) {
        float4 v = *(float4*)(row + 4 * j);
        uint2 hv = make_uint2(
            (uint32_t)to_h(v.x * inv) | ((uint32_t)to_h(v.y * inv) << 16),
            (uint32_t)to_h(v.z * inv) | ((uint32_t)to_h(v.w * inv) << 16));
        *(uint2*)(g_ph + base + 4 * (size_t)j) = hv;
    }
}

// ---------------- orchestration ----------------
extern "C" void kernel_launch(void* const* d_in, const int* in_sizes, int n_in,
                              void* d_out, int out_size) {
    (void)in_sizes; (void)n_in; (void)out_size;

    float *t1, *y0, *mid, *p;
    ushort_t *wah, *acth, *qh, *kh, *vh, *oh, *ph;
    cudaGetSymbolAddress((void**)&t1,   g_t1);
    cudaGetSymbolAddress((void**)&y0,   g_y0);
    cudaGetSymbolAddress((void**)&mid,  g_mid);
    cudaGetSymbolAddress((void**)&p,    g_p);
    cudaGetSymbolAddress((void**)&wah,  g_wah);
    cudaGetSymbolAddress((void**)&acth, g_ath);
    cudaGetSymbolAddress((void**)&qh,   g_qh);
    cudaGetSymbolAddress((void**)&kh,   g_kh);
    cudaGetSymbolAddress((void**)&vh,   g_vh);
    cudaGetSymbolAddress((void**)&oh,   g_oh);
    cudaGetSymbolAddress((void**)&ph,   g_ph);

    cudaFuncSetAttribute(conv_hmma_k, cudaFuncAttributeMaxDynamicSharedMemorySize, 4 * STG);
    cudaFuncSetAttribute(hmma_gemm_k, cudaFuncAttributeMaxDynamicSharedMemorySize, 3 * STG);

    const float* X = (const float*)d_in[0];
    const float* a_gns = (const float*)d_in[17];
    const float* a_gnb = (const float*)d_in[18];
    const float* a_wq  = (const float*)d_in[19];
    const float* a_bq  = (const float*)d_in[20];
    const float* a_wk  = (const float*)d_in[21];
    const float* a_bk  = (const float*)d_in[22];
    const float* a_wv  = (const float*)d_in[23];
    const float* a_bv  = (const float*)d_in[24];
    const float* a_wo  = (const float*)d_in[25];
    const float* a_bo  = (const float*)d_in[26];

    const dim3 conv_grid(16, 64);
    const dim3 nt_grid(S_ / 32, C_ / 32);
    const dim3 nt_blk(32, 8);
    const int WPACK_CONV = ((C_ * KC) / 8) / 256;
    const int WPACK_SQ   = ((C_ * C_) / 8) / 256;

    auto resnet = [&](const float* in, int base, float* midb, float* outbuf,
                      int in_stats_from_part) {
        const float* n1s = (const float*)d_in[base + 0];
        const float* n1b = (const float*)d_in[base + 1];
        const float* w1  = (const float*)d_in[base + 2];
        const float* b1  = (const float*)d_in[base + 3];
        const float* n2s = (const float*)d_in[base + 4];
        const float* n2b = (const float*)d_in[base + 5];
        const float* w2  = (const float*)d_in[base + 6];
        const float* b2  = (const float*)d_in[base + 7];

        if (in_stats_from_part) gn_stats_p<<<NGROUP, 128>>>();
        else                    gn_stats_k<<<NGROUP, 256>>>(in);
        normact_t_k<<<nt_grid, nt_blk>>>(in, n1s, n1b, 1);
        wpack_conv_k<<<WPACK_CONV, 256>>>(w1);
        conv_hmma_k<<<conv_grid, 256, 4 * STG>>>();
        ksum_k<<<KSUM_BLOCKS, 256>>>(midb, b1, nullptr);
        gn_stats_p<<<NGROUP, 128>>>();
        normact_t_k<<<nt_grid, nt_blk>>>(midb, n2s, n2b, 1);
        wpack_conv_k<<<WPACK_CONV, 256>>>(w2);
        conv_hmma_k<<<conv_grid, 256, 4 * STG>>>();
        ksum_k<<<KSUM_BLOCKS, 256>>>(outbuf, b2, in);
    };

    // ---- ResNet block 0:  X -> y0 ----
    resnet(X, 1, t1, y0, 0);

    // ---- Causal frame attention on y0 (stats via ksum partials) ----
    gn_stats_p<<<NGROUP, 128>>>();
    normact_t_k<<<nt_grid, nt_blk>>>(y0, a_gns, a_gnb, 0);

    // Q[s][d] = act . wq^T + bq
    wpack_k<<<WPACK_SQ, 256>>>(a_wq, wah);
    hmma_gemm_k<<<dim3(4, 64), 256, 3 * STG>>>(acth, C_, wah, C_,
        nullptr, qh, C_, C_, 1.f, nullptr, a_bq, nullptr, 0, 0, 0);
    // K[s][d]
    wpack_k<<<WPACK_SQ, 256>>>(a_wk, wah);
    hmma_gemm_k<<<dim3(4, 64), 256, 3 * STG>>>(acth, C_, wah, C_,
        nullptr, kh, C_, C_, 1.f, nullptr, a_bk, nullptr, 0, 0, 0);
    // V[d][s] = wv . act^T + bv
    wpack_k<<<WPACK_SQ, 256>>>(a_wv, wah);
    hmma_gemm_k<<<dim3(64, 4), 256, 3 * STG>>>(wah, C_, acth, C_,
        nullptr, vh, S_, C_, 1.f, a_bv, nullptr, nullptr, 0, 0, 0);

    // scores: Q . K^T (block-causal tile skip)
    hmma_gemm_k<<<dim3(64, 64), 256, 3 * STG>>>(qh, C_, kh, C_,
        p, nullptr, S_, C_, 0.04419417382415922f,
        nullptr, nullptr, nullptr, 1, 0, 0);
    softmax_k<<<S_, 256>>>();
    // O[s][d] = P . V^T  (reversed m-order, causal K bound)
    hmma_gemm_k<<<dim3(4, 64), 256, 3 * STG>>>(ph, S_, vh, S_,
        nullptr, oh, C_, S_, 1.f, nullptr, nullptr, nullptr, 0, 1, 1);
    // attnout[c][s] = wo . O^T + bo + y0
    wpack_k<<<WPACK_SQ, 256>>>(a_wo, wah);
    hmma_gemm_k<<<dim3(64, 4), 256, 3 * STG>>>(wah, C_, oh, C_,
        t1, nullptr, S_, C_, 1.f, a_bo, nullptr, y0, 0, 0, 0);

    // ---- ResNet block 1:  t1 -> d_out ----
    resnet(t1, 9, mid, (float*)d_out, 0);
}

// round 11
// speedup vs baseline: 7.3833x; 1.0149x over previous
#include <cuda_runtime.h>
#include <cuda_fp16.h>
#include <math.h>
#include <stdint.h>

#define C_      512
#define S_      8192
#define HW_     1024
#define W_      32
#define NGROUP  32
#define CPG     16
#define KC      13824
#define NSPLIT  4
#define KSPLIT_ITERS 108      // (KC/32)/4
#define KSUM_BLOCKS 4096      // (C_*S_/4)/256

// smem stage: A 8K | B 8K
#define STG 16384

typedef unsigned short ushort_t;

__device__ float g_mean[NGROUP];
__device__ float g_rstd[NGROUP];
__device__ float2 g_part[KSUM_BLOCKS];
__device__ float g_t1 [(size_t)C_ * S_];
__device__ float g_y0 [(size_t)C_ * S_];
__device__ float g_mid[(size_t)C_ * S_];
__device__ float g_p  [(size_t)S_ * S_];
__device__ float g_ks [(size_t)NSPLIT * C_ * S_];
// fp16 operands
__device__ __align__(16) ushort_t g_ath[(size_t)S_ * C_];    // normalized act [s][c]
__device__ __align__(16) ushort_t g_wh [(size_t)C_ * KC];    // conv weights, K = r*512+ci
__device__ __align__(16) ushort_t g_wah[(size_t)C_ * C_];
__device__ __align__(16) ushort_t g_qh [(size_t)S_ * C_];
__device__ __align__(16) ushort_t g_kh [(size_t)S_ * C_];
__device__ __align__(16) ushort_t g_vh [(size_t)C_ * S_];
__device__ __align__(16) ushort_t g_oh [(size_t)S_ * C_];
__device__ __align__(16) ushort_t g_ph [(size_t)S_ * S_];

// ---------------- PTX helpers ----------------
__device__ __forceinline__ uint32_t smem_u32(const void* p) {
    uint32_t a;
    asm("{ .reg .u64 t; cvta.to.shared.u64 t, %1; cvt.u32.u64 %0, t; }" : "=r"(a) : "l"(p));
    return a;
}
#define CP_ASYNC16(smem, gmem) \
    asm volatile("cp.async.cg.shared.global [%0], [%1], 16;" :: "r"(smem), "l"(gmem) : "memory")
#define CP_COMMIT() asm volatile("cp.async.commit_group;" ::: "memory")
#define CP_WAIT1()  asm volatile("cp.async.wait_group 1;" ::: "memory")
#define CP_WAIT2()  asm volatile("cp.async.wait_group 2;" ::: "memory")
#define LDSM4(r, addr) \
    asm volatile("ldmatrix.sync.aligned.m8n8.x4.shared.b16 {%0,%1,%2,%3}, [%4];" \
        : "=r"((r)[0]),"=r"((r)[1]),"=r"((r)[2]),"=r"((r)[3]) : "r"(addr))
#define MMA16816(d, a, b0, b1) \
    asm volatile("mma.sync.aligned.m16n8k16.row.col.f32.f16.f16.f32 " \
        "{%0,%1,%2,%3}, {%4,%5,%6,%7}, {%8,%9}, {%0,%1,%2,%3};" \
        : "+f"((d)[0]),"+f"((d)[1]),"+f"((d)[2]),"+f"((d)[3]) \
        : "r"((a)[0]),"r"((a)[1]),"r"((a)[2]),"r"((a)[3]), "r"(b0),"r"(b1))

__device__ __forceinline__ ushort_t to_h(float v) {
    return __half_as_ushort(__float2half_rn(v));
}

__inline__ __device__ float warp_sum(float v) {
    #pragma unroll
    for (int o = 16; o; o >>= 1) v += __shfl_down_sync(0xffffffffu, v, o);
    return v;
}
__inline__ __device__ float warp_max(float v) {
    #pragma unroll
    for (int o = 16; o; o >>= 1) v = fmaxf(v, __shfl_down_sync(0xffffffffu, v, o));
    return v;
}

// ---------------- GroupNorm stats (full read) ----------------
__global__ void gn_stats_k(const float* __restrict__ x) {
    int g = blockIdx.x;
    const float4* p = (const float4*)(x + (size_t)g * CPG * S_);
    const int n4 = (CPG * S_) / 4;
    float s = 0.f, s2 = 0.f;
    for (int i = threadIdx.x; i < n4; i += blockDim.x) {
        float4 v = p[i];
        s  += v.x + v.y + v.z + v.w;
        s2 += v.x * v.x + v.y * v.y + v.z * v.z + v.w * v.w;
    }
    __shared__ float sh0[8], sh1[8];
    float ws = warp_sum(s), ws2 = warp_sum(s2);
    int wid = threadIdx.x >> 5, lid = threadIdx.x & 31;
    if (!lid) { sh0[wid] = ws; sh1[wid] = ws2; }
    __syncthreads();
    if (threadIdx.x == 0) {
        float a = 0.f, b = 0.f;
        #pragma unroll
        for (int i = 0; i < 8; i++) { a += sh0[i]; b += sh1[i]; }
        const float inv_n = 1.f / (float)(CPG * S_);
        float m = a * inv_n;
        g_mean[g] = m;
        g_rstd[g] = rsqrtf(b * inv_n - m * m + 1e-6f);
    }
}

// ---------------- GroupNorm stats from ksum partials ----------------
__global__ void gn_stats_p() {
    int g = blockIdx.x;
    float2 v = g_part[g * 128 + threadIdx.x];
    __shared__ float sh0[4], sh1[4];
    float ws = warp_sum(v.x), ws2 = warp_sum(v.y);
    int wid = threadIdx.x >> 5, lid = threadIdx.x & 31;
    if (!lid) { sh0[wid] = ws; sh1[wid] = ws2; }
    __syncthreads();
    if (threadIdx.x == 0) {
        float a = sh0[0] + sh0[1] + sh0[2] + sh0[3];
        float b = sh1[0] + sh1[1] + sh1[2] + sh1[3];
        const float inv_n = 1.f / (float)(CPG * S_);
        float m = a * inv_n;
        g_mean[g] = m;
        g_rstd[g] = rsqrtf(b * inv_n - m * m + 1e-6f);
    }
}

// ---------------- transposing GN (+optional SiLU): x [c][s] -> fp16 [s][c] ------
__global__ void normact_t_k(const float* __restrict__ x, const float* __restrict__ sc,
                            const float* __restrict__ bi, int do_silu) {
    __shared__ float tile[32][33];
    int s0 = blockIdx.x * 32, c0 = blockIdx.y * 32;
    int tx = threadIdx.x, ty = threadIdx.y;
    #pragma unroll
    for (int i = ty; i < 32; i += 8)
        tile[i][tx] = x[(size_t)(c0 + i) * S_ + s0 + tx];
    __syncthreads();
    int c = c0 + tx;
    int g = c >> 4;
    float mu = g_mean[g], rs = g_rstd[g], sv = sc[c], bv = bi[c];
    #pragma unroll
    for (int i = ty; i < 32; i += 8) {
        float v = (tile[tx][i] - mu) * rs * sv + bv;
        if (do_silu) v = v / (1.f + __expf(-v));
        g_ath[(size_t)(s0 + i) * C_ + c] = to_h(v);
    }
}

// ---------------- conv weight pack: w[co][ci*27+r] -> fp16 g_wh[co][r*512+ci] ----
__global__ void wpack_conv_k(const float* __restrict__ w) {
    size_t id = (size_t)blockIdx.x * 256 + threadIdx.x;
    int co = (int)(id / 1728);
    int kk = (int)(id - (size_t)co * 1728) * 8;
    int r  = kk >> 9;
    int ci0 = kk & 511;
    const float* src = w + (size_t)co * KC + r;
    __align__(16) ushort_t hv[8];
    #pragma unroll
    for (int e = 0; e < 8; e++)
        hv[e] = to_h(src[(size_t)(ci0 + e) * 27]);
    *(uint4*)(g_wh + (size_t)co * KC + kk) = *(uint4*)hv;
}

// ---------------- pack: fp32 row-major -> fp16 (attention weights) ----------------
__global__ void wpack_k(const float* __restrict__ w, ushort_t* __restrict__ dh) {
    size_t id = (size_t)blockIdx.x * 256 + threadIdx.x;
    const float4* src = (const float4*)w;
    float4 v0 = src[id * 2], v1 = src[id * 2 + 1];
    __align__(16) ushort_t hv[8];
    hv[0] = to_h(v0.x); hv[1] = to_h(v0.y); hv[2] = to_h(v0.z); hv[3] = to_h(v0.w);
    hv[4] = to_h(v1.x); hv[5] = to_h(v1.y); hv[6] = to_h(v1.z); hv[7] = to_h(v1.w);
    *(uint4*)(dh + id * 8) = *(uint4*)hv;
}

// ---------------- split-K reduce + per-block GN partials ----------------
__global__ void ksum_k(float* __restrict__ out, const float* __restrict__ bias,
                       const float* __restrict__ addend) {
    size_t i = ((size_t)blockIdx.x * 256 + threadIdx.x) * 4;
    int c = (int)(i >> 13);
    float4 v0 = *(const float4*)(g_ks + i);
    float4 v1 = *(const float4*)(g_ks + (size_t)C_ * S_ + i);
    float4 v2 = *(const float4*)(g_ks + (size_t)2 * C_ * S_ + i);
    float4 v3 = *(const float4*)(g_ks + (size_t)3 * C_ * S_ + i);
    float bv = bias[c];
    float4 r;
    r.x = v0.x + v1.x + v2.x + v3.x + bv;
    r.y = v0.y + v1.y + v2.y + v3.y + bv;
    r.z = v0.z + v1.z + v2.z + v3.z + bv;
    r.w = v0.w + v1.w + v2.w + v3.w + bv;
    if (addend) {
        float4 a = *(const float4*)(addend + i);
        r.x += a.x; r.y += a.y; r.z += a.z; r.w += a.w;
    }
    *(float4*)(out + i) = r;
    float s  = r.x + r.y + r.z + r.w;
    float s2 = r.x * r.x + r.y * r.y + r.z * r.z + r.w * r.w;
    __shared__ float sh0[8], sh1[8];
    float ws = warp_sum(s), ws2 = warp_sum(s2);
    int wid = threadIdx.x >> 5, lid = threadIdx.x & 31;
    if (!lid) { sh0[wid] = ws; sh1[wid] = ws2; }
    __syncthreads();
    if (threadIdx.x == 0) {
        float a = 0.f, b = 0.f;
        #pragma unroll
        for (int k = 0; k < 8; k++) { a += sh0[k]; b += sh1[k]; }
        g_part[blockIdx.x] = make_float2(a, b);
    }
}

// ================= HMMA mainloop (single-pass fp16, 3-stage, 1 sync/iter) =========
struct HmmaAcc { float a[4][4][4]; };

__device__ __forceinline__ void hmma_mainloop(
    HmmaAcc& A4, uint32_t sm0, int tid,
    const ushort_t* __restrict__ Ah, int lda,
    const ushort_t* __restrict__ Bh, int ldb,
    int m0, int n0, int kiters) {
    const int lane = tid & 31, warp = tid >> 5;
    const int wm = warp & 1, wn = warp >> 1;

    auto issue = [&](int stage, int k0) {
        uint32_t sb = sm0 + stage * STG;
        #pragma unroll
        for (int h = 0; h < 2; h++) {
            int id = tid + h * 256;
            int r = id >> 2, cu = id & 3;
            uint32_t soff = r * 64 + (((cu ^ ((r >> 1) & 3))) << 4);
            CP_ASYNC16(sb + soff,        Ah + (size_t)(m0 + r) * lda + k0 + cu * 8);
            CP_ASYNC16(sb + 8192 + soff, Bh + (size_t)(n0 + r) * ldb + k0 + cu * 8);
        }
        CP_COMMIT();
    };

    issue(0, 0);
    issue(1, 32);

    const int rl = lane & 15, ul = lane >> 4;
    for (int it = 0; it < kiters; it++) {
        CP_WAIT1();
        __syncthreads();
        if (it + 2 < kiters) issue((it + 2) % 3, (it + 2) * 32);
        else CP_COMMIT();
        uint32_t sb = sm0 + (it % 3) * STG;
        #pragma unroll
        for (int k16 = 0; k16 < 2; k16++) {
            uint32_t a4[4][4], b4[2][4];
            int u = k16 * 2 + ul;
            #pragma unroll
            for (int i = 0; i < 4; i++) {
                int r = wm * 64 + i * 16 + rl;
                LDSM4(a4[i], sb + r * 64 + (((u ^ ((r >> 1) & 3))) << 4));
            }
            #pragma unroll
            for (int j2 = 0; j2 < 2; j2++) {
                int r = wn * 32 + j2 * 16 + rl;
                LDSM4(b4[j2], sb + 8192 + r * 64 + (((u ^ ((r >> 1) & 3))) << 4));
            }
            #pragma unroll
            for (int i = 0; i < 4; i++)
                #pragma unroll
                for (int j = 0; j < 4; j++) {
                    int j2 = j >> 1, ts = j & 1;
                    MMA16816(A4.a[i][j], a4[i], b4[j2][ts], b4[j2][ts + 2]);
                }
        }
    }
}

// ---------------- conv GEMM: implicit gather, split-K, 4-stage, 1 sync/iter, occ2 --
// grid (16, 64): x -> m-tile (x&3), ksplit (x>>2); y -> n-tile
__global__ void __launch_bounds__(256, 2) conv_hmma_k() {
    extern __shared__ unsigned char dynsm[];
    const uint32_t sm0 = smem_u32(dynsm);
    const int tid = threadIdx.x, lane = tid & 31, warp = tid >> 5;
    const int m0 = (blockIdx.x & 3) * 128;
    const int ks = blockIdx.x >> 2;
    const int n0 = blockIdx.y * 128;
    const int kbase = ks * (KSPLIT_ITERS * 32);
    const int wm = warp & 1, wn = warp >> 1;

    int rrow[2], cu8[2];
    uint32_t soffv[2];
    int tm2[2], ym1[2], xm1[2];
    #pragma unroll
    for (int h = 0; h < 2; h++) {
        int id = tid + h * 256;
        int r = id >> 2, cu = id & 3;
        rrow[h] = r; cu8[h] = cu * 8;
        soffv[h] = r * 64 + (((cu ^ ((r >> 1) & 3))) << 4);
        int pos = n0 + r;
        tm2[h] = (pos >> 10) - 2;
        ym1[h] = ((pos >> 5) & 31) - 1;
        xm1[h] = (pos & 31) - 1;
    }

    auto issue = [&](int stage, int k0) {
        uint32_t sb = sm0 + stage * STG;
        int rcode = k0 >> 9;
        int ci0 = k0 & 511;
        int kd = rcode / 9;
        int rr = rcode - kd * 9;
        int kh = rr / 3;
        int kw = rr - kh * 3;
        #pragma unroll
        for (int h = 0; h < 2; h++) {
            CP_ASYNC16(sb + soffv[h],
                       g_wh + (size_t)(m0 + rrow[h]) * KC + k0 + cu8[h]);
            int ts = min(max(tm2[h] + kd, 0), 7);
            int ys = min(max(ym1[h] + kh, 0), 31);
            int xs = min(max(xm1[h] + kw, 0), 31);
            CP_ASYNC16(sb + 8192 + soffv[h],
                       g_ath + (size_t)((ts << 10) + (ys << 5) + xs) * C_ + ci0 + cu8[h]);
        }
        CP_COMMIT();
    };

    float acc[4][4][4];
    #pragma unroll
    for (int i = 0; i < 4; i++)
        #pragma unroll
        for (int j = 0; j < 4; j++)
            #pragma unroll
            for (int r = 0; r < 4; r++) acc[i][j][r] = 0.f;

    issue(0, kbase);
    issue(1, kbase + 32);
    issue(2, kbase + 64);

    const int rl = lane & 15, ul = lane >> 4;
    for (int it = 0; it < KSPLIT_ITERS; it++) {
        CP_WAIT2();
        __syncthreads();
        if (it + 3 < KSPLIT_ITERS) issue((it + 3) & 3, kbase + (it + 3) * 32);
        else CP_COMMIT();
        uint32_t sb = sm0 + (it & 3) * STG;
        #pragma unroll
        for (int k16 = 0; k16 < 2; k16++) {
            uint32_t a4[4][4], b4[2][4];
            int u = k16 * 2 + ul;
            #pragma unroll
            for (int i = 0; i < 4; i++) {
                int r = wm * 64 + i * 16 + rl;
                LDSM4(a4[i], sb + r * 64 + (((u ^ ((r >> 1) & 3))) << 4));
            }
            #pragma unroll
            for (int j2 = 0; j2 < 2; j2++) {
                int r = wn * 32 + j2 * 16 + rl;
                LDSM4(b4[j2], sb + 8192 + r * 64 + (((u ^ ((r >> 1) & 3))) << 4));
            }
            #pragma unroll
            for (int i = 0; i < 4; i++)
                #pragma unroll
                for (int j = 0; j < 4; j++) {
                    int j2 = j >> 1, ts = j & 1;
                    MMA16816(acc[i][j], a4[i], b4[j2][ts], b4[j2][ts + 2]);
                }
        }
    }

    float* Sp = g_ks + (size_t)ks * C_ * S_;
    const int mrow = m0 + wm * 64 + (lane >> 2);
    const int ncol = n0 + wn * 32 + (lane & 3) * 2;
    #pragma unroll
    for (int i = 0; i < 4; i++) {
        int ma = mrow + i * 16, mb = ma + 8;
        #pragma unroll
        for (int j = 0; j < 4; j++) {
            int n = ncol + j * 8;
            *(float2*)(Sp + (size_t)ma * S_ + n) = make_float2(acc[i][j][0], acc[i][j][1]);
            *(float2*)(Sp + (size_t)mb * S_ + n) = make_float2(acc[i][j][2], acc[i][j][3]);
        }
    }
}

// ---------------- generic attention GEMM, occ2 ----------------
__global__ void __launch_bounds__(256, 2) hmma_gemm_k(
    const ushort_t* __restrict__ Ah, int lda,
    const ushort_t* __restrict__ Bh, int ldb,
    float* __restrict__ Cf, ushort_t* __restrict__ Ch,
    int ldc, int K, float alpha,
    const float* __restrict__ biasM, const float* __restrict__ biasN,
    const float* __restrict__ addend, int causal, int kcausal, int mrev) {
    const int by = mrev ? (gridDim.y - 1 - blockIdx.y) : blockIdx.y;
    const int m0 = by * 128, n0 = blockIdx.x * 128;
    if (causal && n0 >= (((m0 >> 10) + 1) << 10)) return;
    int Keff = kcausal ? (((m0 >> 10) + 1) << 10) : K;

    extern __shared__ unsigned char dynsm[];
    const uint32_t sm0 = smem_u32(dynsm);
    const int tid = threadIdx.x, lane = tid & 31, warp = tid >> 5;
    const int wm = warp & 1, wn = warp >> 1;

    HmmaAcc acc;
    #pragma unroll
    for (int i = 0; i < 4; i++)
        #pragma unroll
        for (int j = 0; j < 4; j++)
            #pragma unroll
            for (int r = 0; r < 4; r++) acc.a[i][j][r] = 0.f;

    hmma_mainloop(acc, sm0, tid, Ah, lda, Bh, ldb, m0, n0, Keff >> 5);

    const int mrow = m0 + wm * 64 + (lane >> 2);
    const int ncol = n0 + wn * 32 + (lane & 3) * 2;
    #pragma unroll
    for (int i = 0; i < 4; i++) {
        int ma = mrow + i * 16, mb = ma + 8;
        float bva = biasM ? biasM[ma] : 0.f;
        float bvb = biasM ? biasM[mb] : 0.f;
        #pragma unroll
        for (int j = 0; j < 4; j++) {
            int n = ncol + j * 8;
            float2 va = make_float2(acc.a[i][j][0] * alpha + bva, acc.a[i][j][1] * alpha + bva);
            float2 vb = make_float2(acc.a[i][j][2] * alpha + bvb, acc.a[i][j][3] * alpha + bvb);
            if (biasN) {
                float b0 = biasN[n], b1 = biasN[n + 1];
                va.x += b0; va.y += b1; vb.x += b0; vb.y += b1;
            }
            if (addend) {
                float2 aa = *(const float2*)(addend + (size_t)ma * ldc + n);
                float2 ab = *(const float2*)(addend + (size_t)mb * ldc + n);
                va.x += aa.x; va.y += aa.y; vb.x += ab.x; vb.y += ab.y;
            }
            if (Cf) {
                *(float2*)(Cf + (size_t)ma * ldc + n) = va;
                *(float2*)(Cf + (size_t)mb * ldc + n) = vb;
            }
            if (Ch) {
                *(ushort2*)(Ch + (size_t)ma * ldc + n) = make_ushort2(to_h(va.x), to_h(va.y));
                *(ushort2*)(Ch + (size_t)mb * ldc + n) = make_ushort2(to_h(vb.x), to_h(vb.y));
            }
        }
    }
}

// ---------------- softmax: single gmem pass via smem row buffer ----------------
__global__ void softmax_k() {
    __shared__ float row[S_];
    __shared__ float sh[8];
    int i = blockIdx.x;
    int L = ((i >> 10) + 1) << 10;
    const float4* src = (const float4*)(g_p + ((size_t)i << 13));
    int n4 = L >> 2;
    int tid = threadIdx.x;

    float mx = -1e30f;
    for (int j = tid; j < n4; j += 256) {
        float4 v = src[j];
        *(float4*)(row + 4 * j) = v;
        mx = fmaxf(mx, fmaxf(fmaxf(v.x, v.y), fmaxf(v.z, v.w)));
    }
    float wm = warp_max(mx);
    if ((tid & 31) == 0) sh[tid >> 5] = wm;
    __syncthreads();
    if (tid < 32) {
        float m2 = (tid < 8) ? sh[tid] : -1e30f;
        m2 = warp_max(m2);
        if (tid == 0) sh[0] = m2;
    }
    __syncthreads();
    float m = sh[0];
    __syncthreads();

    float s = 0.f;
    for (int j = tid; j < n4; j += 256) {
        float4 v = *(float4*)(row + 4 * j);
        v.x = __expf(v.x - m); v.y = __expf(v.y - m);
        v.z = __expf(v.z - m); v.w = __expf(v.w - m);
        s += v.x + v.y + v.z + v.w;
        *(float4*)(row + 4 * j) = v;
    }
    float ws = warp_sum(s);
    if ((tid & 31) == 0) sh[tid >> 5] = ws;
    __syncthreads();
    if (tid < 32) {
        float s2 = (tid < 8) ? sh[tid] : 0.f;
        s2 = warp_sum(s2);
        if (tid == 0) sh[0] = s2;
    }
    __syncthreads();
    float inv = 1.f / sh[0];
    size_t base = (size_t)i << 13;
    for (int j = tid; j < n4; j += 256) {
        float4 v = *(float4*)(row + 4 * j);
        uint2 hv = make_uint2(
            (uint32_t)to_h(v.x * inv) | ((uint32_t)to_h(v.y * inv) << 16),
            (uint32_t)to_h(v.z * inv) | ((uint32_t)to_h(v.w * inv) << 16));
        *(uint2*)(g_ph + base + 4 * (size_t)j) = hv;
    }
}

// ---------------- orchestration ----------------
extern "C" void kernel_launch(void* const* d_in, const int* in_sizes, int n_in,
                              void* d_out, int out_size) {
    (void)in_sizes; (void)n_in; (void)out_size;

    float *t1, *y0, *mid, *p;
    ushort_t *wah, *acth, *qh, *kh, *vh, *oh, *ph;
    cudaGetSymbolAddress((void**)&t1,   g_t1);
    cudaGetSymbolAddress((void**)&y0,   g_y0);
    cudaGetSymbolAddress((void**)&mid,  g_mid);
    cudaGetSymbolAddress((void**)&p,    g_p);
    cudaGetSymbolAddress((void**)&wah,  g_wah);
    cudaGetSymbolAddress((void**)&acth, g_ath);
    cudaGetSymbolAddress((void**)&qh,   g_qh);
    cudaGetSymbolAddress((void**)&kh,   g_kh);
    cudaGetSymbolAddress((void**)&vh,   g_vh);
    cudaGetSymbolAddress((void**)&oh,   g_oh);
    cudaGetSymbolAddress((void**)&ph,   g_ph);

    cudaFuncSetAttribute(conv_hmma_k, cudaFuncAttributeMaxDynamicSharedMemorySize, 4 * STG);
    cudaFuncSetAttribute(hmma_gemm_k, cudaFuncAttributeMaxDynamicSharedMemorySize, 3 * STG);

    const float* X = (const float*)d_in[0];
    const float* a_gns = (const float*)d_in[17];
    const float* a_gnb = (const float*)d_in[18];
    const float* a_wq  = (const float*)d_in[19];
    const float* a_bq  = (const float*)d_in[20];
    const float* a_wk  = (const float*)d_in[21];
    const float* a_bk  = (const float*)d_in[22];
    const float* a_wv  = (const float*)d_in[23];
    const float* a_bv  = (const float*)d_in[24];
    const float* a_wo  = (const float*)d_in[25];
    const float* a_bo  = (const float*)d_in[26];

    const dim3 conv_grid(16, 64);
    const dim3 nt_grid(S_ / 32, C_ / 32);
    const dim3 nt_blk(32, 8);
    const int WPACK_CONV = ((C_ * KC) / 8) / 256;
    const int WPACK_SQ   = ((C_ * C_) / 8) / 256;

    auto resnet = [&](const float* in, int base, float* midb, float* outbuf,
                      int in_stats_from_part) {
        const float* n1s = (const float*)d_in[base + 0];
        const float* n1b = (const float*)d_in[base + 1];
        const float* w1  = (const float*)d_in[base + 2];
        const float* b1  = (const float*)d_in[base + 3];
        const float* n2s = (const float*)d_in[base + 4];
        const float* n2b = (const float*)d_in[base + 5];
        const float* w2  = (const float*)d_in[base + 6];
        const float* b2  = (const float*)d_in[base + 7];

        if (in_stats_from_part) gn_stats_p<<<NGROUP, 128>>>();
        else                    gn_stats_k<<<NGROUP, 256>>>(in);
        normact_t_k<<<nt_grid, nt_blk>>>(in, n1s, n1b, 1);
        wpack_conv_k<<<WPACK_CONV, 256>>>(w1);
        conv_hmma_k<<<conv_grid, 256, 4 * STG>>>();
        ksum_k<<<KSUM_BLOCKS, 256>>>(midb, b1, nullptr);
        gn_stats_p<<<NGROUP, 128>>>();
        normact_t_k<<<nt_grid, nt_blk>>>(midb, n2s, n2b, 1);
        wpack_conv_k<<<WPACK_CONV, 256>>>(w2);
        conv_hmma_k<<<conv_grid, 256, 4 * STG>>>();
        ksum_k<<<KSUM_BLOCKS, 256>>>(outbuf, b2, in);
    };

    // ---- ResNet block 0:  X -> y0 ----
    resnet(X, 1, t1, y0, 0);

    // ---- Causal frame attention on y0 (stats via ksum partials) ----
    gn_stats_p<<<NGROUP, 128>>>();
    normact_t_k<<<nt_grid, nt_blk>>>(y0, a_gns, a_gnb, 0);

    // Q[s][d] = act . wq^T + bq
    wpack_k<<<WPACK_SQ, 256>>>(a_wq, wah);
    hmma_gemm_k<<<dim3(4, 64), 256, 3 * STG>>>(acth, C_, wah, C_,
        nullptr, qh, C_, C_, 1.f, nullptr, a_bq, nullptr, 0, 0, 0);
    // K[s][d]
    wpack_k<<<WPACK_SQ, 256>>>(a_wk, wah);
    hmma_gemm_k<<<dim3(4, 64), 256, 3 * STG>>>(acth, C_, wah, C_,
        nullptr, kh, C_, C_, 1.f, nullptr, a_bk, nullptr, 0, 0, 0);
    // V[d][s] = wv . act^T + bv
    wpack_k<<<WPACK_SQ, 256>>>(a_wv, wah);
    hmma_gemm_k<<<dim3(64, 4), 256, 3 * STG>>>(wah, C_, acth, C_,
        nullptr, vh, S_, C_, 1.f, a_bv, nullptr, nullptr, 0, 0, 0);

    // scores: Q . K^T (block-causal tile skip)
    hmma_gemm_k<<<dim3(64, 64), 256, 3 * STG>>>(qh, C_, kh, C_,
        p, nullptr, S_, C_, 0.04419417382415922f,
        nullptr, nullptr, nullptr, 1, 0, 0);
    softmax_k<<<S_, 256>>>();
    // O[s][d] = P . V^T  (reversed m-order, causal K bound)
    hmma_gemm_k<<<dim3(4, 64), 256, 3 * STG>>>(ph, S_, vh, S_,
        nullptr, oh, C_, S_, 1.f, nullptr, nullptr, nullptr, 0, 1, 1);
    // attnout[c][s] = wo . O^T + bo + y0
    wpack_k<<<WPACK_SQ, 256>>>(a_wo, wah);
    hmma_gemm_k<<<dim3(64, 4), 256, 3 * STG>>>(wah, C_, oh, C_,
        t1, nullptr, S_, C_, 1.f, a_bo, nullptr, y0, 0, 0, 0);

    // ---- ResNet block 1:  t1 -> d_out ----
    resnet(t1, 9, mid, (float*)d_out, 0);
}